// round 1
// baseline (speedup 1.0000x reference)
#include <cuda_runtime.h>
#include <math.h>

#define N_TOK 32768
#define C_DIM 256
#define E_NUM 16

// ---------------- scratch (no allocations allowed) ----------------
__device__ float g_combine[N_TOK * E_NUM];   // combine weights (0 where unselected)
__device__ float g_w[N_TOK * E_NUM];         // full softmax probs
__device__ float g_ft[E_NUM];                // frac_tokens
__device__ float g_fp[E_NUM];                // frac_probs

// ---------------- kernel 1: router ----------------
// one warp per token; 8 tokens per 256-thread block
__global__ __launch_bounds__(256) void router_kernel(
    const float* __restrict__ conv,
    const float* __restrict__ emb,
    const float* __restrict__ gateW,   // (C,E) row-major
    const float* __restrict__ gateB,
    const float* __restrict__ gamma,
    const float* __restrict__ beta)
{
    __shared__ float gwT[16 * 257];    // transposed gate_W [e][c], pad 257 -> conflict-free
    int tid = threadIdx.x;
    for (int idx = tid; idx < 4096; idx += 256)
        gwT[(idx & 15) * 257 + (idx >> 4)] = gateW[idx];
    __syncthreads();

    int warp = tid >> 5, lane = tid & 31;
    int n = blockIdx.x * 8 + warp;
    const float* row = conv + (size_t)n * C_DIM;

    float x[8];
    float s = 0.f, s2 = 0.f;
#pragma unroll
    for (int i = 0; i < 8; i++) {
        x[i] = row[lane + 32 * i];
        s += x[i];
        s2 += x[i] * x[i];
    }
#pragma unroll
    for (int o = 16; o; o >>= 1) {
        s  += __shfl_xor_sync(0xffffffffu, s,  o);
        s2 += __shfl_xor_sync(0xffffffffu, s2, o);
    }
    float mu   = s * (1.f / 256.f);
    float var  = s2 * (1.f / 256.f) - mu * mu;
    float rstd = rsqrtf(var + 1e-5f);

    float r[8];
#pragma unroll
    for (int i = 0; i < 8; i++) {
        int c = lane + 32 * i;
        r[i] = (x[i] - mu) * rstd * gamma[c] + beta[c] + emb[c];
    }

    float logit[16];
#pragma unroll
    for (int e = 0; e < 16; e++) {
        float p = 0.f;
#pragma unroll
        for (int i = 0; i < 8; i++)
            p += r[i] * gwT[e * 257 + lane + 32 * i];
#pragma unroll
        for (int o = 16; o; o >>= 1)
            p += __shfl_xor_sync(0xffffffffu, p, o);
        logit[e] = p + gateB[e];
    }

    if (lane == 0) {
        float mx = logit[0];
#pragma unroll
        for (int e = 1; e < 16; e++) mx = fmaxf(mx, logit[e]);
        float w[16];
        float sum = 0.f;
#pragma unroll
        for (int e = 0; e < 16; e++) { w[e] = expf(logit[e] - mx); sum += w[e]; }
        float inv = 1.f / sum;
        float ent = 0.f;
#pragma unroll
        for (int e = 0; e < 16; e++) {
            w[e] *= inv;
            ent -= w[e] * logf(w[e] + 1e-12f);
        }
        // k = clip(ceil(1 + ent/ln(16) * 15), 1, 16)
        float kf = ceilf(1.f + ent * (15.f / 2.7725887222397811f));
        int k = (int)kf;
        k = k < 1 ? 1 : (k > 16 ? 16 : k);
#pragma unroll
        for (int e = 0; e < 16; e++) {
            int rank = 0;
#pragma unroll
            for (int j = 0; j < 16; j++)
                rank += (w[j] > w[e]) || (w[j] == w[e] && j < e);  // stable descending
            float cmb = (rank < k) ? w[e] : 0.f;
            g_combine[n * 16 + e] = cmb;
            g_w[n * 16 + e] = w[e];
        }
    }
}

// ---------------- kernel 2: deterministic balance-loss partials ----------------
__global__ __launch_bounds__(256) void loss_partial_kernel()
{
    int e = blockIdx.x;
    int tid = threadIdx.x;
    float st = 0.f, sp = 0.f;
    for (int n = tid; n < N_TOK; n += 256) {
        float c = g_combine[n * 16 + e];
        st += (c > 0.f) ? 1.f : 0.f;
        sp += g_w[n * 16 + e];
    }
    __shared__ float rt[256], rp[256];
    rt[tid] = st; rp[tid] = sp;
    __syncthreads();
    for (int o = 128; o; o >>= 1) {
        if (tid < o) { rt[tid] += rt[tid + o]; rp[tid] += rp[tid + o]; }
        __syncthreads();
    }
    if (tid == 0) {
        g_ft[e] = rt[0] * (1.f / (float)N_TOK);
        g_fp[e] = rp[0] * (1.f / (float)N_TOK);
    }
}

// ---------------- kernel 3: fused MoE + shared GEMM ----------------
// out[n,c] = sum_{m=0..16} s_m(n) * (X[n,:] @ W_m[:,c] + b_m[c]),  s_0=1 (share)
#define LDX 260
#define LDW 68

__global__ __launch_bounds__(256) void moe_gemm_kernel(
    const float* __restrict__ X,
    const float* __restrict__ shareW,
    const float* __restrict__ shareB,
    const float* __restrict__ expW,
    const float* __restrict__ expB,
    float* __restrict__ out)
{
    extern __shared__ float sm[];
    float* Xs = sm;                   // 64 x LDX (full K=256 resident)
    float* Ws = Xs + 64 * LDX;        // 64 x LDW (one K-chunk of W)
    float* Sc = Ws + 64 * LDW;        // 17 x 64 per-row scales
    float* Bs = Sc + 17 * 64;         // 17 x 64 per-col biases

    int tid = threadIdx.x;
    int rowBase = blockIdx.y * 64;
    int colBase = blockIdx.x * 64;

    // stage scales: Sc[0][*]=1 (share), Sc[e+1][r]=combine
    for (int idx = tid; idx < 1024; idx += 256) {
        int rr = idx >> 4, e = idx & 15;
        Sc[(e + 1) * 64 + rr] = g_combine[(rowBase + rr) * 16 + e];
    }
    if (tid < 64) Sc[tid] = 1.f;

    // stage biases
    for (int idx = tid; idx < 17 * 64; idx += 256) {
        int m = idx >> 6, cc = idx & 63;
        Bs[m * 64 + cc] = (m == 0) ? shareB[colBase + cc]
                                   : expB[(m - 1) * 256 + colBase + cc];
    }

    // stage X tile (64 rows x 256 cols), loaded ONCE, reused for all 17 matrices
    for (int idx = tid; idx < 64 * 64; idx += 256) {
        int rr = idx >> 6, k4 = idx & 63;
        float4 v = reinterpret_cast<const float4*>(X + (size_t)(rowBase + rr) * 256)[k4];
        *reinterpret_cast<float4*>(&Xs[rr * LDX + k4 * 4]) = v;
    }

    int ty = tid >> 4, tx = tid & 15;
    int r0 = ty * 4, c0 = tx * 4;

    float acc[4][4];
#pragma unroll
    for (int i = 0; i < 4; i++)
#pragma unroll
        for (int j = 0; j < 4; j++) acc[i][j] = 0.f;

    for (int m = 0; m < 17; m++) {
        const float* W = (m == 0) ? shareW : (expW + (size_t)(m - 1) * 65536);
        float p[4][4];
#pragma unroll
        for (int i = 0; i < 4; i++)
#pragma unroll
            for (int j = 0; j < 4; j++) p[i][j] = 0.f;

        for (int kk = 0; kk < 256; kk += 64) {
            __syncthreads();   // Ws consumed by previous chunk
            for (int idx = tid; idx < 1024; idx += 256) {
                int kr = idx >> 4, c4 = idx & 15;
                float4 v = reinterpret_cast<const float4*>(
                    W + (size_t)(kk + kr) * 256 + colBase)[c4];
                *reinterpret_cast<float4*>(&Ws[kr * LDW + c4 * 4]) = v;
            }
            __syncthreads();

#pragma unroll 8
            for (int k = 0; k < 64; k++) {
                float a0 = Xs[(r0 + 0) * LDX + kk + k];
                float a1 = Xs[(r0 + 1) * LDX + kk + k];
                float a2 = Xs[(r0 + 2) * LDX + kk + k];
                float a3 = Xs[(r0 + 3) * LDX + kk + k];
                float4 b = *reinterpret_cast<const float4*>(&Ws[k * LDW + c0]);
                p[0][0] += a0 * b.x; p[0][1] += a0 * b.y; p[0][2] += a0 * b.z; p[0][3] += a0 * b.w;
                p[1][0] += a1 * b.x; p[1][1] += a1 * b.y; p[1][2] += a1 * b.z; p[1][3] += a1 * b.w;
                p[2][0] += a2 * b.x; p[2][1] += a2 * b.y; p[2][2] += a2 * b.z; p[2][3] += a2 * b.w;
                p[3][0] += a3 * b.x; p[3][1] += a3 * b.y; p[3][2] += a3 * b.z; p[3][3] += a3 * b.w;
            }
        }

        // scaled accumulate + bias
#pragma unroll
        for (int i = 0; i < 4; i++) {
            float sv = Sc[m * 64 + r0 + i];
#pragma unroll
            for (int j = 0; j < 4; j++)
                acc[i][j] += sv * (p[i][j] + Bs[m * 64 + c0 + j]);
        }
    }

#pragma unroll
    for (int i = 0; i < 4; i++) {
        float4 v = make_float4(acc[i][0], acc[i][1], acc[i][2], acc[i][3]);
        *reinterpret_cast<float4*>(
            out + (size_t)(rowBase + r0 + i) * 256 + colBase + c0) = v;
    }
}

// ---------------- kernel 4: finalize loss scalar ----------------
__global__ void finalize_kernel(float* __restrict__ out, int out_size)
{
    const int NC = N_TOK * C_DIM;
    if (threadIdx.x == 0) {
        float accv = 0.f;
#pragma unroll
        for (int e = 0; e < 16; e++) accv += g_ft[e] * g_fp[e];
        float loss = accv * 16.f;   // mean(ft*fp)*E^2 = (sum/16)*256
        if (out_size > NC) out[NC] = loss;
    }
    // clear any additional padding in the output buffer (poisoned by harness)
    for (int i = NC + 1 + (int)threadIdx.x; i < out_size; i += (int)blockDim.x)
        out[i] = 0.f;
}

// ---------------- launch ----------------
extern "C" void kernel_launch(void* const* d_in, const int* in_sizes, int n_in,
                              void* d_out, int out_size)
{
    const float* inputs = (const float*)d_in[0];
    const float* conv   = (const float*)d_in[1];
    const float* emb    = (const float*)d_in[2];
    const float* shareW = (const float*)d_in[3];
    const float* shareB = (const float*)d_in[4];
    const float* gateW  = (const float*)d_in[5];
    const float* gateB  = (const float*)d_in[6];
    const float* expW   = (const float*)d_in[7];
    const float* expB   = (const float*)d_in[8];
    const float* gamma  = (const float*)d_in[9];
    const float* beta   = (const float*)d_in[10];
    float* out = (float*)d_out;

    router_kernel<<<N_TOK / 8, 256>>>(conv, emb, gateW, gateB, gamma, beta);
    loss_partial_kernel<<<16, 256>>>();

    const int smem_bytes = (64 * LDX + 64 * LDW + 17 * 64 + 17 * 64) * sizeof(float); // 92672
    cudaFuncSetAttribute(moe_gemm_kernel,
                         cudaFuncAttributeMaxDynamicSharedMemorySize, smem_bytes);
    moe_gemm_kernel<<<dim3(4, 512), 256, smem_bytes>>>(inputs, shareW, shareB,
                                                       expW, expB, out);
    finalize_kernel<<<1, 256>>>(out, out_size);
}

// round 3
// speedup vs baseline: 3.0025x; 3.0025x over previous
#include <cuda_runtime.h>
#include <cuda_bf16.h>
#include <math.h>
#include <stdint.h>

#define N_TOK 32768
#define C_DIM 256
#define E_NUM 16
#define NMAT 17

// ---------------- scratch (no allocations allowed) ----------------
__device__ float g_combine[N_TOK * E_NUM];
__device__ float g_w[N_TOK * E_NUM];
__device__ float g_ft[E_NUM];
__device__ float g_fp[E_NUM];
// W transposed to [mat][n][k] (K contiguous), split into bf16 hi/lo
__device__ __align__(128) __nv_bfloat16 g_Wthi[NMAT * C_DIM * C_DIM];
__device__ __align__(128) __nv_bfloat16 g_Wtlo[NMAT * C_DIM * C_DIM];

__device__ __forceinline__ uint32_t smem_u32(const void* p) {
    uint32_t a;
    asm("{ .reg .u64 t; cvta.to.shared.u64 t, %1; cvt.u32.u64 %0, t; }" : "=r"(a) : "l"(p));
    return a;
}

// ---------------- kernel 1: router (proven in round 1) ----------------
__global__ __launch_bounds__(256) void router_kernel(
    const float* __restrict__ conv, const float* __restrict__ emb,
    const float* __restrict__ gateW, const float* __restrict__ gateB,
    const float* __restrict__ gamma, const float* __restrict__ beta)
{
    __shared__ float gwT[16 * 257];
    int tid = threadIdx.x;
    for (int idx = tid; idx < 4096; idx += 256)
        gwT[(idx & 15) * 257 + (idx >> 4)] = gateW[idx];
    __syncthreads();

    int warp = tid >> 5, lane = tid & 31;
    int n = blockIdx.x * 8 + warp;
    const float* row = conv + (size_t)n * C_DIM;

    float x[8];
    float s = 0.f, s2 = 0.f;
#pragma unroll
    for (int i = 0; i < 8; i++) {
        x[i] = row[lane + 32 * i];
        s += x[i]; s2 += x[i] * x[i];
    }
#pragma unroll
    for (int o = 16; o; o >>= 1) {
        s  += __shfl_xor_sync(0xffffffffu, s,  o);
        s2 += __shfl_xor_sync(0xffffffffu, s2, o);
    }
    float mu = s * (1.f / 256.f);
    float var = s2 * (1.f / 256.f) - mu * mu;
    float rstd = rsqrtf(var + 1e-5f);

    float r[8];
#pragma unroll
    for (int i = 0; i < 8; i++) {
        int c = lane + 32 * i;
        r[i] = (x[i] - mu) * rstd * gamma[c] + beta[c] + emb[c];
    }

    float logit[16];
#pragma unroll
    for (int e = 0; e < 16; e++) {
        float p = 0.f;
#pragma unroll
        for (int i = 0; i < 8; i++) p += r[i] * gwT[e * 257 + lane + 32 * i];
#pragma unroll
        for (int o = 16; o; o >>= 1) p += __shfl_xor_sync(0xffffffffu, p, o);
        logit[e] = p + gateB[e];
    }

    if (lane == 0) {
        float mx = logit[0];
#pragma unroll
        for (int e = 1; e < 16; e++) mx = fmaxf(mx, logit[e]);
        float w[16]; float sum = 0.f;
#pragma unroll
        for (int e = 0; e < 16; e++) { w[e] = expf(logit[e] - mx); sum += w[e]; }
        float inv = 1.f / sum; float ent = 0.f;
#pragma unroll
        for (int e = 0; e < 16; e++) { w[e] *= inv; ent -= w[e] * logf(w[e] + 1e-12f); }
        float kf = ceilf(1.f + ent * (15.f / 2.7725887222397811f));
        int k = (int)kf; k = k < 1 ? 1 : (k > 16 ? 16 : k);
#pragma unroll
        for (int e = 0; e < 16; e++) {
            int rank = 0;
#pragma unroll
            for (int j = 0; j < 16; j++)
                rank += (w[j] > w[e]) || (w[j] == w[e] && j < e);
            g_combine[n * 16 + e] = (rank < k) ? w[e] : 0.f;
            g_w[n * 16 + e] = w[e];
        }
    }
}

// ---------------- kernel 2: balance-loss partials ----------------
__global__ __launch_bounds__(256) void loss_partial_kernel()
{
    int e = blockIdx.x, tid = threadIdx.x;
    float st = 0.f, sp = 0.f;
    for (int n = tid; n < N_TOK; n += 256) {
        st += (g_combine[n * 16 + e] > 0.f) ? 1.f : 0.f;
        sp += g_w[n * 16 + e];
    }
    __shared__ float rt[256], rp[256];
    rt[tid] = st; rp[tid] = sp;
    __syncthreads();
    for (int o = 128; o; o >>= 1) {
        if (tid < o) { rt[tid] += rt[tid + o]; rp[tid] += rp[tid + o]; }
        __syncthreads();
    }
    if (tid == 0) {
        g_ft[e] = rt[0] * (1.f / (float)N_TOK);
        g_fp[e] = rp[0] * (1.f / (float)N_TOK);
    }
}

// ---------------- kernel 3: W transpose + bf16 hi/lo split ----------------
__global__ __launch_bounds__(256) void wprep_kernel(
    const float* __restrict__ shareW, const float* __restrict__ expW)
{
    __shared__ float tile[32][33];
    int m = blockIdx.z;
    const float* src = (m == 0) ? shareW : expW + (size_t)(m - 1) * 65536;
    int tx = threadIdx.x & 31, ty = threadIdx.x >> 5;
#pragma unroll
    for (int i = 0; i < 4; i++) {
        int k = blockIdx.y * 32 + ty + i * 8;
        int n = blockIdx.x * 32 + tx;
        tile[ty + i * 8][tx] = src[k * 256 + n];
    }
    __syncthreads();
#pragma unroll
    for (int i = 0; i < 4; i++) {
        int n = blockIdx.x * 32 + ty + i * 8;
        int k = blockIdx.y * 32 + tx;
        float v = tile[tx][ty + i * 8];
        __nv_bfloat16 h = __float2bfloat16(v);
        float lo = v - __bfloat162float(h);
        size_t o = (size_t)m * 65536 + (size_t)n * 256 + k;
        g_Wthi[o] = h;
        g_Wtlo[o] = __float2bfloat16(lo);
    }
}

// ---------------- kernel 4: mma.sync fused MoE GEMM ----------------
// SMEM byte offsets
#define XH_OFF 0            // 128 rows x 528B (256 bf16 + 8 pad)
#define XL_OFF 67584
#define WB_OFF 135168       // 2 bufs x (hi,lo) x 128 rows x 144B (64 bf16 + 8 pad)
#define SC_OFF 208896       // 128 x 17 f32 (slot 0 = 1.0 for share)
#define BS_OFF 217600       // 17 x 128 f32 biases
#define SMEM_BYTES 226304

#define LDSM4(R, A) \
    asm volatile("ldmatrix.sync.aligned.m8n8.x4.shared.b16 {%0,%1,%2,%3}, [%4];" \
        : "=r"((R)[0]), "=r"((R)[1]), "=r"((R)[2]), "=r"((R)[3]) : "r"(A))
#define LDSM2(R, A) \
    asm volatile("ldmatrix.sync.aligned.m8n8.x2.shared.b16 {%0,%1}, [%2];" \
        : "=r"((R)[0]), "=r"((R)[1]) : "r"(A))
#define MMA16816(D, A, B) \
    asm volatile("mma.sync.aligned.m16n8k16.row.col.f32.bf16.bf16.f32 " \
        "{%0,%1,%2,%3}, {%4,%5,%6,%7}, {%8,%9}, {%0,%1,%2,%3};" \
        : "+f"((D)[0]), "+f"((D)[1]), "+f"((D)[2]), "+f"((D)[3]) \
        : "r"((A)[0]), "r"((A)[1]), "r"((A)[2]), "r"((A)[3]), "r"((B)[0]), "r"((B)[1]))

__device__ __forceinline__ uint32_t packbf(float a, float b) {
    uint16_t la = __bfloat16_as_ushort(__float2bfloat16(a));
    uint16_t lb = __bfloat16_as_ushort(__float2bfloat16(b));
    return (uint32_t)la | ((uint32_t)lb << 16);
}

__device__ __forceinline__ void prefetch_chunk(uint32_t wb, int t, int colBase, int tid)
{
    int m = t >> 2, c = t & 3, buf = t & 1;
#pragma unroll
    for (int i = 0; i < 8; i++) {
        int idx = tid + i * 256;           // 0..2047
        int half = idx >> 10;              // 0: hi, 1: lo
        int rr = (idx >> 3) & 127;         // n row 0..127
        int q = idx & 7;                   // 16B segment along k
        const __nv_bfloat16* src = (half ? g_Wtlo : g_Wthi) +
            (size_t)m * 65536 + (size_t)(colBase + rr) * 256 + c * 64 + q * 8;
        uint32_t dst = wb + buf * 36864 + half * 18432 + rr * 144 + q * 16;
        asm volatile("cp.async.cg.shared.global [%0], [%1], 16;"
                     :: "r"(dst), "l"(src) : "memory");
    }
    asm volatile("cp.async.commit_group;" ::: "memory");
}

__global__ __launch_bounds__(256, 1) void moe_mma_kernel(
    const float* __restrict__ X,
    const float* __restrict__ shareB,
    const float* __restrict__ expB,
    float* __restrict__ out)
{
    extern __shared__ char smc[];
    const int tid = threadIdx.x;
    const int lane = tid & 31, warp = tid >> 5;
    const int rowBase = blockIdx.y * 128;
    const int colBase = blockIdx.x * 128;
    const uint32_t sb = smem_u32(smc);

    float* Sc = reinterpret_cast<float*>(smc + SC_OFF);
    float* Bs = reinterpret_cast<float*>(smc + BS_OFF);

    // stage scales (slot 0 = share = 1.0) and biases
    for (int idx = tid; idx < 128 * 17; idx += 256) {
        int r = idx / 17, m = idx % 17;
        Sc[idx] = (m == 0) ? 1.0f : g_combine[(size_t)(rowBase + r) * 16 + (m - 1)];
    }
    for (int idx = tid; idx < 17 * 128; idx += 256) {
        int m = idx >> 7, c = idx & 127;
        Bs[idx] = (m == 0) ? shareB[colBase + c] : expB[(m - 1) * 256 + colBase + c];
    }

    // stage X hi/lo, padded row-major (stride 528B)
    const float* Xb = X + (size_t)rowBase * 256;
#pragma unroll 4
    for (int it = 0; it < 32; it++) {
        int idx = tid + it * 256;
        int r = idx >> 6, k4 = idx & 63;
        float4 v = reinterpret_cast<const float4*>(Xb + (size_t)r * 256)[k4];
        float hx = __bfloat162float(__float2bfloat16(v.x));
        float hy = __bfloat162float(__float2bfloat16(v.y));
        float hz = __bfloat162float(__float2bfloat16(v.z));
        float hw = __bfloat162float(__float2bfloat16(v.w));
        uint2 hi = make_uint2(packbf(v.x, v.y), packbf(v.z, v.w));
        uint2 lo = make_uint2(packbf(v.x - hx, v.y - hy), packbf(v.z - hz, v.w - hw));
        *reinterpret_cast<uint2*>(smc + XH_OFF + r * 528 + k4 * 8) = hi;
        *reinterpret_cast<uint2*>(smc + XL_OFF + r * 528 + k4 * 8) = lo;
    }

    // warp tiling: 2 (M) x 4 (N) warps; each warp 64(M) x 32(N)
    const int m0 = (warp & 1) * 64;
    const int n0 = (warp >> 1) * 32;

    // per-lane ldmatrix base addresses
    const uint32_t xh_base = sb + XH_OFF + (uint32_t)(m0 + (lane & 15)) * 528 + (lane >> 4) * 16;
    const uint32_t xl_base = xh_base + (XL_OFF - XH_OFF);
    const uint32_t wb_base = sb + WB_OFF + (uint32_t)(n0 + (lane & 7)) * 144 + ((lane >> 3) & 1) * 16;

    float acc[4][4][4];
#pragma unroll
    for (int mt = 0; mt < 4; mt++)
#pragma unroll
        for (int nt = 0; nt < 4; nt++)
#pragma unroll
            for (int q = 0; q < 4; q++) acc[mt][nt][q] = 0.f;

    prefetch_chunk(sb + WB_OFF, 0, colBase, tid);
    __syncthreads();   // X/Sc/Bs staged

    float p[4][4][4];

#pragma unroll 1
    for (int t = 0; t < NMAT * 4; t++) {
        const int c = t & 3, buf = t & 1, m = t >> 2;

        if (t + 1 < NMAT * 4) {
            prefetch_chunk(sb + WB_OFF, t + 1, colBase, tid);
            asm volatile("cp.async.wait_group 1;" ::: "memory");
        } else {
            asm volatile("cp.async.wait_group 0;" ::: "memory");
        }
        __syncthreads();

        if (c == 0) {
#pragma unroll
            for (int mt = 0; mt < 4; mt++)
#pragma unroll
                for (int nt = 0; nt < 4; nt++)
#pragma unroll
                    for (int q = 0; q < 4; q++) p[mt][nt][q] = 0.f;
        }

#pragma unroll
        for (int ks = 0; ks < 4; ks++) {
            const uint32_t kOff = (uint32_t)(c * 64 + ks * 16) * 2;
            uint32_t Ah[4][4], Al[4][4], Bh[4][2], Bl[4][2];
#pragma unroll
            for (int mt = 0; mt < 4; mt++) {
                LDSM4(Ah[mt], xh_base + mt * (16 * 528) + kOff);
                LDSM4(Al[mt], xl_base + mt * (16 * 528) + kOff);
            }
            const uint32_t wOff = wb_base + buf * 36864 + ks * 32;
#pragma unroll
            for (int nt = 0; nt < 4; nt++) {
                LDSM2(Bh[nt], wOff + nt * (8 * 144));
                LDSM2(Bl[nt], wOff + nt * (8 * 144) + 18432);
            }
            // term order: hh, hl, lh — 16 independent chains each
#pragma unroll
            for (int mt = 0; mt < 4; mt++)
#pragma unroll
                for (int nt = 0; nt < 4; nt++)
                    MMA16816(p[mt][nt], Ah[mt], Bh[nt]);
#pragma unroll
            for (int mt = 0; mt < 4; mt++)
#pragma unroll
                for (int nt = 0; nt < 4; nt++)
                    MMA16816(p[mt][nt], Ah[mt], Bl[nt]);
#pragma unroll
            for (int mt = 0; mt < 4; mt++)
#pragma unroll
                for (int nt = 0; nt < 4; nt++)
                    MMA16816(p[mt][nt], Al[mt], Bh[nt]);
        }

        if (c == 3) {
            // epilogue: acc += s_row * (p + bias_col)
            float bv[4][2];
#pragma unroll
            for (int nt = 0; nt < 4; nt++) {
                float2 b2 = *reinterpret_cast<const float2*>(
                    &Bs[m * 128 + n0 + nt * 8 + (lane & 3) * 2]);
                bv[nt][0] = b2.x; bv[nt][1] = b2.y;
            }
#pragma unroll
            for (int mt = 0; mt < 4; mt++) {
                int r = m0 + mt * 16 + (lane >> 2);
                float s0 = Sc[r * 17 + m];
                float s1 = Sc[(r + 8) * 17 + m];
#pragma unroll
                for (int nt = 0; nt < 4; nt++) {
                    acc[mt][nt][0] += s0 * (p[mt][nt][0] + bv[nt][0]);
                    acc[mt][nt][1] += s0 * (p[mt][nt][1] + bv[nt][1]);
                    acc[mt][nt][2] += s1 * (p[mt][nt][2] + bv[nt][0]);
                    acc[mt][nt][3] += s1 * (p[mt][nt][3] + bv[nt][1]);
                }
            }
        }
        __syncthreads();   // protect buffer reuse by next prefetch
    }

    // write output
#pragma unroll
    for (int mt = 0; mt < 4; mt++) {
        int rg = rowBase + m0 + mt * 16 + (lane >> 2);
#pragma unroll
        for (int nt = 0; nt < 4; nt++) {
            int cg = colBase + n0 + nt * 8 + (lane & 3) * 2;
            *reinterpret_cast<float2*>(out + (size_t)rg * 256 + cg) =
                make_float2(acc[mt][nt][0], acc[mt][nt][1]);
            *reinterpret_cast<float2*>(out + (size_t)(rg + 8) * 256 + cg) =
                make_float2(acc[mt][nt][2], acc[mt][nt][3]);
        }
    }
}

// ---------------- kernel 5: finalize ----------------
__global__ void finalize_kernel(float* __restrict__ out, int out_size)
{
    const int NC = N_TOK * C_DIM;
    if (threadIdx.x == 0) {
        float a = 0.f;
#pragma unroll
        for (int e = 0; e < 16; e++) a += g_ft[e] * g_fp[e];
        if (out_size > NC) out[NC] = a * 16.f;
    }
    for (int i = NC + 1 + (int)threadIdx.x; i < out_size; i += (int)blockDim.x)
        out[i] = 0.f;
}

// ---------------- launch ----------------
extern "C" void kernel_launch(void* const* d_in, const int* in_sizes, int n_in,
                              void* d_out, int out_size)
{
    const float* inputs = (const float*)d_in[0];
    const float* conv   = (const float*)d_in[1];
    const float* emb    = (const float*)d_in[2];
    const float* shareW = (const float*)d_in[3];
    const float* shareB = (const float*)d_in[4];
    const float* gateW  = (const float*)d_in[5];
    const float* gateB  = (const float*)d_in[6];
    const float* expW   = (const float*)d_in[7];
    const float* expB   = (const float*)d_in[8];
    const float* gamma  = (const float*)d_in[9];
    const float* beta   = (const float*)d_in[10];
    float* out = (float*)d_out;

    router_kernel<<<N_TOK / 8, 256>>>(conv, emb, gateW, gateB, gamma, beta);
    loss_partial_kernel<<<16, 256>>>();
    wprep_kernel<<<dim3(8, 8, NMAT), 256>>>(shareW, expW);

    cudaFuncSetAttribute(moe_mma_kernel,
                         cudaFuncAttributeMaxDynamicSharedMemorySize, SMEM_BYTES);
    moe_mma_kernel<<<dim3(2, 256), 256, SMEM_BYTES>>>(inputs, shareB, expB, out);

    finalize_kernel<<<1, 256>>>(out, out_size);
}

// round 4
// speedup vs baseline: 3.1126x; 1.0367x over previous
#include <cuda_runtime.h>
#include <cuda_bf16.h>
#include <math.h>
#include <stdint.h>

#define N_TOK 32768
#define C_DIM 256
#define E_NUM 16
#define NMAT 17

// ---------------- scratch (no allocations allowed) ----------------
__device__ float g_combine[N_TOK * E_NUM];
__device__ float g_w[N_TOK * E_NUM];
__device__ float g_ft[E_NUM];
__device__ float g_fp[E_NUM];
// W transposed to [mat][n][k] (K contiguous), split into bf16 hi/lo
__device__ __align__(128) __nv_bfloat16 g_Wthi[NMAT * C_DIM * C_DIM];
__device__ __align__(128) __nv_bfloat16 g_Wtlo[NMAT * C_DIM * C_DIM];

__device__ __forceinline__ uint32_t smem_u32(const void* p) {
    uint32_t a;
    asm("{ .reg .u64 t; cvta.to.shared.u64 t, %1; cvt.u32.u64 %0, t; }" : "=r"(a) : "l"(p));
    return a;
}

// ---------------- kernel 1: router (64 tokens/block) ----------------
__global__ __launch_bounds__(256) void router_kernel(
    const float* __restrict__ conv, const float* __restrict__ emb,
    const float* __restrict__ gateW, const float* __restrict__ gateB,
    const float* __restrict__ gamma, const float* __restrict__ beta)
{
    __shared__ float gwT[16 * 257];
    __shared__ float gbev[3 * 256 + 16];   // gamma, beta, emb, gateB staged
    int tid = threadIdx.x;
    for (int idx = tid; idx < 4096; idx += 256)
        gwT[(idx & 15) * 257 + (idx >> 4)] = gateW[idx];
    if (tid < 256) {
        gbev[tid] = gamma[tid];
        gbev[256 + tid] = beta[tid];
        gbev[512 + tid] = emb[tid];
    }
    if (tid < 16) gbev[768 + tid] = gateB[tid];
    __syncthreads();

    int warp = tid >> 5, lane = tid & 31;

#pragma unroll 1
    for (int i = 0; i < 8; i++) {
        int n = blockIdx.x * 64 + warp * 8 + i;
        const float* row = conv + (size_t)n * C_DIM;

        float x[8];
        float s = 0.f, s2 = 0.f;
#pragma unroll
        for (int j = 0; j < 8; j++) {
            x[j] = row[lane + 32 * j];
            s += x[j]; s2 += x[j] * x[j];
        }
#pragma unroll
        for (int o = 16; o; o >>= 1) {
            s  += __shfl_xor_sync(0xffffffffu, s,  o);
            s2 += __shfl_xor_sync(0xffffffffu, s2, o);
        }
        float mu = s * (1.f / 256.f);
        float var = s2 * (1.f / 256.f) - mu * mu;
        float rstd = rsqrtf(var + 1e-5f);

        float r[8];
#pragma unroll
        for (int j = 0; j < 8; j++) {
            int c = lane + 32 * j;
            r[j] = (x[j] - mu) * rstd * gbev[c] + gbev[256 + c] + gbev[512 + c];
        }

        float logit[16];
#pragma unroll
        for (int e = 0; e < 16; e++) {
            float p = 0.f;
#pragma unroll
            for (int j = 0; j < 8; j++) p += r[j] * gwT[e * 257 + lane + 32 * j];
#pragma unroll
            for (int o = 16; o; o >>= 1) p += __shfl_xor_sync(0xffffffffu, p, o);
            logit[e] = p + gbev[768 + e];
        }

        if (lane == 0) {
            float mx = logit[0];
#pragma unroll
            for (int e = 1; e < 16; e++) mx = fmaxf(mx, logit[e]);
            float w[16]; float sum = 0.f;
#pragma unroll
            for (int e = 0; e < 16; e++) { w[e] = expf(logit[e] - mx); sum += w[e]; }
            float inv = 1.f / sum; float ent = 0.f;
#pragma unroll
            for (int e = 0; e < 16; e++) { w[e] *= inv; ent -= w[e] * logf(w[e] + 1e-12f); }
            float kf = ceilf(1.f + ent * (15.f / 2.7725887222397811f));
            int k = (int)kf; k = k < 1 ? 1 : (k > 16 ? 16 : k);
#pragma unroll
            for (int e = 0; e < 16; e++) {
                int rank = 0;
#pragma unroll
                for (int j = 0; j < 16; j++)
                    rank += (w[j] > w[e]) || (w[j] == w[e] && j < e);
                g_combine[n * 16 + e] = (rank < k) ? w[e] : 0.f;
                g_w[n * 16 + e] = w[e];
            }
        }
    }
}

// ---------------- kernel 2: balance-loss partials ----------------
__global__ __launch_bounds__(256) void loss_partial_kernel()
{
    int e = blockIdx.x, tid = threadIdx.x;
    float st = 0.f, sp = 0.f;
    for (int n = tid; n < N_TOK; n += 256) {
        st += (g_combine[n * 16 + e] > 0.f) ? 1.f : 0.f;
        sp += g_w[n * 16 + e];
    }
    __shared__ float rt[256], rp[256];
    rt[tid] = st; rp[tid] = sp;
    __syncthreads();
    for (int o = 128; o; o >>= 1) {
        if (tid < o) { rt[tid] += rt[tid + o]; rp[tid] += rp[tid + o]; }
        __syncthreads();
    }
    if (tid == 0) {
        g_ft[e] = rt[0] * (1.f / (float)N_TOK);
        g_fp[e] = rp[0] * (1.f / (float)N_TOK);
    }
}

// ---------------- kernel 3: W transpose + bf16 hi/lo split ----------------
__global__ __launch_bounds__(256) void wprep_kernel(
    const float* __restrict__ shareW, const float* __restrict__ expW)
{
    __shared__ float tile[32][33];
    int m = blockIdx.z;
    const float* src = (m == 0) ? shareW : expW + (size_t)(m - 1) * 65536;
    int tx = threadIdx.x & 31, ty = threadIdx.x >> 5;
#pragma unroll
    for (int i = 0; i < 4; i++) {
        int k = blockIdx.y * 32 + ty + i * 8;
        int n = blockIdx.x * 32 + tx;
        tile[ty + i * 8][tx] = src[k * 256 + n];
    }
    __syncthreads();
#pragma unroll
    for (int i = 0; i < 4; i++) {
        int n = blockIdx.x * 32 + ty + i * 8;
        int k = blockIdx.y * 32 + tx;
        float v = tile[tx][ty + i * 8];
        __nv_bfloat16 h = __float2bfloat16(v);
        float lo = v - __bfloat162float(h);
        size_t o = (size_t)m * 65536 + (size_t)n * 256 + k;
        g_Wthi[o] = h;
        g_Wtlo[o] = __float2bfloat16(lo);
    }
}

// ---------------- kernel 4: mma.sync fused MoE GEMM v2 ----------------
// CTA tile 128(M) x 64(N); grid (4, 256). 8 warps: 4(M) x 2(N), warp 32x32.
// SMEM byte offsets
#define XH_OFF 0            // 128 rows x 528B (256 bf16 + 8 pad)
#define XL_OFF 67584
#define WS_OFF 135168       // 4 stages x (hi,lo) x 64 rows x 144B
#define SC_OFF 208896       // [17][128] f32 scales (slot 0 = 1.0 share)
#define BS_OFF 217600       // [17][64] f32 biases
#define SMEM_BYTES 221952

#define LDSM4(R, A) \
    asm volatile("ldmatrix.sync.aligned.m8n8.x4.shared.b16 {%0,%1,%2,%3}, [%4];" \
        : "=r"((R)[0]), "=r"((R)[1]), "=r"((R)[2]), "=r"((R)[3]) : "r"(A))
#define LDSM2(R, A) \
    asm volatile("ldmatrix.sync.aligned.m8n8.x2.shared.b16 {%0,%1}, [%2];" \
        : "=r"((R)[0]), "=r"((R)[1]) : "r"(A))
#define MMA16816(D, A, B) \
    asm volatile("mma.sync.aligned.m16n8k16.row.col.f32.bf16.bf16.f32 " \
        "{%0,%1,%2,%3}, {%4,%5,%6,%7}, {%8,%9}, {%0,%1,%2,%3};" \
        : "+f"((D)[0]), "+f"((D)[1]), "+f"((D)[2]), "+f"((D)[3]) \
        : "r"((A)[0]), "r"((A)[1]), "r"((A)[2]), "r"((A)[3]), "r"((B)[0]), "r"((B)[1]))

__device__ __forceinline__ uint32_t packbf(float a, float b) {
    uint16_t la = __bfloat16_as_ushort(__float2bfloat16(a));
    uint16_t lb = __bfloat16_as_ushort(__float2bfloat16(b));
    return (uint32_t)la | ((uint32_t)lb << 16);
}

// prefetch W stage for task t (t = c*17 + m), chunk c, matrix m
__device__ __forceinline__ void prefetch_w(uint32_t wbase, int t, int colBase, int tid)
{
    const int c = t / 17;
    const int m = t - c * 17;
    const int stage = t & 3;
#pragma unroll
    for (int i = 0; i < 4; i++) {
        int idx = tid + i * 256;           // 0..1023
        int half = idx >> 9;               // 0: hi, 1: lo
        int r = (idx >> 3) & 63;           // n row within CTA slice
        int q = idx & 7;                   // 16B segment along k
        const __nv_bfloat16* src = (half ? g_Wtlo : g_Wthi) +
            (size_t)m * 65536 + (size_t)(colBase + r) * 256 + c * 64 + q * 8;
        uint32_t dst = wbase + stage * 18432 + half * 9216 + r * 144 + q * 16;
        asm volatile("cp.async.cg.shared.global [%0], [%1], 16;"
                     :: "r"(dst), "l"(src) : "memory");
    }
}

__global__ __launch_bounds__(256, 1) void moe_mma_kernel(
    const float* __restrict__ X,
    const float* __restrict__ shareB,
    const float* __restrict__ expB,
    float* __restrict__ out)
{
    extern __shared__ char smc[];
    const int tid = threadIdx.x;
    const int lane = tid & 31, warp = tid >> 5;
    const int rowBase = blockIdx.y * 128;
    const int colBase = blockIdx.x * 64;
    const uint32_t sb = smem_u32(smc);
    const uint32_t wbase = sb + WS_OFF;

    // kick off W prefetch for stages 0..2 immediately
    prefetch_w(wbase, 0, colBase, tid);
    asm volatile("cp.async.commit_group;" ::: "memory");
    prefetch_w(wbase, 1, colBase, tid);
    asm volatile("cp.async.commit_group;" ::: "memory");
    prefetch_w(wbase, 2, colBase, tid);
    asm volatile("cp.async.commit_group;" ::: "memory");

    float* Sc = reinterpret_cast<float*>(smc + SC_OFF);
    float* Bs = reinterpret_cast<float*>(smc + BS_OFF);

    // stage scales [17][128] (slot 0 = share = 1.0)
    for (int idx = tid; idx < 17 * 128; idx += 256) {
        int m = idx >> 7, r = idx & 127;
        Sc[idx] = (m == 0) ? 1.0f : g_combine[(size_t)(rowBase + r) * 16 + (m - 1)];
    }
    // stage biases [17][64]
    for (int idx = tid; idx < 17 * 64; idx += 256) {
        int m = idx >> 6, c = idx & 63;
        Bs[idx] = (m == 0) ? shareB[colBase + c] : expB[(m - 1) * 256 + colBase + c];
    }

    // stage X hi/lo, padded row-major (stride 528B), full K resident
    const float* Xb = X + (size_t)rowBase * 256;
#pragma unroll 4
    for (int it = 0; it < 32; it++) {
        int idx = tid + it * 256;
        int r = idx >> 6, k4 = idx & 63;
        float4 v = reinterpret_cast<const float4*>(Xb + (size_t)r * 256)[k4];
        float hx = __bfloat162float(__float2bfloat16(v.x));
        float hy = __bfloat162float(__float2bfloat16(v.y));
        float hz = __bfloat162float(__float2bfloat16(v.z));
        float hw = __bfloat162float(__float2bfloat16(v.w));
        uint2 hi = make_uint2(packbf(v.x, v.y), packbf(v.z, v.w));
        uint2 lo = make_uint2(packbf(v.x - hx, v.y - hy), packbf(v.z - hz, v.w - hw));
        *reinterpret_cast<uint2*>(smc + XH_OFF + r * 528 + k4 * 8) = hi;
        *reinterpret_cast<uint2*>(smc + XL_OFF + r * 528 + k4 * 8) = lo;
    }
    __syncthreads();   // X / Sc / Bs visible

    // warp tiling: m0 in {0,32,64,96}, n0 in {0,32}; warp computes 32x32
    const int m0 = (warp & 3) * 32;
    const int n0 = (warp >> 2) * 32;

    const uint32_t xh_base = sb + XH_OFF + (uint32_t)(m0 + (lane & 15)) * 528 + (lane >> 4) * 16;
    const uint32_t xl_base = xh_base + (uint32_t)(XL_OFF - XH_OFF);
    const uint32_t wb_base = wbase + (uint32_t)(n0 + (lane & 7)) * 144 + ((lane >> 3) & 1) * 16;

    // acc init = combined bias: sum_m s_m * b_m (m=0 share with s=1)
    const int rq = lane >> 2;           // 0..7
    const int cq = (lane & 3) * 2;      // 0,2,4,6
    float acc[2][4][4];
#pragma unroll
    for (int mt = 0; mt < 2; mt++)
#pragma unroll
        for (int nt = 0; nt < 4; nt++)
#pragma unroll
            for (int q = 0; q < 4; q++) acc[mt][nt][q] = 0.f;
#pragma unroll 1
    for (int m = 0; m < NMAT; m++) {
        float s00 = Sc[m * 128 + m0 + rq];
        float s01 = Sc[m * 128 + m0 + rq + 8];
        float s10 = Sc[m * 128 + m0 + rq + 16];
        float s11 = Sc[m * 128 + m0 + rq + 24];
#pragma unroll
        for (int nt = 0; nt < 4; nt++) {
            float b0 = Bs[m * 64 + n0 + nt * 8 + cq];
            float b1 = Bs[m * 64 + n0 + nt * 8 + cq + 1];
            acc[0][nt][0] += s00 * b0; acc[0][nt][1] += s00 * b1;
            acc[0][nt][2] += s01 * b0; acc[0][nt][3] += s01 * b1;
            acc[1][nt][0] += s10 * b0; acc[1][nt][1] += s10 * b1;
            acc[1][nt][2] += s11 * b0; acc[1][nt][3] += s11 * b1;
        }
    }

    uint32_t Ah[4][2][4], Al[4][2][4];
    float p[2][4][4];

#pragma unroll 1
    for (int t = 0; t < NMAT * 4; t++) {
        const int c = t / 17;
        const int m = t - c * 17;
        const int stage = t & 3;

        asm volatile("cp.async.wait_group 2;" ::: "memory");
        __syncthreads();   // stage t data visible to all; prior compute drained

        if (m == 0) {
            // load A fragments for chunk c (reused across all 17 matrices)
#pragma unroll
            for (int ks = 0; ks < 4; ks++) {
                const uint32_t kOff = (uint32_t)(c * 64 + ks * 16) * 2;
#pragma unroll
                for (int mt = 0; mt < 2; mt++) {
                    LDSM4(Ah[ks][mt], xh_base + mt * (16 * 528) + kOff);
                    LDSM4(Al[ks][mt], xl_base + mt * (16 * 528) + kOff);
                }
            }
        }

#pragma unroll
        for (int mt = 0; mt < 2; mt++)
#pragma unroll
            for (int nt = 0; nt < 4; nt++)
#pragma unroll
                for (int q = 0; q < 4; q++) p[mt][nt][q] = 0.f;

        const uint32_t wbs = wb_base + stage * 18432;
#pragma unroll
        for (int ks = 0; ks < 4; ks++) {
            uint32_t Bh[4][2], Bl[4][2];
#pragma unroll
            for (int nt = 0; nt < 4; nt++) {
                LDSM2(Bh[nt], wbs + nt * (8 * 144) + ks * 32);
                LDSM2(Bl[nt], wbs + 9216 + nt * (8 * 144) + ks * 32);
            }
#pragma unroll
            for (int mt = 0; mt < 2; mt++)
#pragma unroll
                for (int nt = 0; nt < 4; nt++)
                    MMA16816(p[mt][nt], Ah[ks][mt], Bh[nt]);
#pragma unroll
            for (int mt = 0; mt < 2; mt++)
#pragma unroll
                for (int nt = 0; nt < 4; nt++)
                    MMA16816(p[mt][nt], Ah[ks][mt], Bl[nt]);
#pragma unroll
            for (int mt = 0; mt < 2; mt++)
#pragma unroll
                for (int nt = 0; nt < 4; nt++)
                    MMA16816(p[mt][nt], Al[ks][mt], Bh[nt]);
        }

        // epilogue: acc += s_row * p
        {
            float s00 = Sc[m * 128 + m0 + rq];
            float s01 = Sc[m * 128 + m0 + rq + 8];
            float s10 = Sc[m * 128 + m0 + rq + 16];
            float s11 = Sc[m * 128 + m0 + rq + 24];
#pragma unroll
            for (int nt = 0; nt < 4; nt++) {
                acc[0][nt][0] += s00 * p[0][nt][0];
                acc[0][nt][1] += s00 * p[0][nt][1];
                acc[0][nt][2] += s01 * p[0][nt][2];
                acc[0][nt][3] += s01 * p[0][nt][3];
                acc[1][nt][0] += s10 * p[1][nt][0];
                acc[1][nt][1] += s10 * p[1][nt][1];
                acc[1][nt][2] += s11 * p[1][nt][2];
                acc[1][nt][3] += s11 * p[1][nt][3];
            }
        }

        // prefetch next stage (always commit to keep group arithmetic valid)
        if (t + 3 < NMAT * 4) prefetch_w(wbase, t + 3, colBase, tid);
        asm volatile("cp.async.commit_group;" ::: "memory");
    }

    // write output
#pragma unroll
    for (int mt = 0; mt < 2; mt++) {
        int rg = rowBase + m0 + mt * 16 + rq;
#pragma unroll
        for (int nt = 0; nt < 4; nt++) {
            int cg = colBase + n0 + nt * 8 + cq;
            *reinterpret_cast<float2*>(out + (size_t)rg * 256 + cg) =
                make_float2(acc[mt][nt][0], acc[mt][nt][1]);
            *reinterpret_cast<float2*>(out + (size_t)(rg + 8) * 256 + cg) =
                make_float2(acc[mt][nt][2], acc[mt][nt][3]);
        }
    }
}

// ---------------- kernel 5: finalize ----------------
__global__ void finalize_kernel(float* __restrict__ out, int out_size)
{
    const int NC = N_TOK * C_DIM;
    if (threadIdx.x == 0) {
        float a = 0.f;
#pragma unroll
        for (int e = 0; e < 16; e++) a += g_ft[e] * g_fp[e];
        if (out_size > NC) out[NC] = a * 16.f;
    }
    for (int i = NC + 1 + (int)threadIdx.x; i < out_size; i += (int)blockDim.x)
        out[i] = 0.f;
}

// ---------------- launch ----------------
extern "C" void kernel_launch(void* const* d_in, const int* in_sizes, int n_in,
                              void* d_out, int out_size)
{
    const float* inputs = (const float*)d_in[0];
    const float* conv   = (const float*)d_in[1];
    const float* emb    = (const float*)d_in[2];
    const float* shareW = (const float*)d_in[3];
    const float* shareB = (const float*)d_in[4];
    const float* gateW  = (const float*)d_in[5];
    const float* gateB  = (const float*)d_in[6];
    const float* expW   = (const float*)d_in[7];
    const float* expB   = (const float*)d_in[8];
    const float* gamma  = (const float*)d_in[9];
    const float* beta   = (const float*)d_in[10];
    float* out = (float*)d_out;

    router_kernel<<<N_TOK / 64, 256>>>(conv, emb, gateW, gateB, gamma, beta);
    loss_partial_kernel<<<16, 256>>>();
    wprep_kernel<<<dim3(8, 8, NMAT), 256>>>(shareW, expW);

    cudaFuncSetAttribute(moe_mma_kernel,
                         cudaFuncAttributeMaxDynamicSharedMemorySize, SMEM_BYTES);
    moe_mma_kernel<<<dim3(4, 256), 256, SMEM_BYTES>>>(inputs, shareB, expB, out);

    finalize_kernel<<<1, 256>>>(out, out_size);
}

// round 5
// speedup vs baseline: 3.1484x; 1.0115x over previous
#include <cuda_runtime.h>
#include <cuda_bf16.h>
#include <math.h>
#include <stdint.h>

#define N_TOK 32768
#define C_DIM 256
#define E_NUM 16
#define NMAT 17
#define RBLK 512          // router blocks (64 tokens each)

// ---------------- scratch (no allocations allowed) ----------------
__device__ float g_combine[N_TOK * E_NUM];
__device__ float g_pt[RBLK * 16];     // per-router-block sel-count partials
__device__ float g_pp[RBLK * 16];     // per-router-block prob-sum partials
__device__ __align__(128) __nv_bfloat16 g_Wthi[NMAT * C_DIM * C_DIM];
__device__ __align__(128) __nv_bfloat16 g_Wtlo[NMAT * C_DIM * C_DIM];

__device__ __forceinline__ uint32_t smem_u32(const void* p) {
    uint32_t a;
    asm("{ .reg .u64 t; cvta.to.shared.u64 t, %1; cvt.u32.u64 %0, t; }" : "=r"(a) : "l"(p));
    return a;
}

// ---------------- kernel 1: fused router + W-prep ----------------
// blocks [0, RBLK): router (64 tokens each, with loss partials)
// blocks [RBLK, RBLK+1088): W transpose + bf16 hi/lo split
__global__ __launch_bounds__(256) void prep_kernel(
    const float* __restrict__ conv, const float* __restrict__ emb,
    const float* __restrict__ gateW, const float* __restrict__ gateB,
    const float* __restrict__ gamma, const float* __restrict__ beta,
    const float* __restrict__ shareW, const float* __restrict__ expW)
{
    int tid = threadIdx.x;

    if (blockIdx.x >= RBLK) {
        // ---- W prep ----
        __shared__ float tile[32][33];
        int w = blockIdx.x - RBLK;
        int m = w >> 6;
        int rr = w & 63;
        int by = rr >> 3, bx = rr & 7;
        const float* src = (m == 0) ? shareW : expW + (size_t)(m - 1) * 65536;
        int tx = tid & 31, ty = tid >> 5;
#pragma unroll
        for (int i = 0; i < 4; i++) {
            int k = by * 32 + ty + i * 8;
            int n = bx * 32 + tx;
            tile[ty + i * 8][tx] = src[k * 256 + n];
        }
        __syncthreads();
#pragma unroll
        for (int i = 0; i < 4; i++) {
            int n = bx * 32 + ty + i * 8;
            int k = by * 32 + tx;
            float v = tile[tx][ty + i * 8];
            __nv_bfloat16 h = __float2bfloat16(v);
            float lo = v - __bfloat162float(h);
            size_t o = (size_t)m * 65536 + (size_t)n * 256 + k;
            g_Wthi[o] = h;
            g_Wtlo[o] = __float2bfloat16(lo);
        }
        return;
    }

    // ---- router ----
    __shared__ float gwT[16 * 257];
    __shared__ float gbev[3 * 256 + 16];
    __shared__ float wpt[8 * 16], wpp[8 * 16];
    for (int idx = tid; idx < 4096; idx += 256)
        gwT[(idx & 15) * 257 + (idx >> 4)] = gateW[idx];
    if (tid < 256) {
        gbev[tid] = gamma[tid];
        gbev[256 + tid] = beta[tid];
        gbev[512 + tid] = emb[tid];
    }
    if (tid < 16) gbev[768 + tid] = gateB[tid];
    __syncthreads();

    int warp = tid >> 5, lane = tid & 31;
    float st[16], sp[16];
#pragma unroll
    for (int e = 0; e < 16; e++) { st[e] = 0.f; sp[e] = 0.f; }

#pragma unroll 1
    for (int i = 0; i < 8; i++) {
        int n = blockIdx.x * 64 + warp * 8 + i;
        const float* row = conv + (size_t)n * C_DIM;

        float x[8];
        float s = 0.f, s2 = 0.f;
#pragma unroll
        for (int j = 0; j < 8; j++) {
            x[j] = row[lane + 32 * j];
            s += x[j]; s2 += x[j] * x[j];
        }
#pragma unroll
        for (int o = 16; o; o >>= 1) {
            s  += __shfl_xor_sync(0xffffffffu, s,  o);
            s2 += __shfl_xor_sync(0xffffffffu, s2, o);
        }
        float mu = s * (1.f / 256.f);
        float var = s2 * (1.f / 256.f) - mu * mu;
        float rstd = rsqrtf(var + 1e-5f);

        float r[8];
#pragma unroll
        for (int j = 0; j < 8; j++) {
            int c = lane + 32 * j;
            r[j] = (x[j] - mu) * rstd * gbev[c] + gbev[256 + c] + gbev[512 + c];
        }

        float logit[16];
#pragma unroll
        for (int e = 0; e < 16; e++) {
            float p = 0.f;
#pragma unroll
            for (int j = 0; j < 8; j++) p += r[j] * gwT[e * 257 + lane + 32 * j];
#pragma unroll
            for (int o = 16; o; o >>= 1) p += __shfl_xor_sync(0xffffffffu, p, o);
            logit[e] = p + gbev[768 + e];
        }

        if (lane == 0) {
            float mx = logit[0];
#pragma unroll
            for (int e = 1; e < 16; e++) mx = fmaxf(mx, logit[e]);
            float w[16]; float sum = 0.f;
#pragma unroll
            for (int e = 0; e < 16; e++) { w[e] = expf(logit[e] - mx); sum += w[e]; }
            float inv = 1.f / sum; float ent = 0.f;
#pragma unroll
            for (int e = 0; e < 16; e++) { w[e] *= inv; ent -= w[e] * logf(w[e] + 1e-12f); }
            float kf = ceilf(1.f + ent * (15.f / 2.7725887222397811f));
            int k = (int)kf; k = k < 1 ? 1 : (k > 16 ? 16 : k);
#pragma unroll
            for (int e = 0; e < 16; e++) {
                int rank = 0;
#pragma unroll
                for (int j = 0; j < 16; j++)
                    rank += (w[j] > w[e]) || (w[j] == w[e] && j < e);
                int sel = rank < k;
                g_combine[n * 16 + e] = sel ? w[e] : 0.f;
                st[e] += sel ? 1.f : 0.f;
                sp[e] += w[e];
            }
        }
    }

    if (lane == 0) {
#pragma unroll
        for (int e = 0; e < 16; e++) { wpt[warp * 16 + e] = st[e]; wpp[warp * 16 + e] = sp[e]; }
    }
    __syncthreads();
    if (tid < 16) {
        float t = 0.f, p = 0.f;
#pragma unroll
        for (int w = 0; w < 8; w++) { t += wpt[w * 16 + tid]; p += wpp[w * 16 + tid]; }
        g_pt[blockIdx.x * 16 + tid] = t;
        g_pp[blockIdx.x * 16 + tid] = p;
    }
}

// ---------------- kernel 2: mma.sync fused MoE GEMM v3 ----------------
// CTA 64(M) x 64(N), 128 threads (4 warps 2x2, warp 32x32), 2 CTAs/SM.
#define XH_OFF 0            // 64 rows x 528B
#define XL_OFF 33792
#define WS_OFF 67584        // 2 stages x (hi 9216 + lo 9216), row stride 144
#define SC_OFF 104448       // [17][64] f32
#define BS_OFF 108800       // [17][64] f32
#define SMEM_BYTES 113152

#define LDSM4(R, A) \
    asm volatile("ldmatrix.sync.aligned.m8n8.x4.shared.b16 {%0,%1,%2,%3}, [%4];" \
        : "=r"((R)[0]), "=r"((R)[1]), "=r"((R)[2]), "=r"((R)[3]) : "r"(A))
#define MMA16816(D, A, B) \
    asm volatile("mma.sync.aligned.m16n8k16.row.col.f32.bf16.bf16.f32 " \
        "{%0,%1,%2,%3}, {%4,%5,%6,%7}, {%8,%9}, {%0,%1,%2,%3};" \
        : "+f"((D)[0]), "+f"((D)[1]), "+f"((D)[2]), "+f"((D)[3]) \
        : "r"((A)[0]), "r"((A)[1]), "r"((A)[2]), "r"((A)[3]), "r"((B)[0]), "r"((B)[1]))

__device__ __forceinline__ uint32_t packbf(float a, float b) {
    uint16_t la = __bfloat16_as_ushort(__float2bfloat16(a));
    uint16_t lb = __bfloat16_as_ushort(__float2bfloat16(b));
    return (uint32_t)la | ((uint32_t)lb << 16);
}

// prefetch W stage for task t (c = t/17, m = t%17) into buffer t&1
__device__ __forceinline__ void prefetch_w(uint32_t wbase, int t, int colBase, int tid)
{
    const int c = t / 17;
    const int m = t - c * 17;
    const int buf = t & 1;
#pragma unroll
    for (int i = 0; i < 8; i++) {
        int idx = tid + i * 128;           // 0..1023
        int half = idx >> 9;               // 0: hi, 1: lo
        int r = (idx >> 3) & 63;           // n row within slice
        int q = idx & 7;                   // 16B segment along k
        const __nv_bfloat16* src = (half ? g_Wtlo : g_Wthi) +
            (size_t)m * 65536 + (size_t)(colBase + r) * 256 + c * 64 + q * 8;
        uint32_t dst = wbase + buf * 18432 + half * 9216 + r * 144 + q * 16;
        asm volatile("cp.async.cg.shared.global [%0], [%1], 16;"
                     :: "r"(dst), "l"(src) : "memory");
    }
    asm volatile("cp.async.commit_group;" ::: "memory");
}

__global__ __launch_bounds__(128, 2) void moe_mma_kernel(
    const float* __restrict__ X,
    const float* __restrict__ shareB,
    const float* __restrict__ expB,
    float* __restrict__ out)
{
    extern __shared__ char smc[];
    const int tid = threadIdx.x;
    const int lane = tid & 31, warp = tid >> 5;
    const int rowBase = blockIdx.y * 64;
    const int colBase = blockIdx.x * 64;
    const uint32_t sb = smem_u32(smc);
    const uint32_t wbase = sb + WS_OFF;

    prefetch_w(wbase, 0, colBase, tid);   // stage 0 in flight

    float* Sc = reinterpret_cast<float*>(smc + SC_OFF);
    float* Bs = reinterpret_cast<float*>(smc + BS_OFF);

    for (int idx = tid; idx < 17 * 64; idx += 128) {
        int m = idx >> 6, r = idx & 63;
        Sc[idx] = (m == 0) ? 1.0f : g_combine[(size_t)(rowBase + r) * 16 + (m - 1)];
    }
    for (int idx = tid; idx < 17 * 64; idx += 128) {
        int m = idx >> 6, c = idx & 63;
        Bs[idx] = (m == 0) ? shareB[colBase + c] : expB[(m - 1) * 256 + colBase + c];
    }

    // stage X hi/lo (64 rows x 256 k, padded stride 528B)
    const float* Xb = X + (size_t)rowBase * 256;
#pragma unroll 4
    for (int it = 0; it < 32; it++) {
        int idx = tid + it * 128;
        int r = idx >> 6, k4 = idx & 63;
        float4 v = reinterpret_cast<const float4*>(Xb + (size_t)r * 256)[k4];
        float hx = __bfloat162float(__float2bfloat16(v.x));
        float hy = __bfloat162float(__float2bfloat16(v.y));
        float hz = __bfloat162float(__float2bfloat16(v.z));
        float hw = __bfloat162float(__float2bfloat16(v.w));
        uint2 hi = make_uint2(packbf(v.x, v.y), packbf(v.z, v.w));
        uint2 lo = make_uint2(packbf(v.x - hx, v.y - hy), packbf(v.z - hz, v.w - hw));
        *reinterpret_cast<uint2*>(smc + XH_OFF + r * 528 + k4 * 8) = hi;
        *reinterpret_cast<uint2*>(smc + XL_OFF + r * 528 + k4 * 8) = lo;
    }

    // warp tiling: m0 in {0,32}, n0 in {0,32}
    const int m0 = (warp & 1) * 32;
    const int n0 = (warp >> 1) * 32;

    const uint32_t xh_base = sb + XH_OFF + (uint32_t)(m0 + (lane & 15)) * 528 + (lane >> 4) * 16;
    const uint32_t xl_base = xh_base + (uint32_t)(XL_OFF - XH_OFF);
    // B ldmatrix x4: two 8-row n-tiles per instr
    const uint32_t wb_base = wbase +
        (uint32_t)(n0 + ((lane >> 4) & 1) * 8 + (lane & 7)) * 144 + ((lane >> 3) & 1) * 16;

    const int rq = lane >> 2;
    const int cq = (lane & 3) * 2;

    // acc init = sum_m s_m * b_m
    float acc[2][4][4];
#pragma unroll
    for (int mt = 0; mt < 2; mt++)
#pragma unroll
        for (int nt = 0; nt < 4; nt++)
#pragma unroll
            for (int q = 0; q < 4; q++) acc[mt][nt][q] = 0.f;

    __syncthreads();   // X / Sc / Bs visible

#pragma unroll 1
    for (int m = 0; m < NMAT; m++) {
        float s0 = Sc[m * 64 + m0 + rq];
        float s1 = Sc[m * 64 + m0 + rq + 8];
        float s2 = Sc[m * 64 + m0 + rq + 16];
        float s3 = Sc[m * 64 + m0 + rq + 24];
#pragma unroll
        for (int nt = 0; nt < 4; nt++) {
            float b0 = Bs[m * 64 + n0 + nt * 8 + cq];
            float b1 = Bs[m * 64 + n0 + nt * 8 + cq + 1];
            acc[0][nt][0] += s0 * b0; acc[0][nt][1] += s0 * b1;
            acc[0][nt][2] += s1 * b0; acc[0][nt][3] += s1 * b1;
            acc[1][nt][0] += s2 * b0; acc[1][nt][1] += s2 * b1;
            acc[1][nt][2] += s3 * b0; acc[1][nt][3] += s3 * b1;
        }
    }

    uint32_t Ah[4][2][4], Al[4][2][4];
    float p[2][4][4];

#pragma unroll 1
    for (int t = 0; t < NMAT * 4; t++) {
        const int c = t / 17;
        const int m = t - c * 17;
        const int buf = t & 1;

        asm volatile("cp.async.wait_group 0;" ::: "memory");
        __syncthreads();   // stage t visible to all; compute t-1 drained by all

        if (t + 1 < NMAT * 4) prefetch_w(wbase, t + 1, colBase, tid);

        if (m == 0) {
#pragma unroll
            for (int ks = 0; ks < 4; ks++) {
                const uint32_t kOff = (uint32_t)(c * 64 + ks * 16) * 2;
#pragma unroll
                for (int mt = 0; mt < 2; mt++) {
                    LDSM4(Ah[ks][mt], xh_base + mt * (16 * 528) + kOff);
                    LDSM4(Al[ks][mt], xl_base + mt * (16 * 528) + kOff);
                }
            }
        }

#pragma unroll
        for (int mt = 0; mt < 2; mt++)
#pragma unroll
            for (int nt = 0; nt < 4; nt++)
#pragma unroll
                for (int q = 0; q < 4; q++) p[mt][nt][q] = 0.f;

        const uint32_t wbs = wb_base + buf * 18432;
#pragma unroll
        for (int ks = 0; ks < 4; ks++) {
            uint32_t Bh[4][2], Bl[4][2];   // [nt][2]
#pragma unroll
            for (int ntp = 0; ntp < 2; ntp++) {
                uint32_t r4[4];
                LDSM4(r4, wbs + ntp * (16 * 144) + ks * 32);
                Bh[ntp * 2][0] = r4[0]; Bh[ntp * 2][1] = r4[1];
                Bh[ntp * 2 + 1][0] = r4[2]; Bh[ntp * 2 + 1][1] = r4[3];
                LDSM4(r4, wbs + 9216 + ntp * (16 * 144) + ks * 32);
                Bl[ntp * 2][0] = r4[0]; Bl[ntp * 2][1] = r4[1];
                Bl[ntp * 2 + 1][0] = r4[2]; Bl[ntp * 2 + 1][1] = r4[3];
            }
#pragma unroll
            for (int mt = 0; mt < 2; mt++)
#pragma unroll
                for (int nt = 0; nt < 4; nt++)
                    MMA16816(p[mt][nt], Ah[ks][mt], Bh[nt]);
#pragma unroll
            for (int mt = 0; mt < 2; mt++)
#pragma unroll
                for (int nt = 0; nt < 4; nt++)
                    MMA16816(p[mt][nt], Ah[ks][mt], Bl[nt]);
#pragma unroll
            for (int mt = 0; mt < 2; mt++)
#pragma unroll
                for (int nt = 0; nt < 4; nt++)
                    MMA16816(p[mt][nt], Al[ks][mt], Bh[nt]);
        }

        // epilogue: acc += s_row * p
        {
            float s0 = Sc[m * 64 + m0 + rq];
            float s1 = Sc[m * 64 + m0 + rq + 8];
            float s2 = Sc[m * 64 + m0 + rq + 16];
            float s3 = Sc[m * 64 + m0 + rq + 24];
#pragma unroll
            for (int nt = 0; nt < 4; nt++) {
                acc[0][nt][0] += s0 * p[0][nt][0];
                acc[0][nt][1] += s0 * p[0][nt][1];
                acc[0][nt][2] += s1 * p[0][nt][2];
                acc[0][nt][3] += s1 * p[0][nt][3];
                acc[1][nt][0] += s2 * p[1][nt][0];
                acc[1][nt][1] += s2 * p[1][nt][1];
                acc[1][nt][2] += s3 * p[1][nt][2];
                acc[1][nt][3] += s3 * p[1][nt][3];
            }
        }
    }

    // write output
#pragma unroll
    for (int mt = 0; mt < 2; mt++) {
        int rg = rowBase + m0 + mt * 16 + rq;
#pragma unroll
        for (int nt = 0; nt < 4; nt++) {
            int cg = colBase + n0 + nt * 8 + cq;
            *reinterpret_cast<float2*>(out + (size_t)rg * 256 + cg) =
                make_float2(acc[mt][nt][0], acc[mt][nt][1]);
            *reinterpret_cast<float2*>(out + (size_t)(rg + 8) * 256 + cg) =
                make_float2(acc[mt][nt][2], acc[mt][nt][3]);
        }
    }
}

// ---------------- kernel 3: loss reduce + finalize ----------------
__global__ __launch_bounds__(256) void finalize_kernel(float* __restrict__ out, int out_size)
{
    __shared__ float rt[16][17], rp[16][17];
    __shared__ float prod[16];
    int tid = threadIdx.x;
    int e = tid & 15, part = tid >> 4;   // 16 parts x 32 blocks
    float t = 0.f, p = 0.f;
    for (int b = part * 32; b < part * 32 + 32; b++) {
        t += g_pt[b * 16 + e];
        p += g_pp[b * 16 + e];
    }
    rt[part][e] = t; rp[part][e] = p;
    __syncthreads();
    if (tid < 16) {
        float ts = 0.f, ps = 0.f;
#pragma unroll
        for (int q = 0; q < 16; q++) { ts += rt[q][tid]; ps += rp[q][tid]; }
        prod[tid] = (ts * (1.f / (float)N_TOK)) * (ps * (1.f / (float)N_TOK));
    }
    __syncthreads();
    const int NC = N_TOK * C_DIM;
    if (tid == 0) {
        float a = 0.f;
#pragma unroll
        for (int q = 0; q < 16; q++) a += prod[q];
        if (out_size > NC) out[NC] = a * 16.f;
    }
    for (int i = NC + 1 + tid; i < out_size; i += 256)
        out[i] = 0.f;
}

// ---------------- launch ----------------
extern "C" void kernel_launch(void* const* d_in, const int* in_sizes, int n_in,
                              void* d_out, int out_size)
{
    const float* inputs = (const float*)d_in[0];
    const float* conv   = (const float*)d_in[1];
    const float* emb    = (const float*)d_in[2];
    const float* shareW = (const float*)d_in[3];
    const float* shareB = (const float*)d_in[4];
    const float* gateW  = (const float*)d_in[5];
    const float* gateB  = (const float*)d_in[6];
    const float* expW   = (const float*)d_in[7];
    const float* expB   = (const float*)d_in[8];
    const float* gamma  = (const float*)d_in[9];
    const float* beta   = (const float*)d_in[10];
    float* out = (float*)d_out;

    prep_kernel<<<RBLK + NMAT * 64, 256>>>(conv, emb, gateW, gateB, gamma, beta,
                                           shareW, expW);

    cudaFuncSetAttribute(moe_mma_kernel,
                         cudaFuncAttributeMaxDynamicSharedMemorySize, SMEM_BYTES);
    moe_mma_kernel<<<dim3(4, 512), 128, SMEM_BYTES>>>(inputs, shareB, expB, out);

    finalize_kernel<<<1, 256>>>(out, out_size);
}

// round 6
// speedup vs baseline: 3.3962x; 1.0787x over previous
#include <cuda_runtime.h>
#include <cuda_bf16.h>
#include <math.h>
#include <stdint.h>

#define N_TOK 32768
#define C_DIM 256
#define E_NUM 16
#define NMAT 17
#define RBLK 256          // router blocks (128 tokens each)

// ---------------- scratch (no allocations allowed) ----------------
__device__ float g_combine[N_TOK * E_NUM];
__device__ float g_pt[RBLK * 16];
__device__ float g_pp[RBLK * 16];
__device__ __align__(128) __nv_bfloat16 g_Wthi[NMAT * C_DIM * C_DIM];
__device__ __align__(128) __nv_bfloat16 g_Wtlo[NMAT * C_DIM * C_DIM];

__device__ __forceinline__ uint32_t smem_u32(const void* p) {
    uint32_t a;
    asm("{ .reg .u64 t; cvta.to.shared.u64 t, %1; cvt.u32.u64 %0, t; }" : "=r"(a) : "l"(p));
    return a;
}

// ---------------- kernel 1: fused router + W-prep ----------------
// blocks [0, RBLK): router (128 tokens each, warp-parallel epilogue)
// blocks [RBLK, RBLK+1088): W transpose + bf16 hi/lo split
__global__ __launch_bounds__(256) void prep_kernel(
    const float* __restrict__ conv, const float* __restrict__ emb,
    const float* __restrict__ gateW, const float* __restrict__ gateB,
    const float* __restrict__ gamma, const float* __restrict__ beta,
    const float* __restrict__ shareW, const float* __restrict__ expW)
{
    int tid = threadIdx.x;

    if (blockIdx.x >= RBLK) {
        // ---- W prep ----
        __shared__ float tile[32][33];
        int w = blockIdx.x - RBLK;
        int m = w >> 6;
        int rr = w & 63;
        int by = rr >> 3, bx = rr & 7;
        const float* src = (m == 0) ? shareW : expW + (size_t)(m - 1) * 65536;
        int tx = tid & 31, ty = tid >> 5;
        if (ty < 8) {
#pragma unroll
            for (int i = 0; i < 4; i++) {
                int k = by * 32 + ty + i * 8;
                int n = bx * 32 + tx;
                tile[ty + i * 8][tx] = src[k * 256 + n];
            }
        }
        __syncthreads();
        if (ty < 8) {
#pragma unroll
            for (int i = 0; i < 4; i++) {
                int n = bx * 32 + ty + i * 8;
                int k = by * 32 + tx;
                float v = tile[tx][ty + i * 8];
                __nv_bfloat16 h = __float2bfloat16(v);
                float lo = v - __bfloat162float(h);
                size_t o = (size_t)m * 65536 + (size_t)n * 256 + k;
                g_Wthi[o] = h;
                g_Wtlo[o] = __float2bfloat16(lo);
            }
        }
        return;
    }

    // ---- router: 8 warps x 16 tokens ----
    __shared__ float gwT[16 * 257];
    __shared__ float gbev[3 * 256 + 16];
    __shared__ float wpt[8 * 16], wpp[8 * 16];
    for (int idx = tid; idx < 4096; idx += 256)
        gwT[(idx & 15) * 257 + (idx >> 4)] = gateW[idx];
    if (tid < 256) {
        gbev[tid] = gamma[tid];
        gbev[256 + tid] = beta[tid];
        gbev[512 + tid] = emb[tid];
    }
    if (tid < 16) gbev[768 + tid] = gateB[tid];
    __syncthreads();

    int warp = tid >> 5, lane = tid & 31;
    float st = 0.f, sp = 0.f;     // per-lane (lane<16 owns expert=lane)

#pragma unroll 1
    for (int i = 0; i < 16; i++) {
        int n = blockIdx.x * 128 + warp * 16 + i;
        const float* row = conv + (size_t)n * C_DIM;

        float x[8];
        float s = 0.f, s2 = 0.f;
#pragma unroll
        for (int j = 0; j < 8; j++) {
            x[j] = row[lane + 32 * j];
            s += x[j]; s2 += x[j] * x[j];
        }
#pragma unroll
        for (int o = 16; o; o >>= 1) {
            s  += __shfl_xor_sync(0xffffffffu, s,  o);
            s2 += __shfl_xor_sync(0xffffffffu, s2, o);
        }
        float mu = s * (1.f / 256.f);
        float var = s2 * (1.f / 256.f) - mu * mu;
        float rstd = rsqrtf(var + 1e-5f);

        float r[8];
#pragma unroll
        for (int j = 0; j < 8; j++) {
            int c = lane + 32 * j;
            r[j] = (x[j] - mu) * rstd * gbev[c] + gbev[256 + c] + gbev[512 + c];
        }

        float w[16];
#pragma unroll
        for (int e = 0; e < 16; e++) {
            float p = 0.f;
#pragma unroll
            for (int j = 0; j < 8; j++) p += r[j] * gwT[e * 257 + lane + 32 * j];
#pragma unroll
            for (int o = 16; o; o >>= 1) p += __shfl_xor_sync(0xffffffffu, p, o);
            w[e] = p + gbev[768 + e];   // logit, all lanes hold all 16
        }

        // softmax / entropy / k computed redundantly on all lanes
        float mx = w[0];
#pragma unroll
        for (int e = 1; e < 16; e++) mx = fmaxf(mx, w[e]);
        float sum = 0.f;
#pragma unroll
        for (int e = 0; e < 16; e++) { w[e] = expf(w[e] - mx); sum += w[e]; }
        float inv = 1.f / sum;
        float ent = 0.f;
#pragma unroll
        for (int e = 0; e < 16; e++) { w[e] *= inv; ent -= w[e] * logf(w[e] + 1e-12f); }
        float kf = ceilf(1.f + ent * (15.f / 2.7725887222397811f));
        int k = (int)kf; k = k < 1 ? 1 : (k > 16 ? 16 : k);

        // lane-parallel rank: lane e handles expert e
        if (lane < 16) {
            float we = w[lane];
            int rank = 0;
#pragma unroll
            for (int j = 0; j < 16; j++)
                rank += (w[j] > we) || (w[j] == we && j < lane);
            int sel = rank < k;
            g_combine[n * 16 + lane] = sel ? we : 0.f;
            st += sel ? 1.f : 0.f;
            sp += we;
        }
    }

    if (lane < 16) { wpt[warp * 16 + lane] = st; wpp[warp * 16 + lane] = sp; }
    __syncthreads();
    if (tid < 16) {
        float t = 0.f, p = 0.f;
#pragma unroll
        for (int w = 0; w < 8; w++) { t += wpt[w * 16 + tid]; p += wpp[w * 16 + tid]; }
        g_pt[blockIdx.x * 16 + tid] = t;
        g_pp[blockIdx.x * 16 + tid] = p;
    }
}

// ---------------- kernel 2: mma.sync fused MoE GEMM v4 ----------------
// CTA 64(M) x 64(N), 128 threads (4 warps 2x2, warp 32x32), 3 CTAs/SM.
// X resident only one 64-k chunk at a time (refilled overlapped at m==1).
#define WS_OFF 0            // 2 stages x (hi 9216 + lo 9216), row stride 144
#define XC_OFF 36864        // current X chunk: hi 9216 + lo 9216
#define SC_OFF 55296        // [17][64] f32
#define BS_OFF 59648        // [17][64] f32
#define SMEM_BYTES 64000

#define LDSM4(R, A) \
    asm volatile("ldmatrix.sync.aligned.m8n8.x4.shared.b16 {%0,%1,%2,%3}, [%4];" \
        : "=r"((R)[0]), "=r"((R)[1]), "=r"((R)[2]), "=r"((R)[3]) : "r"(A))
#define MMA16816(D, A, B) \
    asm volatile("mma.sync.aligned.m16n8k16.row.col.f32.bf16.bf16.f32 " \
        "{%0,%1,%2,%3}, {%4,%5,%6,%7}, {%8,%9}, {%0,%1,%2,%3};" \
        : "+f"((D)[0]), "+f"((D)[1]), "+f"((D)[2]), "+f"((D)[3]) \
        : "r"((A)[0]), "r"((A)[1]), "r"((A)[2]), "r"((A)[3]), "r"((B)[0]), "r"((B)[1]))

__device__ __forceinline__ uint32_t packbf(float a, float b) {
    uint16_t la = __bfloat16_as_ushort(__float2bfloat16(a));
    uint16_t lb = __bfloat16_as_ushort(__float2bfloat16(b));
    return (uint32_t)la | ((uint32_t)lb << 16);
}

// prefetch W stage for task t (c = t/17, m = t%17) into buffer t&1
__device__ __forceinline__ void prefetch_w(uint32_t wbase, int t, int colBase, int tid)
{
    const int c = t / 17;
    const int m = t - c * 17;
    const int buf = t & 1;
#pragma unroll
    for (int i = 0; i < 8; i++) {
        int idx = tid + i * 128;           // 0..1023
        int half = idx >> 9;
        int r = (idx >> 3) & 63;
        int q = idx & 7;
        const __nv_bfloat16* src = (half ? g_Wtlo : g_Wthi) +
            (size_t)m * 65536 + (size_t)(colBase + r) * 256 + c * 64 + q * 8;
        uint32_t dst = wbase + buf * 18432 + half * 9216 + r * 144 + q * 16;
        asm volatile("cp.async.cg.shared.global [%0], [%1], 16;"
                     :: "r"(dst), "l"(src) : "memory");
    }
    asm volatile("cp.async.commit_group;" ::: "memory");
}

// convert X chunk (64 rows x 64 k) from gmem into XC buffer
__device__ __forceinline__ void convert_x(char* smc, const float* Xb, int chunk, int tid)
{
#pragma unroll
    for (int i = 0; i < 8; i++) {
        int idx = tid + i * 128;           // 0..1023 float4 slots
        int r = idx >> 4;                  // row 0..63
        int k4 = idx & 15;                 // float4 within chunk
        float4 v = reinterpret_cast<const float4*>(Xb + (size_t)r * 256 + chunk * 64)[k4];
        float hx = __bfloat162float(__float2bfloat16(v.x));
        float hy = __bfloat162float(__float2bfloat16(v.y));
        float hz = __bfloat162float(__float2bfloat16(v.z));
        float hw = __bfloat162float(__float2bfloat16(v.w));
        uint2 hi = make_uint2(packbf(v.x, v.y), packbf(v.z, v.w));
        uint2 lo = make_uint2(packbf(v.x - hx, v.y - hy), packbf(v.z - hz, v.w - hw));
        *reinterpret_cast<uint2*>(smc + XC_OFF + r * 144 + k4 * 8) = hi;
        *reinterpret_cast<uint2*>(smc + XC_OFF + 9216 + r * 144 + k4 * 8) = lo;
    }
}

__global__ __launch_bounds__(128, 3) void moe_mma_kernel(
    const float* __restrict__ X,
    const float* __restrict__ shareB,
    const float* __restrict__ expB,
    float* __restrict__ out)
{
    extern __shared__ char smc[];
    const int tid = threadIdx.x;
    const int lane = tid & 31, warp = tid >> 5;
    const int rowBase = blockIdx.y * 64;
    const int colBase = blockIdx.x * 64;
    const uint32_t sb = smem_u32(smc);
    const uint32_t wbase = sb + WS_OFF;

    prefetch_w(wbase, 0, colBase, tid);   // stage 0 in flight

    float* Sc = reinterpret_cast<float*>(smc + SC_OFF);
    float* Bs = reinterpret_cast<float*>(smc + BS_OFF);

    for (int idx = tid; idx < 17 * 64; idx += 128) {
        int m = idx >> 6, r = idx & 63;
        Sc[idx] = (m == 0) ? 1.0f : g_combine[(size_t)(rowBase + r) * 16 + (m - 1)];
    }
    for (int idx = tid; idx < 17 * 64; idx += 128) {
        int m = idx >> 6, c = idx & 63;
        Bs[idx] = (m == 0) ? shareB[colBase + c] : expB[(m - 1) * 256 + colBase + c];
    }

    const float* Xb = X + (size_t)rowBase * 256;
    convert_x(smc, Xb, 0, tid);           // chunk 0 staged

    // warp tiling: m0 in {0,32}, n0 in {0,32}
    const int m0 = (warp & 1) * 32;
    const int n0 = (warp >> 1) * 32;

    const uint32_t xh_base = sb + XC_OFF + (uint32_t)(m0 + (lane & 15)) * 144 + (lane >> 4) * 16;
    const uint32_t xl_base = xh_base + 9216u;
    const uint32_t wb_base = wbase +
        (uint32_t)(n0 + ((lane >> 4) & 1) * 8 + (lane & 7)) * 144 + ((lane >> 3) & 1) * 16;

    const int rq = lane >> 2;
    const int cq = (lane & 3) * 2;

    float acc[2][4][4];
#pragma unroll
    for (int mt = 0; mt < 2; mt++)
#pragma unroll
        for (int nt = 0; nt < 4; nt++)
#pragma unroll
            for (int q = 0; q < 4; q++) acc[mt][nt][q] = 0.f;

    __syncthreads();   // X chunk 0 / Sc / Bs visible

    // acc init = sum_m s_m * b_m
#pragma unroll 1
    for (int m = 0; m < NMAT; m++) {
        float s0 = Sc[m * 64 + m0 + rq];
        float s1 = Sc[m * 64 + m0 + rq + 8];
        float s2 = Sc[m * 64 + m0 + rq + 16];
        float s3 = Sc[m * 64 + m0 + rq + 24];
#pragma unroll
        for (int nt = 0; nt < 4; nt++) {
            float b0 = Bs[m * 64 + n0 + nt * 8 + cq];
            float b1 = Bs[m * 64 + n0 + nt * 8 + cq + 1];
            acc[0][nt][0] += s0 * b0; acc[0][nt][1] += s0 * b1;
            acc[0][nt][2] += s1 * b0; acc[0][nt][3] += s1 * b1;
            acc[1][nt][0] += s2 * b0; acc[1][nt][1] += s2 * b1;
            acc[1][nt][2] += s3 * b0; acc[1][nt][3] += s3 * b1;
        }
    }

    uint32_t Ah[4][2][4], Al[4][2][4];
    float p[2][4][4];

#pragma unroll 1
    for (int t = 0; t < NMAT * 4; t++) {
        const int c = t / 17;
        const int m = t - c * 17;
        const int buf = t & 1;

        asm volatile("cp.async.wait_group 0;" ::: "memory");
        __syncthreads();   // W stage t visible; all warps past previous iteration

        if (t + 1 < NMAT * 4) prefetch_w(wbase, t + 1, colBase, tid);

        if (m == 0) {
            // A fragments for chunk c — X buffer not read again until next chunk
#pragma unroll
            for (int ks = 0; ks < 4; ks++) {
#pragma unroll
                for (int mt = 0; mt < 2; mt++) {
                    LDSM4(Ah[ks][mt], xh_base + mt * (16 * 144) + ks * 32);
                    LDSM4(Al[ks][mt], xl_base + mt * (16 * 144) + ks * 32);
                }
            }
        }
        if (m == 1 && c < 3) {
            // refill X buffer with chunk c+1 (m==0 LDSMs done thanks to the
            // iteration barrier above); next read is 16 barriers away
            convert_x(smc, Xb, c + 1, tid);
        }

#pragma unroll
        for (int mt = 0; mt < 2; mt++)
#pragma unroll
            for (int nt = 0; nt < 4; nt++)
#pragma unroll
                for (int q = 0; q < 4; q++) p[mt][nt][q] = 0.f;

        const uint32_t wbs = wb_base + buf * 18432;
#pragma unroll
        for (int ks = 0; ks < 4; ks++) {
            uint32_t Bh[4][2], Bl[4][2];
#pragma unroll
            for (int ntp = 0; ntp < 2; ntp++) {
                uint32_t r4[4];
                LDSM4(r4, wbs + ntp * (16 * 144) + ks * 32);
                Bh[ntp * 2][0] = r4[0]; Bh[ntp * 2][1] = r4[1];
                Bh[ntp * 2 + 1][0] = r4[2]; Bh[ntp * 2 + 1][1] = r4[3];
                LDSM4(r4, wbs + 9216 + ntp * (16 * 144) + ks * 32);
                Bl[ntp * 2][0] = r4[0]; Bl[ntp * 2][1] = r4[1];
                Bl[ntp * 2 + 1][0] = r4[2]; Bl[ntp * 2 + 1][1] = r4[3];
            }
#pragma unroll
            for (int mt = 0; mt < 2; mt++)
#pragma unroll
                for (int nt = 0; nt < 4; nt++)
                    MMA16816(p[mt][nt], Ah[ks][mt], Bh[nt]);
#pragma unroll
            for (int mt = 0; mt < 2; mt++)
#pragma unroll
                for (int nt = 0; nt < 4; nt++)
                    MMA16816(p[mt][nt], Ah[ks][mt], Bl[nt]);
#pragma unroll
            for (int mt = 0; mt < 2; mt++)
#pragma unroll
                for (int nt = 0; nt < 4; nt++)
                    MMA16816(p[mt][nt], Al[ks][mt], Bh[nt]);
        }

        // epilogue: acc += s_row * p
        {
            float s0 = Sc[m * 64 + m0 + rq];
            float s1 = Sc[m * 64 + m0 + rq + 8];
            float s2 = Sc[m * 64 + m0 + rq + 16];
            float s3 = Sc[m * 64 + m0 + rq + 24];
#pragma unroll
            for (int nt = 0; nt < 4; nt++) {
                acc[0][nt][0] += s0 * p[0][nt][0];
                acc[0][nt][1] += s0 * p[0][nt][1];
                acc[0][nt][2] += s1 * p[0][nt][2];
                acc[0][nt][3] += s1 * p[0][nt][3];
                acc[1][nt][0] += s2 * p[1][nt][0];
                acc[1][nt][1] += s2 * p[1][nt][1];
                acc[1][nt][2] += s3 * p[1][nt][2];
                acc[1][nt][3] += s3 * p[1][nt][3];
            }
        }
    }

    // write output
#pragma unroll
    for (int mt = 0; mt < 2; mt++) {
        int rg = rowBase + m0 + mt * 16 + rq;
#pragma unroll
        for (int nt = 0; nt < 4; nt++) {
            int cg = colBase + n0 + nt * 8 + cq;
            *reinterpret_cast<float2*>(out + (size_t)rg * 256 + cg) =
                make_float2(acc[mt][nt][0], acc[mt][nt][1]);
            *reinterpret_cast<float2*>(out + (size_t)(rg + 8) * 256 + cg) =
                make_float2(acc[mt][nt][2], acc[mt][nt][3]);
        }
    }
}

// ---------------- kernel 3: loss reduce + finalize ----------------
__global__ __launch_bounds__(256) void finalize_kernel(float* __restrict__ out, int out_size)
{
    __shared__ float rt[16][17], rp[16][17];
    __shared__ float prod[16];
    int tid = threadIdx.x;
    int e = tid & 15, part = tid >> 4;   // 16 parts x 16 blocks
    float t = 0.f, p = 0.f;
    for (int b = part * 16; b < part * 16 + 16; b++) {
        t += g_pt[b * 16 + e];
        p += g_pp[b * 16 + e];
    }
    rt[part][e] = t; rp[part][e] = p;
    __syncthreads();
    if (tid < 16) {
        float ts = 0.f, ps = 0.f;
#pragma unroll
        for (int q = 0; q < 16; q++) { ts += rt[q][tid]; ps += rp[q][tid]; }
        prod[tid] = (ts * (1.f / (float)N_TOK)) * (ps * (1.f / (float)N_TOK));
    }
    __syncthreads();
    const int NC = N_TOK * C_DIM;
    if (tid == 0) {
        float a = 0.f;
#pragma unroll
        for (int q = 0; q < 16; q++) a += prod[q];
        if (out_size > NC) out[NC] = a * 16.f;
    }
    for (int i = NC + 1 + tid; i < out_size; i += 256)
        out[i] = 0.f;
}

// ---------------- launch ----------------
extern "C" void kernel_launch(void* const* d_in, const int* in_sizes, int n_in,
                              void* d_out, int out_size)
{
    const float* inputs = (const float*)d_in[0];
    const float* conv   = (const float*)d_in[1];
    const float* emb    = (const float*)d_in[2];
    const float* shareW = (const float*)d_in[3];
    const float* shareB = (const float*)d_in[4];
    const float* gateW  = (const float*)d_in[5];
    const float* gateB  = (const float*)d_in[6];
    const float* expW   = (const float*)d_in[7];
    const float* expB   = (const float*)d_in[8];
    const float* gamma  = (const float*)d_in[9];
    const float* beta   = (const float*)d_in[10];
    float* out = (float*)d_out;

    prep_kernel<<<RBLK + NMAT * 64, 256>>>(conv, emb, gateW, gateB, gamma, beta,
                                           shareW, expW);

    cudaFuncSetAttribute(moe_mma_kernel,
                         cudaFuncAttributeMaxDynamicSharedMemorySize, SMEM_BYTES);
    moe_mma_kernel<<<dim3(4, 512), 128, SMEM_BYTES>>>(inputs, shareB, expB, out);

    finalize_kernel<<<1, 256>>>(out, out_size);
}

// round 7
// speedup vs baseline: 4.3824x; 1.2904x over previous
#include <cuda_runtime.h>
#include <cuda_fp16.h>
#include <math.h>
#include <stdint.h>

#define N_TOK 32768
#define C_DIM 256
#define E_NUM 16
#define NMAT 17
#define RBLK 256          // router blocks (128 tokens each)

// ---------------- scratch (no allocations allowed) ----------------
__device__ float g_combine[N_TOK * E_NUM];
__device__ float g_pt[RBLK * 16];
__device__ float g_pp[RBLK * 16];
// W transposed to [mat][n][k] (K contiguous), split into fp16 hi/lo
__device__ __align__(128) __half g_Whi[NMAT * C_DIM * C_DIM];
__device__ __align__(128) __half g_Wlo[NMAT * C_DIM * C_DIM];

__device__ __forceinline__ uint32_t smem_u32(const void* p) {
    uint32_t a;
    asm("{ .reg .u64 t; cvta.to.shared.u64 t, %1; cvt.u32.u64 %0, t; }" : "=r"(a) : "l"(p));
    return a;
}

// ---------------- kernel 1: fused router + W-prep ----------------
__global__ __launch_bounds__(256) void prep_kernel(
    const float* __restrict__ conv, const float* __restrict__ emb,
    const float* __restrict__ gateW, const float* __restrict__ gateB,
    const float* __restrict__ gamma, const float* __restrict__ beta,
    const float* __restrict__ shareW, const float* __restrict__ expW)
{
    int tid = threadIdx.x;

    if (blockIdx.x >= RBLK) {
        // ---- W prep: transpose + fp16 hi/lo split ----
        __shared__ float tile[32][33];
        int w = blockIdx.x - RBLK;
        int m = w >> 6;
        int rr = w & 63;
        int by = rr >> 3, bx = rr & 7;
        const float* src = (m == 0) ? shareW : expW + (size_t)(m - 1) * 65536;
        int tx = tid & 31, ty = tid >> 5;
        if (ty < 8) {
#pragma unroll
            for (int i = 0; i < 4; i++) {
                int k = by * 32 + ty + i * 8;
                int n = bx * 32 + tx;
                tile[ty + i * 8][tx] = src[k * 256 + n];
            }
        }
        __syncthreads();
        if (ty < 8) {
#pragma unroll
            for (int i = 0; i < 4; i++) {
                int n = bx * 32 + ty + i * 8;
                int k = by * 32 + tx;
                float v = tile[tx][ty + i * 8];
                __half h = __float2half_rn(v);
                float lo = v - __half2float(h);
                size_t o = (size_t)m * 65536 + (size_t)n * 256 + k;
                g_Whi[o] = h;
                g_Wlo[o] = __float2half_rn(lo);
            }
        }
        return;
    }

    // ---- router: 8 warps x 16 tokens, warp-parallel epilogue ----
    __shared__ float gwT[16 * 257];
    __shared__ float gbev[3 * 256 + 16];
    __shared__ float wpt[8 * 16], wpp[8 * 16];
    for (int idx = tid; idx < 4096; idx += 256)
        gwT[(idx & 15) * 257 + (idx >> 4)] = gateW[idx];
    if (tid < 256) {
        gbev[tid] = gamma[tid];
        gbev[256 + tid] = beta[tid];
        gbev[512 + tid] = emb[tid];
    }
    if (tid < 16) gbev[768 + tid] = gateB[tid];
    __syncthreads();

    int warp = tid >> 5, lane = tid & 31;
    float st = 0.f, sp = 0.f;

#pragma unroll 2
    for (int i = 0; i < 16; i++) {
        int n = blockIdx.x * 128 + warp * 16 + i;
        const float* row = conv + (size_t)n * C_DIM;

        float x[8];
        float s = 0.f, s2 = 0.f;
#pragma unroll
        for (int j = 0; j < 8; j++) {
            x[j] = row[lane + 32 * j];
            s += x[j]; s2 += x[j] * x[j];
        }
#pragma unroll
        for (int o = 16; o; o >>= 1) {
            s  += __shfl_xor_sync(0xffffffffu, s,  o);
            s2 += __shfl_xor_sync(0xffffffffu, s2, o);
        }
        float mu = s * (1.f / 256.f);
        float var = s2 * (1.f / 256.f) - mu * mu;
        float rstd = rsqrtf(var + 1e-5f);

        float r[8];
#pragma unroll
        for (int j = 0; j < 8; j++) {
            int c = lane + 32 * j;
            r[j] = (x[j] - mu) * rstd * gbev[c] + gbev[256 + c] + gbev[512 + c];
        }

        float w[16];
#pragma unroll
        for (int e = 0; e < 16; e++) {
            float p = 0.f;
#pragma unroll
            for (int j = 0; j < 8; j++) p += r[j] * gwT[e * 257 + lane + 32 * j];
#pragma unroll
            for (int o = 16; o; o >>= 1) p += __shfl_xor_sync(0xffffffffu, p, o);
            w[e] = p + gbev[768 + e];
        }

        float mx = w[0];
#pragma unroll
        for (int e = 1; e < 16; e++) mx = fmaxf(mx, w[e]);
        float sum = 0.f;
#pragma unroll
        for (int e = 0; e < 16; e++) { w[e] = expf(w[e] - mx); sum += w[e]; }
        float inv = 1.f / sum;
        float ent = 0.f;
#pragma unroll
        for (int e = 0; e < 16; e++) { w[e] *= inv; ent -= w[e] * logf(w[e] + 1e-12f); }
        float kf = ceilf(1.f + ent * (15.f / 2.7725887222397811f));
        int k = (int)kf; k = k < 1 ? 1 : (k > 16 ? 16 : k);

        if (lane < 16) {
            float we = w[lane];
            int rank = 0;
#pragma unroll
            for (int j = 0; j < 16; j++)
                rank += (w[j] > we) || (w[j] == we && j < lane);
            int sel = rank < k;
            g_combine[n * 16 + lane] = sel ? we : 0.f;
            st += sel ? 1.f : 0.f;
            sp += we;
        }
    }

    if (lane < 16) { wpt[warp * 16 + lane] = st; wpp[warp * 16 + lane] = sp; }
    __syncthreads();
    if (tid < 16) {
        float t = 0.f, p = 0.f;
#pragma unroll
        for (int w = 0; w < 8; w++) { t += wpt[w * 16 + tid]; p += wpp[w * 16 + tid]; }
        g_pt[blockIdx.x * 16 + tid] = t;
        g_pp[blockIdx.x * 16 + tid] = p;
    }
}

// ---------------- kernel 2: mma.sync fused MoE GEMM v5 (fp16 2-term) ----------------
// CTA 64(M) x 64(N), 128 threads (4 warps 2x2, warp 32x32), 3 CTAs/SM.
#define WS_OFF 0            // 2 stages x (wh 9216 + wl 9216), row stride 144
#define XC_OFF 36864        // current X chunk (fp16): 9216
#define SC_OFF 46080        // [17][64] f32
#define BS_OFF 50432        // [17][64] f32
#define SMEM_BYTES 54784

#define LDSM4(R, A) \
    asm volatile("ldmatrix.sync.aligned.m8n8.x4.shared.b16 {%0,%1,%2,%3}, [%4];" \
        : "=r"((R)[0]), "=r"((R)[1]), "=r"((R)[2]), "=r"((R)[3]) : "r"(A))
#define MMA16816(D, A, B) \
    asm volatile("mma.sync.aligned.m16n8k16.row.col.f32.f16.f16.f32 " \
        "{%0,%1,%2,%3}, {%4,%5,%6,%7}, {%8,%9}, {%0,%1,%2,%3};" \
        : "+f"((D)[0]), "+f"((D)[1]), "+f"((D)[2]), "+f"((D)[3]) \
        : "r"((A)[0]), "r"((A)[1]), "r"((A)[2]), "r"((A)[3]), "r"((B)[0]), "r"((B)[1]))

__device__ __forceinline__ uint32_t packh(float a, float b) {
    __half2 h = __floats2half2_rn(a, b);
    return *reinterpret_cast<uint32_t*>(&h);
}

// prefetch W stage for task t (c = t/17, m = t%17) into buffer t&1
__device__ __forceinline__ void prefetch_w(uint32_t wbase, int t, int colBase, int tid)
{
    const int c = t / 17;
    const int m = t - c * 17;
    const int buf = t & 1;
#pragma unroll
    for (int i = 0; i < 8; i++) {
        int idx = tid + i * 128;           // 0..1023
        int half = idx >> 9;               // 0: wh, 1: wl
        int r = (idx >> 3) & 63;
        int q = idx & 7;
        const __half* src = (half ? g_Wlo : g_Whi) +
            (size_t)m * 65536 + (size_t)(colBase + r) * 256 + c * 64 + q * 8;
        uint32_t dst = wbase + buf * 18432 + half * 9216 + r * 144 + q * 16;
        asm volatile("cp.async.cg.shared.global [%0], [%1], 16;"
                     :: "r"(dst), "l"(src) : "memory");
    }
    asm volatile("cp.async.commit_group;" ::: "memory");
}

// convert X chunk (64 rows x 64 k) from gmem to fp16 into XC buffer
__device__ __forceinline__ void convert_x(char* smc, const float* Xb, int chunk, int tid)
{
#pragma unroll
    for (int i = 0; i < 8; i++) {
        int idx = tid + i * 128;           // 0..1023 float4 slots
        int r = idx >> 4;
        int k4 = idx & 15;
        float4 v = reinterpret_cast<const float4*>(Xb + (size_t)r * 256 + chunk * 64)[k4];
        uint2 h = make_uint2(packh(v.x, v.y), packh(v.z, v.w));
        *reinterpret_cast<uint2*>(smc + XC_OFF + r * 144 + k4 * 8) = h;
    }
}

__global__ __launch_bounds__(128, 3) void moe_mma_kernel(
    const float* __restrict__ X,
    const float* __restrict__ shareB,
    const float* __restrict__ expB,
    float* __restrict__ out)
{
    extern __shared__ char smc[];
    const int tid = threadIdx.x;
    const int lane = tid & 31, warp = tid >> 5;
    const int rowBase = blockIdx.y * 64;
    const int colBase = blockIdx.x * 64;
    const uint32_t sb = smem_u32(smc);
    const uint32_t wbase = sb + WS_OFF;

    prefetch_w(wbase, 0, colBase, tid);

    float* Sc = reinterpret_cast<float*>(smc + SC_OFF);
    float* Bs = reinterpret_cast<float*>(smc + BS_OFF);

    for (int idx = tid; idx < 17 * 64; idx += 128) {
        int m = idx >> 6, r = idx & 63;
        Sc[idx] = (m == 0) ? 1.0f : g_combine[(size_t)(rowBase + r) * 16 + (m - 1)];
    }
    for (int idx = tid; idx < 17 * 64; idx += 128) {
        int m = idx >> 6, c = idx & 63;
        Bs[idx] = (m == 0) ? shareB[colBase + c] : expB[(m - 1) * 256 + colBase + c];
    }

    const float* Xb = X + (size_t)rowBase * 256;
    convert_x(smc, Xb, 0, tid);

    const int m0 = (warp & 1) * 32;
    const int n0 = (warp >> 1) * 32;

    const uint32_t xh_base = sb + XC_OFF + (uint32_t)(m0 + (lane & 15)) * 144 + (lane >> 4) * 16;
    const uint32_t wb_base = wbase +
        (uint32_t)(n0 + ((lane >> 4) & 1) * 8 + (lane & 7)) * 144 + ((lane >> 3) & 1) * 16;

    const int rq = lane >> 2;
    const int cq = (lane & 3) * 2;

    float acc[2][4][4];
#pragma unroll
    for (int mt = 0; mt < 2; mt++)
#pragma unroll
        for (int nt = 0; nt < 4; nt++)
#pragma unroll
            for (int q = 0; q < 4; q++) acc[mt][nt][q] = 0.f;

    __syncthreads();   // X chunk 0 / Sc / Bs visible

    // acc init = sum_m s_m * b_m
#pragma unroll 1
    for (int m = 0; m < NMAT; m++) {
        float s0 = Sc[m * 64 + m0 + rq];
        float s1 = Sc[m * 64 + m0 + rq + 8];
        float s2 = Sc[m * 64 + m0 + rq + 16];
        float s3 = Sc[m * 64 + m0 + rq + 24];
#pragma unroll
        for (int nt = 0; nt < 4; nt++) {
            float b0 = Bs[m * 64 + n0 + nt * 8 + cq];
            float b1 = Bs[m * 64 + n0 + nt * 8 + cq + 1];
            acc[0][nt][0] += s0 * b0; acc[0][nt][1] += s0 * b1;
            acc[0][nt][2] += s1 * b0; acc[0][nt][3] += s1 * b1;
            acc[1][nt][0] += s2 * b0; acc[1][nt][1] += s2 * b1;
            acc[1][nt][2] += s3 * b0; acc[1][nt][3] += s3 * b1;
        }
    }

    uint32_t Ah[4][2][4];
    float p[2][4][4];

#pragma unroll 1
    for (int t = 0; t < NMAT * 4; t++) {
        const int c = t / 17;
        const int m = t - c * 17;
        const int buf = t & 1;

        asm volatile("cp.async.wait_group 0;" ::: "memory");
        __syncthreads();

        if (t + 1 < NMAT * 4) prefetch_w(wbase, t + 1, colBase, tid);

        if (m == 0) {
#pragma unroll
            for (int ks = 0; ks < 4; ks++) {
#pragma unroll
                for (int mt = 0; mt < 2; mt++)
                    LDSM4(Ah[ks][mt], xh_base + mt * (16 * 144) + ks * 32);
            }
        }
        if (m == 1 && c < 3) {
            convert_x(smc, Xb, c + 1, tid);
        }

#pragma unroll
        for (int mt = 0; mt < 2; mt++)
#pragma unroll
            for (int nt = 0; nt < 4; nt++)
#pragma unroll
                for (int q = 0; q < 4; q++) p[mt][nt][q] = 0.f;

        const uint32_t wbs = wb_base + buf * 18432;
#pragma unroll
        for (int ks = 0; ks < 4; ks++) {
            uint32_t Bh[4][2], Bl[4][2];
#pragma unroll
            for (int ntp = 0; ntp < 2; ntp++) {
                uint32_t r4[4];
                LDSM4(r4, wbs + ntp * (16 * 144) + ks * 32);
                Bh[ntp * 2][0] = r4[0]; Bh[ntp * 2][1] = r4[1];
                Bh[ntp * 2 + 1][0] = r4[2]; Bh[ntp * 2 + 1][1] = r4[3];
                LDSM4(r4, wbs + 9216 + ntp * (16 * 144) + ks * 32);
                Bl[ntp * 2][0] = r4[0]; Bl[ntp * 2][1] = r4[1];
                Bl[ntp * 2 + 1][0] = r4[2]; Bl[ntp * 2 + 1][1] = r4[3];
            }
#pragma unroll
            for (int mt = 0; mt < 2; mt++)
#pragma unroll
                for (int nt = 0; nt < 4; nt++)
                    MMA16816(p[mt][nt], Ah[ks][mt], Bh[nt]);
#pragma unroll
            for (int mt = 0; mt < 2; mt++)
#pragma unroll
                for (int nt = 0; nt < 4; nt++)
                    MMA16816(p[mt][nt], Ah[ks][mt], Bl[nt]);
        }

        // epilogue: acc += s_row * p
        {
            float s0 = Sc[m * 64 + m0 + rq];
            float s1 = Sc[m * 64 + m0 + rq + 8];
            float s2 = Sc[m * 64 + m0 + rq + 16];
            float s3 = Sc[m * 64 + m0 + rq + 24];
#pragma unroll
            for (int nt = 0; nt < 4; nt++) {
                acc[0][nt][0] += s0 * p[0][nt][0];
                acc[0][nt][1] += s0 * p[0][nt][1];
                acc[0][nt][2] += s1 * p[0][nt][2];
                acc[0][nt][3] += s1 * p[0][nt][3];
                acc[1][nt][0] += s2 * p[1][nt][0];
                acc[1][nt][1] += s2 * p[1][nt][1];
                acc[1][nt][2] += s3 * p[1][nt][2];
                acc[1][nt][3] += s3 * p[1][nt][3];
            }
        }
    }

    // write output
#pragma unroll
    for (int mt = 0; mt < 2; mt++) {
        int rg = rowBase + m0 + mt * 16 + rq;
#pragma unroll
        for (int nt = 0; nt < 4; nt++) {
            int cg = colBase + n0 + nt * 8 + cq;
            *reinterpret_cast<float2*>(out + (size_t)rg * 256 + cg) =
                make_float2(acc[mt][nt][0], acc[mt][nt][1]);
            *reinterpret_cast<float2*>(out + (size_t)(rg + 8) * 256 + cg) =
                make_float2(acc[mt][nt][2], acc[mt][nt][3]);
        }
    }
}

// ---------------- kernel 3: loss reduce + finalize ----------------
__global__ __launch_bounds__(256) void finalize_kernel(float* __restrict__ out, int out_size)
{
    __shared__ float rt[16][17], rp[16][17];
    __shared__ float prod[16];
    int tid = threadIdx.x;
    int e = tid & 15, part = tid >> 4;
    float t = 0.f, p = 0.f;
    for (int b = part * 16; b < part * 16 + 16; b++) {
        t += g_pt[b * 16 + e];
        p += g_pp[b * 16 + e];
    }
    rt[part][e] = t; rp[part][e] = p;
    __syncthreads();
    if (tid < 16) {
        float ts = 0.f, ps = 0.f;
#pragma unroll
        for (int q = 0; q < 16; q++) { ts += rt[q][tid]; ps += rp[q][tid]; }
        prod[tid] = (ts * (1.f / (float)N_TOK)) * (ps * (1.f / (float)N_TOK));
    }
    __syncthreads();
    const int NC = N_TOK * C_DIM;
    if (tid == 0) {
        float a = 0.f;
#pragma unroll
        for (int q = 0; q < 16; q++) a += prod[q];
        if (out_size > NC) out[NC] = a * 16.f;
    }
    for (int i = NC + 1 + tid; i < out_size; i += 256)
        out[i] = 0.f;
}

// ---------------- launch ----------------
extern "C" void kernel_launch(void* const* d_in, const int* in_sizes, int n_in,
                              void* d_out, int out_size)
{
    const float* inputs = (const float*)d_in[0];
    const float* conv   = (const float*)d_in[1];
    const float* emb    = (const float*)d_in[2];
    const float* shareW = (const float*)d_in[3];
    const float* shareB = (const float*)d_in[4];
    const float* gateW  = (const float*)d_in[5];
    const float* gateB  = (const float*)d_in[6];
    const float* expW   = (const float*)d_in[7];
    const float* expB   = (const float*)d_in[8];
    const float* gamma  = (const float*)d_in[9];
    const float* beta   = (const float*)d_in[10];
    float* out = (float*)d_out;

    prep_kernel<<<RBLK + NMAT * 64, 256>>>(conv, emb, gateW, gateB, gamma, beta,
                                           shareW, expW);

    cudaFuncSetAttribute(moe_mma_kernel,
                         cudaFuncAttributeMaxDynamicSharedMemorySize, SMEM_BYTES);
    moe_mma_kernel<<<dim3(4, 512), 128, SMEM_BYTES>>>(inputs, shareB, expB, out);

    finalize_kernel<<<1, 256>>>(out, out_size);
}

// round 8
// speedup vs baseline: 4.4690x; 1.0198x over previous
#include <cuda_runtime.h>
#include <cuda_fp16.h>
#include <math.h>
#include <stdint.h>

#define N_TOK 32768
#define C_DIM 256
#define E_NUM 16
#define NMAT 17
#define RBLK 256          // router blocks (128 tokens each)
#define NTASK (NMAT * 4)  // 68

// ---------------- scratch (no allocations allowed) ----------------
__device__ float g_combine[N_TOK * E_NUM];
__device__ float g_pt[RBLK * 16];
__device__ float g_pp[RBLK * 16];
__device__ __align__(128) __half g_Whi[NMAT * C_DIM * C_DIM];
__device__ __align__(128) __half g_Wlo[NMAT * C_DIM * C_DIM];

__device__ __forceinline__ uint32_t smem_u32(const void* p) {
    uint32_t a;
    asm("{ .reg .u64 t; cvta.to.shared.u64 t, %1; cvt.u32.u64 %0, t; }" : "=r"(a) : "l"(p));
    return a;
}

// ---------------- kernel 1: fused router + W-prep ----------------
__global__ __launch_bounds__(256) void prep_kernel(
    const float* __restrict__ conv, const float* __restrict__ emb,
    const float* __restrict__ gateW, const float* __restrict__ gateB,
    const float* __restrict__ gamma, const float* __restrict__ beta,
    const float* __restrict__ shareW, const float* __restrict__ expW)
{
    int tid = threadIdx.x;

    if (blockIdx.x >= RBLK) {
        // ---- W prep: transpose + fp16 hi/lo split ----
        __shared__ float tile[32][33];
        int w = blockIdx.x - RBLK;
        int m = w >> 6;
        int rr = w & 63;
        int by = rr >> 3, bx = rr & 7;
        const float* src = (m == 0) ? shareW : expW + (size_t)(m - 1) * 65536;
        int tx = tid & 31, ty = tid >> 5;
        if (ty < 8) {
#pragma unroll
            for (int i = 0; i < 4; i++) {
                int k = by * 32 + ty + i * 8;
                int n = bx * 32 + tx;
                tile[ty + i * 8][tx] = src[k * 256 + n];
            }
        }
        __syncthreads();
        if (ty < 8) {
#pragma unroll
            for (int i = 0; i < 4; i++) {
                int n = bx * 32 + ty + i * 8;
                int k = by * 32 + tx;
                float v = tile[tx][ty + i * 8];
                __half h = __float2half_rn(v);
                float lo = v - __half2float(h);
                size_t o = (size_t)m * 65536 + (size_t)n * 256 + k;
                g_Whi[o] = h;
                g_Wlo[o] = __float2half_rn(lo);
            }
        }
        return;
    }

    // ---- router: 8 warps, each warp 16 tokens as 8 pairs (2 tokens/warp-pass) ----
    __shared__ float gwT[16 * 257];
    __shared__ float gbev[3 * 256 + 16];
    __shared__ float wpt[8 * 16], wpp[8 * 16];
    for (int idx = tid; idx < 4096; idx += 256)
        gwT[(idx & 15) * 257 + (idx >> 4)] = gateW[idx];
    if (tid < 256) {
        gbev[tid] = gamma[tid];
        gbev[256 + tid] = beta[tid];
        gbev[512 + tid] = emb[tid];
    }
    if (tid < 16) gbev[768 + tid] = gateB[tid];
    __syncthreads();

    int warp = tid >> 5, lane = tid & 31;
    int half = lane >> 4;       // which token of the pair
    int sl = lane & 15;         // sub-lane within 16-lane group
    float st = 0.f, sp = 0.f;   // lane owns expert sl for its half's tokens

#pragma unroll 1
    for (int i = 0; i < 8; i++) {
        int n = blockIdx.x * 128 + warp * 16 + i * 2 + half;
        const float* row = conv + (size_t)n * C_DIM;

        float x[16];
        float s = 0.f, s2 = 0.f;
#pragma unroll
        for (int j = 0; j < 16; j++) {
            x[j] = row[sl + 16 * j];
            s += x[j]; s2 += x[j] * x[j];
        }
#pragma unroll
        for (int o = 8; o; o >>= 1) {
            s  += __shfl_xor_sync(0xffffffffu, s,  o);
            s2 += __shfl_xor_sync(0xffffffffu, s2, o);
        }
        float mu = s * (1.f / 256.f);
        float var = s2 * (1.f / 256.f) - mu * mu;
        float rstd = rsqrtf(var + 1e-5f);

        float r[16];
#pragma unroll
        for (int j = 0; j < 16; j++) {
            int c = sl + 16 * j;
            r[j] = (x[j] - mu) * rstd * gbev[c] + gbev[256 + c] + gbev[512 + c];
        }

        float w[16];
#pragma unroll
        for (int e = 0; e < 16; e++) {
            float p = 0.f;
#pragma unroll
            for (int j = 0; j < 16; j++) p += r[j] * gwT[e * 257 + sl + 16 * j];
#pragma unroll
            for (int o = 8; o; o >>= 1) p += __shfl_xor_sync(0xffffffffu, p, o);
            w[e] = p + gbev[768 + e];
        }

        // softmax / entropy / k redundant across the 16 lanes of this half
        float mx = w[0];
#pragma unroll
        for (int e = 1; e < 16; e++) mx = fmaxf(mx, w[e]);
        float sum = 0.f;
#pragma unroll
        for (int e = 0; e < 16; e++) { w[e] = expf(w[e] - mx); sum += w[e]; }
        float inv = 1.f / sum;
        float ent = 0.f;
#pragma unroll
        for (int e = 0; e < 16; e++) { w[e] *= inv; ent -= w[e] * logf(w[e] + 1e-12f); }
        float kf = ceilf(1.f + ent * (15.f / 2.7725887222397811f));
        int k = (int)kf; k = k < 1 ? 1 : (k > 16 ? 16 : k);

        // lane sl handles expert sl of its token
        float we = w[sl];
        int rank = 0;
#pragma unroll
        for (int j = 0; j < 16; j++)
            rank += (w[j] > we) || (w[j] == we && j < sl);
        int sel = rank < k;
        g_combine[(size_t)n * 16 + sl] = sel ? we : 0.f;
        st += sel ? 1.f : 0.f;
        sp += we;
    }

    // merge the two halves' per-expert partials
    st += __shfl_xor_sync(0xffffffffu, st, 16);
    sp += __shfl_xor_sync(0xffffffffu, sp, 16);
    if (lane < 16) { wpt[warp * 16 + lane] = st; wpp[warp * 16 + lane] = sp; }
    __syncthreads();
    if (tid < 16) {
        float t = 0.f, p = 0.f;
#pragma unroll
        for (int w = 0; w < 8; w++) { t += wpt[w * 16 + tid]; p += wpp[w * 16 + tid]; }
        g_pt[blockIdx.x * 16 + tid] = t;
        g_pp[blockIdx.x * 16 + tid] = p;
    }
}

// ---------------- kernel 2: mma.sync fused MoE GEMM v6 (3-stage ring) ----------------
// CTA 64(M) x 64(N), 128 threads (4 warps 2x2, warp 32x32), 3 CTAs/SM.
#define WS_OFF 0            // 3 stages x (wh 9216 + wl 9216), row stride 144
#define XC_OFF 55296        // current X chunk (fp16): 9216
#define SC_OFF 64512        // [17][64] f32
#define BS_OFF 68864        // [17][64] f32
#define SMEM_BYTES 73216

#define LDSM4(R, A) \
    asm volatile("ldmatrix.sync.aligned.m8n8.x4.shared.b16 {%0,%1,%2,%3}, [%4];" \
        : "=r"((R)[0]), "=r"((R)[1]), "=r"((R)[2]), "=r"((R)[3]) : "r"(A))
#define MMA16816(D, A, B) \
    asm volatile("mma.sync.aligned.m16n8k16.row.col.f32.f16.f16.f32 " \
        "{%0,%1,%2,%3}, {%4,%5,%6,%7}, {%8,%9}, {%0,%1,%2,%3};" \
        : "+f"((D)[0]), "+f"((D)[1]), "+f"((D)[2]), "+f"((D)[3]) \
        : "r"((A)[0]), "r"((A)[1]), "r"((A)[2]), "r"((A)[3]), "r"((B)[0]), "r"((B)[1]))

__device__ __forceinline__ uint32_t packh(float a, float b) {
    __half2 h = __floats2half2_rn(a, b);
    return *reinterpret_cast<uint32_t*>(&h);
}

// prefetch W for task t (c = t/17, m = t%17) into ring stage t%3
__device__ __forceinline__ void prefetch_w(uint32_t wbase, int t, int colBase, int tid)
{
    const int c = t / 17;
    const int m = t - c * 17;
    const int stage = t % 3;
#pragma unroll
    for (int i = 0; i < 8; i++) {
        int idx = tid + i * 128;           // 0..1023
        int half = idx >> 9;               // 0: wh, 1: wl
        int r = (idx >> 3) & 63;
        int q = idx & 7;
        const __half* src = (half ? g_Wlo : g_Whi) +
            (size_t)m * 65536 + (size_t)(colBase + r) * 256 + c * 64 + q * 8;
        uint32_t dst = wbase + stage * 18432 + half * 9216 + r * 144 + q * 16;
        asm volatile("cp.async.cg.shared.global [%0], [%1], 16;"
                     :: "r"(dst), "l"(src) : "memory");
    }
    asm volatile("cp.async.commit_group;" ::: "memory");
}

__device__ __forceinline__ void convert_x(char* smc, const float* Xb, int chunk, int tid)
{
#pragma unroll
    for (int i = 0; i < 8; i++) {
        int idx = tid + i * 128;
        int r = idx >> 4;
        int k4 = idx & 15;
        float4 v = reinterpret_cast<const float4*>(Xb + (size_t)r * 256 + chunk * 64)[k4];
        uint2 h = make_uint2(packh(v.x, v.y), packh(v.z, v.w));
        *reinterpret_cast<uint2*>(smc + XC_OFF + r * 144 + k4 * 8) = h;
    }
}

__global__ __launch_bounds__(128, 3) void moe_mma_kernel(
    const float* __restrict__ X,
    const float* __restrict__ shareB,
    const float* __restrict__ expB,
    float* __restrict__ out)
{
    extern __shared__ char smc[];
    const int tid = threadIdx.x;
    const int lane = tid & 31, warp = tid >> 5;
    const int rowBase = blockIdx.y * 64;
    const int colBase = blockIdx.x * 64;
    const uint32_t sb = smem_u32(smc);
    const uint32_t wbase = sb + WS_OFF;

    prefetch_w(wbase, 0, colBase, tid);     // group 0 = stage 0

    float* Sc = reinterpret_cast<float*>(smc + SC_OFF);
    float* Bs = reinterpret_cast<float*>(smc + BS_OFF);

    for (int idx = tid; idx < 17 * 64; idx += 128) {
        int m = idx >> 6, r = idx & 63;
        Sc[idx] = (m == 0) ? 1.0f : g_combine[(size_t)(rowBase + r) * 16 + (m - 1)];
    }
    for (int idx = tid; idx < 17 * 64; idx += 128) {
        int m = idx >> 6, c = idx & 63;
        Bs[idx] = (m == 0) ? shareB[colBase + c] : expB[(m - 1) * 256 + colBase + c];
    }

    prefetch_w(wbase, 1, colBase, tid);     // group 1 = stage 1

    const float* Xb = X + (size_t)rowBase * 256;
    convert_x(smc, Xb, 0, tid);

    const int m0 = (warp & 1) * 32;
    const int n0 = (warp >> 1) * 32;

    const uint32_t xh_base = sb + XC_OFF + (uint32_t)(m0 + (lane & 15)) * 144 + (lane >> 4) * 16;
    const uint32_t wb_base = wbase +
        (uint32_t)(n0 + ((lane >> 4) & 1) * 8 + (lane & 7)) * 144 + ((lane >> 3) & 1) * 16;

    const int rq = lane >> 2;
    const int cq = (lane & 3) * 2;

    float acc[2][4][4];
#pragma unroll
    for (int mt = 0; mt < 2; mt++)
#pragma unroll
        for (int nt = 0; nt < 4; nt++)
#pragma unroll
            for (int q = 0; q < 4; q++) acc[mt][nt][q] = 0.f;

    __syncthreads();   // X chunk 0 / Sc / Bs visible

    // acc init = sum_m s_m * b_m
#pragma unroll 1
    for (int m = 0; m < NMAT; m++) {
        float s0 = Sc[m * 64 + m0 + rq];
        float s1 = Sc[m * 64 + m0 + rq + 8];
        float s2 = Sc[m * 64 + m0 + rq + 16];
        float s3 = Sc[m * 64 + m0 + rq + 24];
#pragma unroll
        for (int nt = 0; nt < 4; nt++) {
            float b0 = Bs[m * 64 + n0 + nt * 8 + cq];
            float b1 = Bs[m * 64 + n0 + nt * 8 + cq + 1];
            acc[0][nt][0] += s0 * b0; acc[0][nt][1] += s0 * b1;
            acc[0][nt][2] += s1 * b0; acc[0][nt][3] += s1 * b1;
            acc[1][nt][0] += s2 * b0; acc[1][nt][1] += s2 * b1;
            acc[1][nt][2] += s3 * b0; acc[1][nt][3] += s3 * b1;
        }
    }

    uint32_t Ah[4][2][4];
    float p[2][4][4];

#pragma unroll 1
    for (int t = 0; t < NTASK; t++) {
        const int c = t / 17;
        const int m = t - c * 17;
        const int stage = t % 3;

        // ring depth 2: stage t must be done; stage t+1 may still fly
        asm volatile("cp.async.wait_group 1;" ::: "memory");
        __syncthreads();

        if (m == 0) {
#pragma unroll
            for (int ks = 0; ks < 4; ks++) {
#pragma unroll
                for (int mt = 0; mt < 2; mt++)
                    LDSM4(Ah[ks][mt], xh_base + mt * (16 * 144) + ks * 32);
            }
        }
        if (m == 1 && c < 3) {
            convert_x(smc, Xb, c + 1, tid);
        }

#pragma unroll
        for (int mt = 0; mt < 2; mt++)
#pragma unroll
            for (int nt = 0; nt < 4; nt++)
#pragma unroll
                for (int q = 0; q < 4; q++) p[mt][nt][q] = 0.f;

        const uint32_t wbs = wb_base + stage * 18432;
#pragma unroll
        for (int ks = 0; ks < 4; ks++) {
            uint32_t Bh[4][2], Bl[4][2];
#pragma unroll
            for (int ntp = 0; ntp < 2; ntp++) {
                uint32_t r4[4];
                LDSM4(r4, wbs + ntp * (16 * 144) + ks * 32);
                Bh[ntp * 2][0] = r4[0]; Bh[ntp * 2][1] = r4[1];
                Bh[ntp * 2 + 1][0] = r4[2]; Bh[ntp * 2 + 1][1] = r4[3];
                LDSM4(r4, wbs + 9216 + ntp * (16 * 144) + ks * 32);
                Bl[ntp * 2][0] = r4[0]; Bl[ntp * 2][1] = r4[1];
                Bl[ntp * 2 + 1][0] = r4[2]; Bl[ntp * 2 + 1][1] = r4[3];
            }
#pragma unroll
            for (int mt = 0; mt < 2; mt++)
#pragma unroll
                for (int nt = 0; nt < 4; nt++)
                    MMA16816(p[mt][nt], Ah[ks][mt], Bh[nt]);
#pragma unroll
            for (int mt = 0; mt < 2; mt++)
#pragma unroll
                for (int nt = 0; nt < 4; nt++)
                    MMA16816(p[mt][nt], Ah[ks][mt], Bl[nt]);
        }

        // epilogue: acc += s_row * p
        {
            float s0 = Sc[m * 64 + m0 + rq];
            float s1 = Sc[m * 64 + m0 + rq + 8];
            float s2 = Sc[m * 64 + m0 + rq + 16];
            float s3 = Sc[m * 64 + m0 + rq + 24];
#pragma unroll
            for (int nt = 0; nt < 4; nt++) {
                acc[0][nt][0] += s0 * p[0][nt][0];
                acc[0][nt][1] += s0 * p[0][nt][1];
                acc[0][nt][2] += s1 * p[0][nt][2];
                acc[0][nt][3] += s1 * p[0][nt][3];
                acc[1][nt][0] += s2 * p[1][nt][0];
                acc[1][nt][1] += s2 * p[1][nt][1];
                acc[1][nt][2] += s3 * p[1][nt][2];
                acc[1][nt][3] += s3 * p[1][nt][3];
            }
        }

        // keep the ring full; always commit so group accounting stays exact
        if (t + 2 < NTASK) prefetch_w(wbase, t + 2, colBase, tid);
        else asm volatile("cp.async.commit_group;" ::: "memory");
    }

    // write output
#pragma unroll
    for (int mt = 0; mt < 2; mt++) {
        int rg = rowBase + m0 + mt * 16 + rq;
#pragma unroll
        for (int nt = 0; nt < 4; nt++) {
            int cg = colBase + n0 + nt * 8 + cq;
            *reinterpret_cast<float2*>(out + (size_t)rg * 256 + cg) =
                make_float2(acc[mt][nt][0], acc[mt][nt][1]);
            *reinterpret_cast<float2*>(out + (size_t)(rg + 8) * 256 + cg) =
                make_float2(acc[mt][nt][2], acc[mt][nt][3]);
        }
    }
}

// ---------------- kernel 3: loss reduce + finalize ----------------
__global__ __launch_bounds__(256) void finalize_kernel(float* __restrict__ out, int out_size)
{
    __shared__ float rt[16][17], rp[16][17];
    __shared__ float prod[16];
    int tid = threadIdx.x;
    int e = tid & 15, part = tid >> 4;
    float t = 0.f, p = 0.f;
    for (int b = part * 16; b < part * 16 + 16; b++) {
        t += g_pt[b * 16 + e];
        p += g_pp[b * 16 + e];
    }
    rt[part][e] = t; rp[part][e] = p;
    __syncthreads();
    if (tid < 16) {
        float ts = 0.f, ps = 0.f;
#pragma unroll
        for (int q = 0; q < 16; q++) { ts += rt[q][tid]; ps += rp[q][tid]; }
        prod[tid] = (ts * (1.f / (float)N_TOK)) * (ps * (1.f / (float)N_TOK));
    }
    __syncthreads();
    const int NC = N_TOK * C_DIM;
    if (tid == 0) {
        float a = 0.f;
#pragma unroll
        for (int q = 0; q < 16; q++) a += prod[q];
        if (out_size > NC) out[NC] = a * 16.f;
    }
    for (int i = NC + 1 + tid; i < out_size; i += 256)
        out[i] = 0.f;
}

// ---------------- launch ----------------
extern "C" void kernel_launch(void* const* d_in, const int* in_sizes, int n_in,
                              void* d_out, int out_size)
{
    const float* inputs = (const float*)d_in[0];
    const float* conv   = (const float*)d_in[1];
    const float* emb    = (const float*)d_in[2];
    const float* shareW = (const float*)d_in[3];
    const float* shareB = (const float*)d_in[4];
    const float* gateW  = (const float*)d_in[5];
    const float* gateB  = (const float*)d_in[6];
    const float* expW   = (const float*)d_in[7];
    const float* expB   = (const float*)d_in[8];
    const float* gamma  = (const float*)d_in[9];
    const float* beta   = (const float*)d_in[10];
    float* out = (float*)d_out;

    prep_kernel<<<RBLK + NMAT * 64, 256>>>(conv, emb, gateW, gateB, gamma, beta,
                                           shareW, expW);

    cudaFuncSetAttribute(moe_mma_kernel,
                         cudaFuncAttributeMaxDynamicSharedMemorySize, SMEM_BYTES);
    moe_mma_kernel<<<dim3(4, 512), 128, SMEM_BYTES>>>(inputs, shareB, expB, out);

    finalize_kernel<<<1, 256>>>(out, out_size);
}

// round 9
// speedup vs baseline: 5.2351x; 1.1714x over previous
#include <cuda_runtime.h>
#include <cuda_fp16.h>
#include <math.h>
#include <stdint.h>

#define N_TOK 32768
#define C_DIM 256
#define E_NUM 16
#define NMAT 17
#define RBLK 512          // router blocks (64 tokens each)
#define NTASK (NMAT * 4)  // 68

// ---------------- scratch (no allocations allowed) ----------------
__device__ float g_combine[N_TOK * E_NUM];
__device__ float g_pt[RBLK * 16];
__device__ float g_pp[RBLK * 16];
__device__ __align__(128) __half g_Whi[NMAT * C_DIM * C_DIM];
__device__ __align__(128) __half g_Wlo[NMAT * C_DIM * C_DIM];

__device__ __forceinline__ uint32_t smem_u32(const void* p) {
    uint32_t a;
    asm("{ .reg .u64 t; cvta.to.shared.u64 t, %1; cvt.u32.u64 %0, t; }" : "=r"(a) : "l"(p));
    return a;
}

// ---------------- kernel 1: fused router + W-prep ----------------
__global__ __launch_bounds__(256) void prep_kernel(
    const float* __restrict__ conv, const float* __restrict__ emb,
    const float* __restrict__ gateW, const float* __restrict__ gateB,
    const float* __restrict__ gamma, const float* __restrict__ beta,
    const float* __restrict__ shareW, const float* __restrict__ expW)
{
    int tid = threadIdx.x;

    if (blockIdx.x >= RBLK) {
        // ---- W prep: transpose + fp16 hi/lo split ----
        __shared__ float tile[32][33];
        int w = blockIdx.x - RBLK;
        int m = w >> 6;
        int rr = w & 63;
        int by = rr >> 3, bx = rr & 7;
        const float* src = (m == 0) ? shareW : expW + (size_t)(m - 1) * 65536;
        int tx = tid & 31, ty = tid >> 5;
        if (ty < 8) {
#pragma unroll
            for (int i = 0; i < 4; i++) {
                int k = by * 32 + ty + i * 8;
                int n = bx * 32 + tx;
                tile[ty + i * 8][tx] = src[k * 256 + n];
            }
        }
        __syncthreads();
        if (ty < 8) {
#pragma unroll
            for (int i = 0; i < 4; i++) {
                int n = bx * 32 + ty + i * 8;
                int k = by * 32 + tx;
                float v = tile[tx][ty + i * 8];
                __half h = __float2half_rn(v);
                float lo = v - __half2float(h);
                size_t o = (size_t)m * 65536 + (size_t)n * 256 + k;
                g_Whi[o] = h;
                g_Wlo[o] = __float2half_rn(lo);
            }
        }
        return;
    }

    // ---- router: 8 warps x 8 tokens (4 pair-passes, 2 tokens/warp-pass) ----
    __shared__ float gwT[16 * 257];
    __shared__ float gbev[3 * 256 + 16];
    __shared__ float wpt[8 * 16], wpp[8 * 16];
    for (int idx = tid; idx < 4096; idx += 256)
        gwT[(idx & 15) * 257 + (idx >> 4)] = gateW[idx];
    if (tid < 256) {
        gbev[tid] = gamma[tid];
        gbev[256 + tid] = beta[tid];
        gbev[512 + tid] = emb[tid];
    }
    if (tid < 16) gbev[768 + tid] = gateB[tid];
    __syncthreads();

    int warp = tid >> 5, lane = tid & 31;
    int half = lane >> 4;
    int sl = lane & 15;
    float st = 0.f, sp = 0.f;

#pragma unroll 1
    for (int i = 0; i < 4; i++) {
        int n = blockIdx.x * 64 + warp * 8 + i * 2 + half;
        const float* row = conv + (size_t)n * C_DIM;

        float x[16];
        float s = 0.f, s2 = 0.f;
#pragma unroll
        for (int j = 0; j < 16; j++) {
            x[j] = row[sl + 16 * j];
            s += x[j]; s2 += x[j] * x[j];
        }
#pragma unroll
        for (int o = 8; o; o >>= 1) {
            s  += __shfl_xor_sync(0xffffffffu, s,  o);
            s2 += __shfl_xor_sync(0xffffffffu, s2, o);
        }
        float mu = s * (1.f / 256.f);
        float var = s2 * (1.f / 256.f) - mu * mu;
        float rstd = rsqrtf(var + 1e-5f);

        float r[16];
#pragma unroll
        for (int j = 0; j < 16; j++) {
            int c = sl + 16 * j;
            r[j] = (x[j] - mu) * rstd * gbev[c] + gbev[256 + c] + gbev[512 + c];
        }

        float w[16];
#pragma unroll
        for (int e = 0; e < 16; e++) {
            float p = 0.f;
#pragma unroll
            for (int j = 0; j < 16; j++) p += r[j] * gwT[e * 257 + sl + 16 * j];
#pragma unroll
            for (int o = 8; o; o >>= 1) p += __shfl_xor_sync(0xffffffffu, p, o);
            w[e] = p + gbev[768 + e];
        }

        float mx = w[0];
#pragma unroll
        for (int e = 1; e < 16; e++) mx = fmaxf(mx, w[e]);
        float sum = 0.f;
#pragma unroll
        for (int e = 0; e < 16; e++) { w[e] = expf(w[e] - mx); sum += w[e]; }
        float inv = 1.f / sum;
        float ent = 0.f;
#pragma unroll
        for (int e = 0; e < 16; e++) { w[e] *= inv; ent -= w[e] * logf(w[e] + 1e-12f); }
        float kf = ceilf(1.f + ent * (15.f / 2.7725887222397811f));
        int k = (int)kf; k = k < 1 ? 1 : (k > 16 ? 16 : k);

        float we = w[sl];
        int rank = 0;
#pragma unroll
        for (int j = 0; j < 16; j++)
            rank += (w[j] > we) || (w[j] == we && j < sl);
        int sel = rank < k;
        g_combine[(size_t)n * 16 + sl] = sel ? we : 0.f;
        st += sel ? 1.f : 0.f;
        sp += we;
    }

    st += __shfl_xor_sync(0xffffffffu, st, 16);
    sp += __shfl_xor_sync(0xffffffffu, sp, 16);
    if (lane < 16) { wpt[warp * 16 + lane] = st; wpp[warp * 16 + lane] = sp; }
    __syncthreads();
    if (tid < 16) {
        float t = 0.f, p = 0.f;
#pragma unroll
        for (int w = 0; w < 8; w++) { t += wpt[w * 16 + tid]; p += wpp[w * 16 + tid]; }
        g_pt[blockIdx.x * 16 + tid] = t;
        g_pp[blockIdx.x * 16 + tid] = p;
    }
}

// ---------------- kernel 2: mma.sync fused MoE GEMM v7 ----------------
// CTA 128(M) x 64(N), 256 threads (8 warps 4x2, warp 32x32), 2 CTAs/SM.
// W traffic halved vs 64x64 tiles (grid 1024): L2 decongested.
#define WS_OFF 0            // 3 stages x (wh 9216 + wl 9216), row stride 144
#define XC_OFF 55296        // current X chunk (fp16): 128 rows x 144B = 18432
#define SC_OFF 73728        // [17][128] f32 = 8704
#define BS_OFF 82432        // [17][64] f32 = 4352
#define SMEM_BYTES 86784

#define LDSM4(R, A) \
    asm volatile("ldmatrix.sync.aligned.m8n8.x4.shared.b16 {%0,%1,%2,%3}, [%4];" \
        : "=r"((R)[0]), "=r"((R)[1]), "=r"((R)[2]), "=r"((R)[3]) : "r"(A))
#define MMA16816(D, A, B) \
    asm volatile("mma.sync.aligned.m16n8k16.row.col.f32.f16.f16.f32 " \
        "{%0,%1,%2,%3}, {%4,%5,%6,%7}, {%8,%9}, {%0,%1,%2,%3};" \
        : "+f"((D)[0]), "+f"((D)[1]), "+f"((D)[2]), "+f"((D)[3]) \
        : "r"((A)[0]), "r"((A)[1]), "r"((A)[2]), "r"((A)[3]), "r"((B)[0]), "r"((B)[1]))

__device__ __forceinline__ uint32_t packh(float a, float b) {
    __half2 h = __floats2half2_rn(a, b);
    return *reinterpret_cast<uint32_t*>(&h);
}

// prefetch W for task t (c = t/17, m = t%17) into ring stage t%3
__device__ __forceinline__ void prefetch_w(uint32_t wbase, int t, int colBase, int tid)
{
    const int c = t / 17;
    const int m = t - c * 17;
    const int stage = t % 3;
#pragma unroll
    for (int i = 0; i < 4; i++) {
        int idx = tid + i * 256;           // 0..1023
        int half = idx >> 9;               // 0: wh, 1: wl
        int r = (idx >> 3) & 63;
        int q = idx & 7;
        const __half* src = (half ? g_Wlo : g_Whi) +
            (size_t)m * 65536 + (size_t)(colBase + r) * 256 + c * 64 + q * 8;
        uint32_t dst = wbase + stage * 18432 + half * 9216 + r * 144 + q * 16;
        asm volatile("cp.async.cg.shared.global [%0], [%1], 16;"
                     :: "r"(dst), "l"(src) : "memory");
    }
    asm volatile("cp.async.commit_group;" ::: "memory");
}

// convert X chunk (128 rows x 64 k) from gmem to fp16 into XC buffer
__device__ __forceinline__ void convert_x(char* smc, const float* Xb, int chunk, int tid)
{
#pragma unroll
    for (int i = 0; i < 8; i++) {
        int idx = tid + i * 256;           // 0..2047 float4 slots
        int r = idx >> 4;                  // row 0..127
        int k4 = idx & 15;
        float4 v = reinterpret_cast<const float4*>(Xb + (size_t)r * 256 + chunk * 64)[k4];
        uint2 h = make_uint2(packh(v.x, v.y), packh(v.z, v.w));
        *reinterpret_cast<uint2*>(smc + XC_OFF + r * 144 + k4 * 8) = h;
    }
}

__global__ __launch_bounds__(256, 2) void moe_mma_kernel(
    const float* __restrict__ X,
    const float* __restrict__ shareB,
    const float* __restrict__ expB,
    float* __restrict__ out)
{
    extern __shared__ char smc[];
    const int tid = threadIdx.x;
    const int lane = tid & 31, warp = tid >> 5;
    const int rowBase = blockIdx.y * 128;
    const int colBase = blockIdx.x * 64;
    const uint32_t sb = smem_u32(smc);
    const uint32_t wbase = sb + WS_OFF;

    prefetch_w(wbase, 0, colBase, tid);     // group 0 = stage 0

    float* Sc = reinterpret_cast<float*>(smc + SC_OFF);
    float* Bs = reinterpret_cast<float*>(smc + BS_OFF);

    for (int idx = tid; idx < 17 * 128; idx += 256) {
        int m = idx >> 7, r = idx & 127;
        Sc[idx] = (m == 0) ? 1.0f : g_combine[(size_t)(rowBase + r) * 16 + (m - 1)];
    }
    for (int idx = tid; idx < 17 * 64; idx += 256) {
        int m = idx >> 6, c = idx & 63;
        Bs[idx] = (m == 0) ? shareB[colBase + c] : expB[(m - 1) * 256 + colBase + c];
    }

    prefetch_w(wbase, 1, colBase, tid);     // group 1 = stage 1

    const float* Xb = X + (size_t)rowBase * 256;
    convert_x(smc, Xb, 0, tid);

    // warp tiling: m0 in {0,32,64,96}, n0 in {0,32}
    const int m0 = (warp & 3) * 32;
    const int n0 = (warp >> 2) * 32;

    const uint32_t xh_base = sb + XC_OFF + (uint32_t)(m0 + (lane & 15)) * 144 + (lane >> 4) * 16;
    const uint32_t wb_base = wbase +
        (uint32_t)(n0 + ((lane >> 4) & 1) * 8 + (lane & 7)) * 144 + ((lane >> 3) & 1) * 16;

    const int rq = lane >> 2;
    const int cq = (lane & 3) * 2;

    float acc[2][4][4];
#pragma unroll
    for (int mt = 0; mt < 2; mt++)
#pragma unroll
        for (int nt = 0; nt < 4; nt++)
#pragma unroll
            for (int q = 0; q < 4; q++) acc[mt][nt][q] = 0.f;

    __syncthreads();   // X chunk 0 / Sc / Bs visible

    // acc init = sum_m s_m * b_m
#pragma unroll 1
    for (int m = 0; m < NMAT; m++) {
        float s0 = Sc[m * 128 + m0 + rq];
        float s1 = Sc[m * 128 + m0 + rq + 8];
        float s2 = Sc[m * 128 + m0 + rq + 16];
        float s3 = Sc[m * 128 + m0 + rq + 24];
#pragma unroll
        for (int nt = 0; nt < 4; nt++) {
            float b0 = Bs[m * 64 + n0 + nt * 8 + cq];
            float b1 = Bs[m * 64 + n0 + nt * 8 + cq + 1];
            acc[0][nt][0] += s0 * b0; acc[0][nt][1] += s0 * b1;
            acc[0][nt][2] += s1 * b0; acc[0][nt][3] += s1 * b1;
            acc[1][nt][0] += s2 * b0; acc[1][nt][1] += s2 * b1;
            acc[1][nt][2] += s3 * b0; acc[1][nt][3] += s3 * b1;
        }
    }

    uint32_t Ah[4][2][4];
    float p[2][4][4];

#pragma unroll 1
    for (int t = 0; t < NTASK; t++) {
        const int c = t / 17;
        const int m = t - c * 17;
        const int stage = t % 3;

        asm volatile("cp.async.wait_group 1;" ::: "memory");
        __syncthreads();

        if (m == 0) {
#pragma unroll
            for (int ks = 0; ks < 4; ks++) {
#pragma unroll
                for (int mt = 0; mt < 2; mt++)
                    LDSM4(Ah[ks][mt], xh_base + mt * (16 * 144) + ks * 32);
            }
        }
        if (m == 1 && c < 3) {
            convert_x(smc, Xb, c + 1, tid);
        }

#pragma unroll
        for (int mt = 0; mt < 2; mt++)
#pragma unroll
            for (int nt = 0; nt < 4; nt++)
#pragma unroll
                for (int q = 0; q < 4; q++) p[mt][nt][q] = 0.f;

        const uint32_t wbs = wb_base + stage * 18432;
#pragma unroll
        for (int ks = 0; ks < 4; ks++) {
            uint32_t Bh[4][2], Bl[4][2];
#pragma unroll
            for (int ntp = 0; ntp < 2; ntp++) {
                uint32_t r4[4];
                LDSM4(r4, wbs + ntp * (16 * 144) + ks * 32);
                Bh[ntp * 2][0] = r4[0]; Bh[ntp * 2][1] = r4[1];
                Bh[ntp * 2 + 1][0] = r4[2]; Bh[ntp * 2 + 1][1] = r4[3];
                LDSM4(r4, wbs + 9216 + ntp * (16 * 144) + ks * 32);
                Bl[ntp * 2][0] = r4[0]; Bl[ntp * 2][1] = r4[1];
                Bl[ntp * 2 + 1][0] = r4[2]; Bl[ntp * 2 + 1][1] = r4[3];
            }
#pragma unroll
            for (int mt = 0; mt < 2; mt++)
#pragma unroll
                for (int nt = 0; nt < 4; nt++)
                    MMA16816(p[mt][nt], Ah[ks][mt], Bh[nt]);
#pragma unroll
            for (int mt = 0; mt < 2; mt++)
#pragma unroll
                for (int nt = 0; nt < 4; nt++)
                    MMA16816(p[mt][nt], Ah[ks][mt], Bl[nt]);
        }

        // epilogue: acc += s_row * p
        {
            float s0 = Sc[m * 128 + m0 + rq];
            float s1 = Sc[m * 128 + m0 + rq + 8];
            float s2 = Sc[m * 128 + m0 + rq + 16];
            float s3 = Sc[m * 128 + m0 + rq + 24];
#pragma unroll
            for (int nt = 0; nt < 4; nt++) {
                acc[0][nt][0] += s0 * p[0][nt][0];
                acc[0][nt][1] += s0 * p[0][nt][1];
                acc[0][nt][2] += s1 * p[0][nt][2];
                acc[0][nt][3] += s1 * p[0][nt][3];
                acc[1][nt][0] += s2 * p[1][nt][0];
                acc[1][nt][1] += s2 * p[1][nt][1];
                acc[1][nt][2] += s3 * p[1][nt][2];
                acc[1][nt][3] += s3 * p[1][nt][3];
            }
        }

        if (t + 2 < NTASK) prefetch_w(wbase, t + 2, colBase, tid);
        else asm volatile("cp.async.commit_group;" ::: "memory");
    }

    // write output
#pragma unroll
    for (int mt = 0; mt < 2; mt++) {
        int rg = rowBase + m0 + mt * 16 + rq;
#pragma unroll
        for (int nt = 0; nt < 4; nt++) {
            int cg = colBase + n0 + nt * 8 + cq;
            *reinterpret_cast<float2*>(out + (size_t)rg * 256 + cg) =
                make_float2(acc[mt][nt][0], acc[mt][nt][1]);
            *reinterpret_cast<float2*>(out + (size_t)(rg + 8) * 256 + cg) =
                make_float2(acc[mt][nt][2], acc[mt][nt][3]);
        }
    }
}

// ---------------- kernel 3: loss reduce + finalize ----------------
__global__ __launch_bounds__(256) void finalize_kernel(float* __restrict__ out, int out_size)
{
    __shared__ float rt[16][17], rp[16][17];
    __shared__ float prod[16];
    int tid = threadIdx.x;
    int e = tid & 15, part = tid >> 4;   // 16 parts x 32 blocks
    float t = 0.f, p = 0.f;
    for (int b = part * 32; b < part * 32 + 32; b++) {
        t += g_pt[b * 16 + e];
        p += g_pp[b * 16 + e];
    }
    rt[part][e] = t; rp[part][e] = p;
    __syncthreads();
    if (tid < 16) {
        float ts = 0.f, ps = 0.f;
#pragma unroll
        for (int q = 0; q < 16; q++) { ts += rt[q][tid]; ps += rp[q][tid]; }
        prod[tid] = (ts * (1.f / (float)N_TOK)) * (ps * (1.f / (float)N_TOK));
    }
    __syncthreads();
    const int NC = N_TOK * C_DIM;
    if (tid == 0) {
        float a = 0.f;
#pragma unroll
        for (int q = 0; q < 16; q++) a += prod[q];
        if (out_size > NC) out[NC] = a * 16.f;
    }
    for (int i = NC + 1 + tid; i < out_size; i += 256)
        out[i] = 0.f;
}

// ---------------- launch ----------------
extern "C" void kernel_launch(void* const* d_in, const int* in_sizes, int n_in,
                              void* d_out, int out_size)
{
    const float* inputs = (const float*)d_in[0];
    const float* conv   = (const float*)d_in[1];
    const float* emb    = (const float*)d_in[2];
    const float* shareW = (const float*)d_in[3];
    const float* shareB = (const float*)d_in[4];
    const float* gateW  = (const float*)d_in[5];
    const float* gateB  = (const float*)d_in[6];
    const float* expW   = (const float*)d_in[7];
    const float* expB   = (const float*)d_in[8];
    const float* gamma  = (const float*)d_in[9];
    const float* beta   = (const float*)d_in[10];
    float* out = (float*)d_out;

    prep_kernel<<<RBLK + NMAT * 64, 256>>>(conv, emb, gateW, gateB, gamma, beta,
                                           shareW, expW);

    cudaFuncSetAttribute(moe_mma_kernel,
                         cudaFuncAttributeMaxDynamicSharedMemorySize, SMEM_BYTES);
    moe_mma_kernel<<<dim3(4, 256), 256, SMEM_BYTES>>>(inputs, shareB, expB, out);

    finalize_kernel<<<1, 256>>>(out, out_size);
}

// round 10
// speedup vs baseline: 7.7569x; 1.4817x over previous
#include <cuda_runtime.h>
#include <cuda_fp16.h>
#include <math.h>
#include <stdint.h>

#define N_TOK 32768
#define C_DIM 256
#define E_NUM 16
#define NMAT 17
#define RBLK 512          // router blocks (64 tokens each)
#define NTASK (NMAT * 4)  // 68

// ---------------- scratch (no allocations allowed) ----------------
__device__ float g_combine[N_TOK * E_NUM];
__device__ float g_pt[RBLK * 16];
__device__ float g_pp[RBLK * 16];
__device__ __align__(128) __half g_Whi[NMAT * C_DIM * C_DIM];

__device__ __forceinline__ uint32_t smem_u32(const void* p) {
    uint32_t a;
    asm("{ .reg .u64 t; cvta.to.shared.u64 t, %1; cvt.u32.u64 %0, t; }" : "=r"(a) : "l"(p));
    return a;
}

// ---------------- kernel 1: fused router + W-prep ----------------
__global__ __launch_bounds__(256) void prep_kernel(
    const float* __restrict__ conv, const float* __restrict__ emb,
    const float* __restrict__ gateW, const float* __restrict__ gateB,
    const float* __restrict__ gamma, const float* __restrict__ beta,
    const float* __restrict__ shareW, const float* __restrict__ expW)
{
    int tid = threadIdx.x;

    if (blockIdx.x >= RBLK) {
        // ---- W prep: transpose + fp16 convert ----
        __shared__ float tile[32][33];
        int w = blockIdx.x - RBLK;
        int m = w >> 6;
        int rr = w & 63;
        int by = rr >> 3, bx = rr & 7;
        const float* src = (m == 0) ? shareW : expW + (size_t)(m - 1) * 65536;
        int tx = tid & 31, ty = tid >> 5;
        if (ty < 8) {
#pragma unroll
            for (int i = 0; i < 4; i++) {
                int k = by * 32 + ty + i * 8;
                int n = bx * 32 + tx;
                tile[ty + i * 8][tx] = src[k * 256 + n];
            }
        }
        __syncthreads();
        if (ty < 8) {
#pragma unroll
            for (int i = 0; i < 4; i++) {
                int n = bx * 32 + ty + i * 8;
                int k = by * 32 + tx;
                float v = tile[tx][ty + i * 8];
                g_Whi[(size_t)m * 65536 + (size_t)n * 256 + k] = __float2half_rn(v);
            }
        }
        return;
    }

    // ---- router: 8 warps x 8 tokens (4 pair-passes, 2 tokens/warp-pass) ----
    __shared__ float gwT[16 * 257];
    __shared__ float gbev[3 * 256 + 16];
    __shared__ float wpt[8 * 16], wpp[8 * 16];
    for (int idx = tid; idx < 4096; idx += 256)
        gwT[(idx & 15) * 257 + (idx >> 4)] = gateW[idx];
    if (tid < 256) {
        gbev[tid] = gamma[tid];
        gbev[256 + tid] = beta[tid];
        gbev[512 + tid] = emb[tid];
    }
    if (tid < 16) gbev[768 + tid] = gateB[tid];
    __syncthreads();

    int warp = tid >> 5, lane = tid & 31;
    int half = lane >> 4;
    int sl = lane & 15;
    float st = 0.f, sp = 0.f;

#pragma unroll 1
    for (int i = 0; i < 4; i++) {
        int n = blockIdx.x * 64 + warp * 8 + i * 2 + half;
        const float* row = conv + (size_t)n * C_DIM;

        float x[16];
        float s = 0.f, s2 = 0.f;
#pragma unroll
        for (int j = 0; j < 16; j++) {
            x[j] = row[sl + 16 * j];
            s += x[j]; s2 += x[j] * x[j];
        }
#pragma unroll
        for (int o = 8; o; o >>= 1) {
            s  += __shfl_xor_sync(0xffffffffu, s,  o);
            s2 += __shfl_xor_sync(0xffffffffu, s2, o);
        }
        float mu = s * (1.f / 256.f);
        float var = s2 * (1.f / 256.f) - mu * mu;
        float rstd = rsqrtf(var + 1e-5f);

        float r[16];
#pragma unroll
        for (int j = 0; j < 16; j++) {
            int c = sl + 16 * j;
            r[j] = (x[j] - mu) * rstd * gbev[c] + gbev[256 + c] + gbev[512 + c];
        }

        float w[16];
#pragma unroll
        for (int e = 0; e < 16; e++) {
            float p = 0.f;
#pragma unroll
            for (int j = 0; j < 16; j++) p += r[j] * gwT[e * 257 + sl + 16 * j];
#pragma unroll
            for (int o = 8; o; o >>= 1) p += __shfl_xor_sync(0xffffffffu, p, o);
            w[e] = p + gbev[768 + e];
        }

        float mx = w[0];
#pragma unroll
        for (int e = 1; e < 16; e++) mx = fmaxf(mx, w[e]);
        float sum = 0.f;
#pragma unroll
        for (int e = 0; e < 16; e++) { w[e] = expf(w[e] - mx); sum += w[e]; }
        float inv = 1.f / sum;
        float ent = 0.f;
#pragma unroll
        for (int e = 0; e < 16; e++) { w[e] *= inv; ent -= w[e] * logf(w[e] + 1e-12f); }
        float kf = ceilf(1.f + ent * (15.f / 2.7725887222397811f));
        int k = (int)kf; k = k < 1 ? 1 : (k > 16 ? 16 : k);

        float we = w[sl];
        int rank = 0;
#pragma unroll
        for (int j = 0; j < 16; j++)
            rank += (w[j] > we) || (w[j] == we && j < sl);
        int sel = rank < k;
        g_combine[(size_t)n * 16 + sl] = sel ? we : 0.f;
        st += sel ? 1.f : 0.f;
        sp += we;
    }

    st += __shfl_xor_sync(0xffffffffu, st, 16);
    sp += __shfl_xor_sync(0xffffffffu, sp, 16);
    if (lane < 16) { wpt[warp * 16 + lane] = st; wpp[warp * 16 + lane] = sp; }
    __syncthreads();
    if (tid < 16) {
        float t = 0.f, p = 0.f;
#pragma unroll
        for (int w = 0; w < 8; w++) { t += wpt[w * 16 + tid]; p += wpp[w * 16 + tid]; }
        g_pt[blockIdx.x * 16 + tid] = t;
        g_pp[blockIdx.x * 16 + tid] = p;
    }
}

// ---------------- kernel 2: mma.sync fused MoE GEMM v8 (1-term fp16) ----------------
// CTA 128(M) x 64(N), 256 threads (8 warps 4x2, warp 32x32), 2 CTAs/SM.
#define WS_OFF 0            // 3 stages x 9216 (64 rows x 144B)
#define XC_OFF 27648        // current X chunk (fp16): 128 rows x 144B = 18432
#define SC_OFF 46080        // [17][128] f32 = 8704
#define BS_OFF 54784        // [17][64] f32 = 4352
#define SMEM_BYTES 59136

#define LDSM4(R, A) \
    asm volatile("ldmatrix.sync.aligned.m8n8.x4.shared.b16 {%0,%1,%2,%3}, [%4];" \
        : "=r"((R)[0]), "=r"((R)[1]), "=r"((R)[2]), "=r"((R)[3]) : "r"(A))
#define MMA16816(D, A, B) \
    asm volatile("mma.sync.aligned.m16n8k16.row.col.f32.f16.f16.f32 " \
        "{%0,%1,%2,%3}, {%4,%5,%6,%7}, {%8,%9}, {%0,%1,%2,%3};" \
        : "+f"((D)[0]), "+f"((D)[1]), "+f"((D)[2]), "+f"((D)[3]) \
        : "r"((A)[0]), "r"((A)[1]), "r"((A)[2]), "r"((A)[3]), "r"((B)[0]), "r"((B)[1]))

__device__ __forceinline__ uint32_t packh(float a, float b) {
    __half2 h = __floats2half2_rn(a, b);
    return *reinterpret_cast<uint32_t*>(&h);
}

// prefetch W for task t (c = t/17, m = t%17) into ring stage t%3
__device__ __forceinline__ void prefetch_w(uint32_t wbase, int t, int colBase, int tid)
{
    const int c = t / 17;
    const int m = t - c * 17;
    const int stage = t % 3;
#pragma unroll
    for (int i = 0; i < 2; i++) {
        int idx = tid + i * 256;           // 0..511
        int r = idx >> 3;                  // n row 0..63
        int q = idx & 7;                   // 16B segment along k
        const __half* src = g_Whi +
            (size_t)m * 65536 + (size_t)(colBase + r) * 256 + c * 64 + q * 8;
        uint32_t dst = wbase + stage * 9216 + r * 144 + q * 16;
        asm volatile("cp.async.cg.shared.global [%0], [%1], 16;"
                     :: "r"(dst), "l"(src) : "memory");
    }
    asm volatile("cp.async.commit_group;" ::: "memory");
}

// convert X chunk (128 rows x 64 k) from gmem to fp16 into XC buffer
__device__ __forceinline__ void convert_x(char* smc, const float* Xb, int chunk, int tid)
{
#pragma unroll
    for (int i = 0; i < 8; i++) {
        int idx = tid + i * 256;           // 0..2047 float4 slots
        int r = idx >> 4;                  // row 0..127
        int k4 = idx & 15;
        float4 v = reinterpret_cast<const float4*>(Xb + (size_t)r * 256 + chunk * 64)[k4];
        uint2 h = make_uint2(packh(v.x, v.y), packh(v.z, v.w));
        *reinterpret_cast<uint2*>(smc + XC_OFF + r * 144 + k4 * 8) = h;
    }
}

__global__ __launch_bounds__(256, 2) void moe_mma_kernel(
    const float* __restrict__ X,
    const float* __restrict__ shareB,
    const float* __restrict__ expB,
    float* __restrict__ out)
{
    extern __shared__ char smc[];
    const int tid = threadIdx.x;
    const int lane = tid & 31, warp = tid >> 5;
    const int rowBase = blockIdx.y * 128;
    const int colBase = blockIdx.x * 64;
    const uint32_t sb = smem_u32(smc);
    const uint32_t wbase = sb + WS_OFF;

    prefetch_w(wbase, 0, colBase, tid);

    float* Sc = reinterpret_cast<float*>(smc + SC_OFF);
    float* Bs = reinterpret_cast<float*>(smc + BS_OFF);

    for (int idx = tid; idx < 17 * 128; idx += 256) {
        int m = idx >> 7, r = idx & 127;
        Sc[idx] = (m == 0) ? 1.0f : g_combine[(size_t)(rowBase + r) * 16 + (m - 1)];
    }
    for (int idx = tid; idx < 17 * 64; idx += 256) {
        int m = idx >> 6, c = idx & 63;
        Bs[idx] = (m == 0) ? shareB[colBase + c] : expB[(m - 1) * 256 + colBase + c];
    }

    prefetch_w(wbase, 1, colBase, tid);

    const float* Xb = X + (size_t)rowBase * 256;
    convert_x(smc, Xb, 0, tid);

    // warp tiling: m0 in {0,32,64,96}, n0 in {0,32}
    const int m0 = (warp & 3) * 32;
    const int n0 = (warp >> 2) * 32;

    const uint32_t xh_base = sb + XC_OFF + (uint32_t)(m0 + (lane & 15)) * 144 + (lane >> 4) * 16;
    const uint32_t wb_base = wbase +
        (uint32_t)(n0 + ((lane >> 4) & 1) * 8 + (lane & 7)) * 144 + ((lane >> 3) & 1) * 16;

    const int rq = lane >> 2;
    const int cq = (lane & 3) * 2;

    float acc[2][4][4];
#pragma unroll
    for (int mt = 0; mt < 2; mt++)
#pragma unroll
        for (int nt = 0; nt < 4; nt++)
#pragma unroll
            for (int q = 0; q < 4; q++) acc[mt][nt][q] = 0.f;

    __syncthreads();   // X chunk 0 / Sc / Bs visible

    // acc init = sum_m s_m * b_m
#pragma unroll 1
    for (int m = 0; m < NMAT; m++) {
        float s0 = Sc[m * 128 + m0 + rq];
        float s1 = Sc[m * 128 + m0 + rq + 8];
        float s2 = Sc[m * 128 + m0 + rq + 16];
        float s3 = Sc[m * 128 + m0 + rq + 24];
#pragma unroll
        for (int nt = 0; nt < 4; nt++) {
            float b0 = Bs[m * 64 + n0 + nt * 8 + cq];
            float b1 = Bs[m * 64 + n0 + nt * 8 + cq + 1];
            acc[0][nt][0] += s0 * b0; acc[0][nt][1] += s0 * b1;
            acc[0][nt][2] += s1 * b0; acc[0][nt][3] += s1 * b1;
            acc[1][nt][0] += s2 * b0; acc[1][nt][1] += s2 * b1;
            acc[1][nt][2] += s3 * b0; acc[1][nt][3] += s3 * b1;
        }
    }

    uint32_t Ah[4][2][4];
    float p[2][4][4];

#pragma unroll 1
    for (int t = 0; t < NTASK; t++) {
        const int c = t / 17;
        const int m = t - c * 17;
        const int stage = t % 3;

        asm volatile("cp.async.wait_group 1;" ::: "memory");
        __syncthreads();

        if (m == 0) {
#pragma unroll
            for (int ks = 0; ks < 4; ks++) {
#pragma unroll
                for (int mt = 0; mt < 2; mt++)
                    LDSM4(Ah[ks][mt], xh_base + mt * (16 * 144) + ks * 32);
            }
        }
        if (m == 1 && c < 3) {
            convert_x(smc, Xb, c + 1, tid);
        }

#pragma unroll
        for (int mt = 0; mt < 2; mt++)
#pragma unroll
            for (int nt = 0; nt < 4; nt++)
#pragma unroll
                for (int q = 0; q < 4; q++) p[mt][nt][q] = 0.f;

        const uint32_t wbs = wb_base + stage * 9216;
#pragma unroll
        for (int ks = 0; ks < 4; ks++) {
            uint32_t Bh[4][2];
#pragma unroll
            for (int ntp = 0; ntp < 2; ntp++) {
                uint32_t r4[4];
                LDSM4(r4, wbs + ntp * (16 * 144) + ks * 32);
                Bh[ntp * 2][0] = r4[0]; Bh[ntp * 2][1] = r4[1];
                Bh[ntp * 2 + 1][0] = r4[2]; Bh[ntp * 2 + 1][1] = r4[3];
            }
#pragma unroll
            for (int mt = 0; mt < 2; mt++)
#pragma unroll
                for (int nt = 0; nt < 4; nt++)
                    MMA16816(p[mt][nt], Ah[ks][mt], Bh[nt]);
        }

        // epilogue: acc += s_row * p
        {
            float s0 = Sc[m * 128 + m0 + rq];
            float s1 = Sc[m * 128 + m0 + rq + 8];
            float s2 = Sc[m * 128 + m0 + rq + 16];
            float s3 = Sc[m * 128 + m0 + rq + 24];
#pragma unroll
            for (int nt = 0; nt < 4; nt++) {
                acc[0][nt][0] += s0 * p[0][nt][0];
                acc[0][nt][1] += s0 * p[0][nt][1];
                acc[0][nt][2] += s1 * p[0][nt][2];
                acc[0][nt][3] += s1 * p[0][nt][3];
                acc[1][nt][0] += s2 * p[1][nt][0];
                acc[1][nt][1] += s2 * p[1][nt][1];
                acc[1][nt][2] += s3 * p[1][nt][2];
                acc[1][nt][3] += s3 * p[1][nt][3];
            }
        }

        if (t + 2 < NTASK) prefetch_w(wbase, t + 2, colBase, tid);
        else asm volatile("cp.async.commit_group;" ::: "memory");
    }

    // write output
#pragma unroll
    for (int mt = 0; mt < 2; mt++) {
        int rg = rowBase + m0 + mt * 16 + rq;
#pragma unroll
        for (int nt = 0; nt < 4; nt++) {
            int cg = colBase + n0 + nt * 8 + cq;
            *reinterpret_cast<float2*>(out + (size_t)rg * 256 + cg) =
                make_float2(acc[mt][nt][0], acc[mt][nt][1]);
            *reinterpret_cast<float2*>(out + (size_t)(rg + 8) * 256 + cg) =
                make_float2(acc[mt][nt][2], acc[mt][nt][3]);
        }
    }
}

// ---------------- kernel 3: loss reduce + finalize ----------------
__global__ __launch_bounds__(256) void finalize_kernel(float* __restrict__ out, int out_size)
{
    __shared__ float rt[16][17], rp[16][17];
    __shared__ float prod[16];
    int tid = threadIdx.x;
    int e = tid & 15, part = tid >> 4;   // 16 parts x 32 blocks
    float t = 0.f, p = 0.f;
    for (int b = part * 32; b < part * 32 + 32; b++) {
        t += g_pt[b * 16 + e];
        p += g_pp[b * 16 + e];
    }
    rt[part][e] = t; rp[part][e] = p;
    __syncthreads();
    if (tid < 16) {
        float ts = 0.f, ps = 0.f;
#pragma unroll
        for (int q = 0; q < 16; q++) { ts += rt[q][tid]; ps += rp[q][tid]; }
        prod[tid] = (ts * (1.f / (float)N_TOK)) * (ps * (1.f / (float)N_TOK));
    }
    __syncthreads();
    const int NC = N_TOK * C_DIM;
    if (tid == 0) {
        float a = 0.f;
#pragma unroll
        for (int q = 0; q < 16; q++) a += prod[q];
        if (out_size > NC) out[NC] = a * 16.f;
    }
    for (int i = NC + 1 + tid; i < out_size; i += 256)
        out[i] = 0.f;
}

// ---------------- launch ----------------
extern "C" void kernel_launch(void* const* d_in, const int* in_sizes, int n_in,
                              void* d_out, int out_size)
{
    const float* inputs = (const float*)d_in[0];
    const float* conv   = (const float*)d_in[1];
    const float* emb    = (const float*)d_in[2];
    const float* shareW = (const float*)d_in[3];
    const float* shareB = (const float*)d_in[4];
    const float* gateW  = (const float*)d_in[5];
    const float* gateB  = (const float*)d_in[6];
    const float* expW   = (const float*)d_in[7];
    const float* expB   = (const float*)d_in[8];
    const float* gamma  = (const float*)d_in[9];
    const float* beta   = (const float*)d_in[10];
    float* out = (float*)d_out;

    prep_kernel<<<RBLK + NMAT * 64, 256>>>(conv, emb, gateW, gateB, gamma, beta,
                                           shareW, expW);

    cudaFuncSetAttribute(moe_mma_kernel,
                         cudaFuncAttributeMaxDynamicSharedMemorySize, SMEM_BYTES);
    moe_mma_kernel<<<dim3(4, 256), 256, SMEM_BYTES>>>(inputs, shareB, expB, out);

    finalize_kernel<<<1, 256>>>(out, out_size);
}

// round 11
// speedup vs baseline: 8.2940x; 1.0692x over previous
#include <cuda_runtime.h>
#include <cuda_fp16.h>
#include <math.h>
#include <stdint.h>

#define N_TOK 32768
#define C_DIM 256
#define E_NUM 16
#define NMAT 17
#define RBLK 512          // router blocks (64 tokens each)
#define NTASK (NMAT * 4)  // 68

// ---------------- scratch (no allocations allowed) ----------------
__device__ float g_combine[N_TOK * E_NUM];
__device__ float g_pt[RBLK * 16];
__device__ float g_pp[RBLK * 16];
__device__ __align__(128) __half g_Whi[NMAT * C_DIM * C_DIM];

__device__ __forceinline__ uint32_t smem_u32(const void* p) {
    uint32_t a;
    asm("{ .reg .u64 t; cvta.to.shared.u64 t, %1; cvt.u32.u64 %0, t; }" : "=r"(a) : "l"(p));
    return a;
}

// ---------------- kernel 1: fused router + W-prep ----------------
__global__ __launch_bounds__(256) void prep_kernel(
    const float* __restrict__ conv, const float* __restrict__ emb,
    const float* __restrict__ gateW, const float* __restrict__ gateB,
    const float* __restrict__ gamma, const float* __restrict__ beta,
    const float* __restrict__ shareW, const float* __restrict__ expW)
{
    int tid = threadIdx.x;

    if (blockIdx.x >= RBLK) {
        // ---- W prep: transpose + fp16 convert ----
        __shared__ float tile[32][33];
        int w = blockIdx.x - RBLK;
        int m = w >> 6;
        int rr = w & 63;
        int by = rr >> 3, bx = rr & 7;
        const float* src = (m == 0) ? shareW : expW + (size_t)(m - 1) * 65536;
        int tx = tid & 31, ty = tid >> 5;
        if (ty < 8) {
#pragma unroll
            for (int i = 0; i < 4; i++) {
                int k = by * 32 + ty + i * 8;
                int n = bx * 32 + tx;
                tile[ty + i * 8][tx] = src[k * 256 + n];
            }
        }
        __syncthreads();
        if (ty < 8) {
#pragma unroll
            for (int i = 0; i < 4; i++) {
                int n = bx * 32 + ty + i * 8;
                int k = by * 32 + tx;
                float v = tile[tx][ty + i * 8];
                g_Whi[(size_t)m * 65536 + (size_t)n * 256 + k] = __float2half_rn(v);
            }
        }
        return;
    }

    // ---- router: 8 warps x 8 tokens (4 pair-passes, 2 tokens/warp-pass) ----
    __shared__ float gwT[16 * 257];
    __shared__ float gbev[3 * 256 + 16];
    __shared__ float wpt[8 * 16], wpp[8 * 16];
    for (int idx = tid; idx < 4096; idx += 256)
        gwT[(idx & 15) * 257 + (idx >> 4)] = gateW[idx];
    if (tid < 256) {
        gbev[tid] = gamma[tid];
        gbev[256 + tid] = beta[tid];
        gbev[512 + tid] = emb[tid];
    }
    if (tid < 16) gbev[768 + tid] = gateB[tid];
    __syncthreads();

    int warp = tid >> 5, lane = tid & 31;
    int half = lane >> 4;
    int sl = lane & 15;
    float st = 0.f, sp = 0.f;

#pragma unroll 1
    for (int i = 0; i < 4; i++) {
        int n = blockIdx.x * 64 + warp * 8 + i * 2 + half;
        const float* row = conv + (size_t)n * C_DIM;

        float x[16];
        float s = 0.f, s2 = 0.f;
#pragma unroll
        for (int j = 0; j < 16; j++) {
            x[j] = row[sl + 16 * j];
            s += x[j]; s2 += x[j] * x[j];
        }
#pragma unroll
        for (int o = 8; o; o >>= 1) {
            s  += __shfl_xor_sync(0xffffffffu, s,  o);
            s2 += __shfl_xor_sync(0xffffffffu, s2, o);
        }
        float mu = s * (1.f / 256.f);
        float var = s2 * (1.f / 256.f) - mu * mu;
        float rstd = rsqrtf(var + 1e-5f);

        float r[16];
#pragma unroll
        for (int j = 0; j < 16; j++) {
            int c = sl + 16 * j;
            r[j] = (x[j] - mu) * rstd * gbev[c] + gbev[256 + c] + gbev[512 + c];
        }

        // per-lane partial dot products for all 16 experts
        float v[16];
#pragma unroll
        for (int e = 0; e < 16; e++) {
            float p = 0.f;
#pragma unroll
            for (int j = 0; j < 16; j++) p += r[j] * gwT[e * 257 + sl + 16 * j];
            v[e] = p;
        }

        // butterfly fold: lane sl ends with logit of expert sl (15 shfls)
        {
            bool hi = (sl & 8) != 0;
#pragma unroll
            for (int j = 0; j < 8; j++) {
                float keep = hi ? v[j + 8] : v[j];
                float send = hi ? v[j] : v[j + 8];
                v[j] = keep + __shfl_xor_sync(0xffffffffu, send, 8);
            }
        }
        {
            bool hi = (sl & 4) != 0;
#pragma unroll
            for (int j = 0; j < 4; j++) {
                float keep = hi ? v[j + 4] : v[j];
                float send = hi ? v[j] : v[j + 4];
                v[j] = keep + __shfl_xor_sync(0xffffffffu, send, 4);
            }
        }
        {
            bool hi = (sl & 2) != 0;
#pragma unroll
            for (int j = 0; j < 2; j++) {
                float keep = hi ? v[j + 2] : v[j];
                float send = hi ? v[j] : v[j + 2];
                v[j] = keep + __shfl_xor_sync(0xffffffffu, send, 2);
            }
        }
        {
            bool hi = (sl & 1) != 0;
            float keep = hi ? v[1] : v[0];
            float send = hi ? v[0] : v[1];
            v[0] = keep + __shfl_xor_sync(0xffffffffu, send, 1);
        }
        float L = v[0] + gbev[768 + sl];   // logit of expert sl

        // all-gather: a[i] = logit of expert (sl ^ i)  (15 shfls)
        float a[16];
        a[0] = L;
        a[1] = __shfl_xor_sync(0xffffffffu, a[0], 1);
#pragma unroll
        for (int q = 0; q < 2; q++) a[2 + q] = __shfl_xor_sync(0xffffffffu, a[q], 2);
#pragma unroll
        for (int q = 0; q < 4; q++) a[4 + q] = __shfl_xor_sync(0xffffffffu, a[q], 4);
#pragma unroll
        for (int q = 0; q < 8; q++) a[8 + q] = __shfl_xor_sync(0xffffffffu, a[q], 8);

        // softmax / entropy / dynamic k (redundant per lane, all in regs)
        float mx = a[0];
#pragma unroll
        for (int e = 1; e < 16; e++) mx = fmaxf(mx, a[e]);
        float sum = 0.f;
#pragma unroll
        for (int e = 0; e < 16; e++) { a[e] = expf(a[e] - mx); sum += a[e]; }
        float inv = 1.f / sum;
        float ent = 0.f;
#pragma unroll
        for (int e = 0; e < 16; e++) { a[e] *= inv; ent -= a[e] * logf(a[e] + 1e-12f); }
        float kf = ceilf(1.f + ent * (15.f / 2.7725887222397811f));
        int k = (int)kf; k = k < 1 ? 1 : (k > 16 ? 16 : k);

        // rank of expert sl (w value a[0]) vs expert sl^i (a[i]), stable by expert idx
        float we = a[0];
        int rank = 0;
#pragma unroll
        for (int j = 1; j < 16; j++) {
            int ej = sl ^ j;
            rank += (a[j] > we) || (a[j] == we && ej < sl);
        }
        int sel = rank < k;
        g_combine[(size_t)n * 16 + sl] = sel ? we : 0.f;
        st += sel ? 1.f : 0.f;
        sp += we;
    }

    st += __shfl_xor_sync(0xffffffffu, st, 16);
    sp += __shfl_xor_sync(0xffffffffu, sp, 16);
    if (lane < 16) { wpt[warp * 16 + lane] = st; wpp[warp * 16 + lane] = sp; }
    __syncthreads();
    if (tid < 16) {
        float t = 0.f, p = 0.f;
#pragma unroll
        for (int w = 0; w < 8; w++) { t += wpt[w * 16 + tid]; p += wpp[w * 16 + tid]; }
        g_pt[blockIdx.x * 16 + tid] = t;
        g_pp[blockIdx.x * 16 + tid] = p;
    }
}

// ---------------- kernel 2: mma.sync fused MoE GEMM v9 ----------------
// CTA 128(M) x 64(N), 256 threads (8 warps 4x2, warp 32x32), 2 CTAs/SM.
// A fragments pre-scaled by combine (HMUL2); all MMAs accumulate into acc.
#define WS_OFF 0            // 3 stages x 9216 (64 rows x 144B)
#define XC_OFF 27648        // current X chunk (fp16): 128 rows x 144B = 18432
#define SC_OFF 46080        // [17][64] half2 pairs (s_r, s_r+8) = 4352
#define BS_OFF 50432        // [17][64] f32 = 4352
#define SMEM_BYTES 54784

#define LDSM4(R, A) \
    asm volatile("ldmatrix.sync.aligned.m8n8.x4.shared.b16 {%0,%1,%2,%3}, [%4];" \
        : "=r"((R)[0]), "=r"((R)[1]), "=r"((R)[2]), "=r"((R)[3]) : "r"(A))
#define MMA16816(D, A, B) \
    asm volatile("mma.sync.aligned.m16n8k16.row.col.f32.f16.f16.f32 " \
        "{%0,%1,%2,%3}, {%4,%5,%6,%7}, {%8,%9}, {%0,%1,%2,%3};" \
        : "+f"((D)[0]), "+f"((D)[1]), "+f"((D)[2]), "+f"((D)[3]) \
        : "r"((A)[0]), "r"((A)[1]), "r"((A)[2]), "r"((A)[3]), "r"((B)[0]), "r"((B)[1]))

__device__ __forceinline__ uint32_t packh(float a, float b) {
    __half2 h = __floats2half2_rn(a, b);
    return *reinterpret_cast<uint32_t*>(&h);
}
__device__ __forceinline__ uint32_t hmul2u(uint32_t a, uint32_t b) {
    __half2 r = __hmul2(*reinterpret_cast<__half2*>(&a), *reinterpret_cast<__half2*>(&b));
    return *reinterpret_cast<uint32_t*>(&r);
}

// prefetch W for task t (c = t/17, m = t%17) into ring stage t%3
__device__ __forceinline__ void prefetch_w(uint32_t wbase, int t, int colBase, int tid)
{
    const int c = t / 17;
    const int m = t - c * 17;
    const int stage = t % 3;
#pragma unroll
    for (int i = 0; i < 2; i++) {
        int idx = tid + i * 256;           // 0..511
        int r = idx >> 3;                  // n row 0..63
        int q = idx & 7;                   // 16B segment along k
        const __half* src = g_Whi +
            (size_t)m * 65536 + (size_t)(colBase + r) * 256 + c * 64 + q * 8;
        uint32_t dst = wbase + stage * 9216 + r * 144 + q * 16;
        asm volatile("cp.async.cg.shared.global [%0], [%1], 16;"
                     :: "r"(dst), "l"(src) : "memory");
    }
    asm volatile("cp.async.commit_group;" ::: "memory");
}

// convert X chunk (128 rows x 64 k) from gmem to fp16 into XC buffer
__device__ __forceinline__ void convert_x(char* smc, const float* Xb, int chunk, int tid)
{
#pragma unroll
    for (int i = 0; i < 8; i++) {
        int idx = tid + i * 256;           // 0..2047 float4 slots
        int r = idx >> 4;                  // row 0..127
        int k4 = idx & 15;
        float4 v = reinterpret_cast<const float4*>(Xb + (size_t)r * 256 + chunk * 64)[k4];
        uint2 h = make_uint2(packh(v.x, v.y), packh(v.z, v.w));
        *reinterpret_cast<uint2*>(smc + XC_OFF + r * 144 + k4 * 8) = h;
    }
}

__global__ __launch_bounds__(256, 2) void moe_mma_kernel(
    const float* __restrict__ X,
    const float* __restrict__ shareB,
    const float* __restrict__ expB,
    float* __restrict__ out)
{
    extern __shared__ char smc[];
    const int tid = threadIdx.x;
    const int lane = tid & 31, warp = tid >> 5;
    const int rowBase = blockIdx.y * 128;
    const int colBase = blockIdx.x * 64;
    const uint32_t sb = smem_u32(smc);
    const uint32_t wbase = sb + WS_OFF;

    prefetch_w(wbase, 0, colBase, tid);

    __half2* Sc2 = reinterpret_cast<__half2*>(smc + SC_OFF);
    float* Bs = reinterpret_cast<float*>(smc + BS_OFF);

    // stage paired scales: Sc2[m][j] = (s(row), s(row+8)), row = (j>>3)*16 + (j&7)
    for (int idx = tid; idx < 17 * 64; idx += 256) {
        int m = idx >> 6, j = idx & 63;
        int row = ((j >> 3) << 4) + (j & 7);
        float f0, f1;
        if (m == 0) { f0 = 1.0f; f1 = 1.0f; }
        else {
            f0 = g_combine[(size_t)(rowBase + row) * 16 + (m - 1)];
            f1 = g_combine[(size_t)(rowBase + row + 8) * 16 + (m - 1)];
        }
        Sc2[idx] = __floats2half2_rn(f0, f1);
    }
    for (int idx = tid; idx < 17 * 64; idx += 256) {
        int m = idx >> 6, c = idx & 63;
        Bs[idx] = (m == 0) ? shareB[colBase + c] : expB[(m - 1) * 256 + colBase + c];
    }

    prefetch_w(wbase, 1, colBase, tid);

    const float* Xb = X + (size_t)rowBase * 256;
    convert_x(smc, Xb, 0, tid);

    // warp tiling: m0 in {0,32,64,96}, n0 in {0,32}
    const int m0 = (warp & 3) * 32;
    const int n0 = (warp >> 2) * 32;

    const uint32_t xh_base = sb + XC_OFF + (uint32_t)(m0 + (lane & 15)) * 144 + (lane >> 4) * 16;
    const uint32_t wb_base = wbase +
        (uint32_t)(n0 + ((lane >> 4) & 1) * 8 + (lane & 7)) * 144 + ((lane >> 3) & 1) * 16;

    const int rq = lane >> 2;
    const int cq = (lane & 3) * 2;
    const int scBase = (warp & 3) * 16 + rq;   // j index of (m0+rq, m0+rq+8) pair

    float acc[2][4][4];
#pragma unroll
    for (int mt = 0; mt < 2; mt++)
#pragma unroll
        for (int nt = 0; nt < 4; nt++)
#pragma unroll
            for (int q = 0; q < 4; q++) acc[mt][nt][q] = 0.f;

    __syncthreads();   // X chunk 0 / Sc2 / Bs visible

    // acc init = sum_m s_m * b_m (using the same fp16-rounded scales)
#pragma unroll 1
    for (int m = 0; m < NMAT; m++) {
        float2 fa = __half22float2(Sc2[m * 64 + scBase]);
        float2 fb = __half22float2(Sc2[m * 64 + scBase + 8]);
#pragma unroll
        for (int nt = 0; nt < 4; nt++) {
            float b0 = Bs[m * 64 + n0 + nt * 8 + cq];
            float b1 = Bs[m * 64 + n0 + nt * 8 + cq + 1];
            acc[0][nt][0] += fa.x * b0; acc[0][nt][1] += fa.x * b1;
            acc[0][nt][2] += fa.y * b0; acc[0][nt][3] += fa.y * b1;
            acc[1][nt][0] += fb.x * b0; acc[1][nt][1] += fb.x * b1;
            acc[1][nt][2] += fb.y * b0; acc[1][nt][3] += fb.y * b1;
        }
    }

    uint32_t Ah[4][2][4];

#pragma unroll 1
    for (int t = 0; t < NTASK; t++) {
        const int c = t / 17;
        const int m = t - c * 17;
        const int stage = t % 3;

        asm volatile("cp.async.wait_group 1;" ::: "memory");
        __syncthreads();

        if (m == 0) {
#pragma unroll
            for (int ks = 0; ks < 4; ks++) {
#pragma unroll
                for (int mt = 0; mt < 2; mt++)
                    LDSM4(Ah[ks][mt], xh_base + mt * (16 * 144) + ks * 32);
            }
        }
        if (m == 1 && c < 3) {
            convert_x(smc, Xb, c + 1, tid);
        }

        // per-matrix row scales (fp16, broadcast to both halves)
        __half2 h2a = Sc2[m * 64 + scBase];
        __half2 h2b = Sc2[m * 64 + scBase + 8];
        uint32_t sA0, sA1, sB0, sB1;
        {
            __half2 t0 = __half2half2(__low2half(h2a));
            __half2 t1 = __half2half2(__high2half(h2a));
            __half2 t2 = __half2half2(__low2half(h2b));
            __half2 t3 = __half2half2(__high2half(h2b));
            sA0 = *reinterpret_cast<uint32_t*>(&t0);
            sA1 = *reinterpret_cast<uint32_t*>(&t1);
            sB0 = *reinterpret_cast<uint32_t*>(&t2);
            sB1 = *reinterpret_cast<uint32_t*>(&t3);
        }

        const uint32_t wbs = wb_base + stage * 9216;
#pragma unroll
        for (int ks = 0; ks < 4; ks++) {
            uint32_t Bh[4][2];
#pragma unroll
            for (int ntp = 0; ntp < 2; ntp++) {
                uint32_t r4[4];
                LDSM4(r4, wbs + ntp * (16 * 144) + ks * 32);
                Bh[ntp * 2][0] = r4[0]; Bh[ntp * 2][1] = r4[1];
                Bh[ntp * 2 + 1][0] = r4[2]; Bh[ntp * 2 + 1][1] = r4[3];
            }
            uint32_t As[4];
            // mt = 0: rows m0+rq (regs 0,2) and m0+rq+8 (regs 1,3)
            As[0] = hmul2u(Ah[ks][0][0], sA0);
            As[1] = hmul2u(Ah[ks][0][1], sA1);
            As[2] = hmul2u(Ah[ks][0][2], sA0);
            As[3] = hmul2u(Ah[ks][0][3], sA1);
#pragma unroll
            for (int nt = 0; nt < 4; nt++)
                MMA16816(acc[0][nt], As, Bh[nt]);
            // mt = 1: rows m0+16+rq and m0+24+rq
            As[0] = hmul2u(Ah[ks][1][0], sB0);
            As[1] = hmul2u(Ah[ks][1][1], sB1);
            As[2] = hmul2u(Ah[ks][1][2], sB0);
            As[3] = hmul2u(Ah[ks][1][3], sB1);
#pragma unroll
            for (int nt = 0; nt < 4; nt++)
                MMA16816(acc[1][nt], As, Bh[nt]);
        }

        if (t + 2 < NTASK) prefetch_w(wbase, t + 2, colBase, tid);
        else asm volatile("cp.async.commit_group;" ::: "memory");
    }

    // write output
#pragma unroll
    for (int mt = 0; mt < 2; mt++) {
        int rg = rowBase + m0 + mt * 16 + rq;
#pragma unroll
        for (int nt = 0; nt < 4; nt++) {
            int cg = colBase + n0 + nt * 8 + cq;
            *reinterpret_cast<float2*>(out + (size_t)rg * 256 + cg) =
                make_float2(acc[mt][nt][0], acc[mt][nt][1]);
            *reinterpret_cast<float2*>(out + (size_t)(rg + 8) * 256 + cg) =
                make_float2(acc[mt][nt][2], acc[mt][nt][3]);
        }
    }
}

// ---------------- kernel 3: loss reduce + finalize ----------------
__global__ __launch_bounds__(256) void finalize_kernel(float* __restrict__ out, int out_size)
{
    __shared__ float rt[16][17], rp[16][17];
    __shared__ float prod[16];
    int tid = threadIdx.x;
    int e = tid & 15, part = tid >> 4;   // 16 parts x 32 blocks
    float t = 0.f, p = 0.f;
    for (int b = part * 32; b < part * 32 + 32; b++) {
        t += g_pt[b * 16 + e];
        p += g_pp[b * 16 + e];
    }
    rt[part][e] = t; rp[part][e] = p;
    __syncthreads();
    if (tid < 16) {
        float ts = 0.f, ps = 0.f;
#pragma unroll
        for (int q = 0; q < 16; q++) { ts += rt[q][tid]; ps += rp[q][tid]; }
        prod[tid] = (ts * (1.f / (float)N_TOK)) * (ps * (1.f / (float)N_TOK));
    }
    __syncthreads();
    const int NC = N_TOK * C_DIM;
    if (tid == 0) {
        float a = 0.f;
#pragma unroll
        for (int q = 0; q < 16; q++) a += prod[q];
        if (out_size > NC) out[NC] = a * 16.f;
    }
    for (int i = NC + 1 + tid; i < out_size; i += 256)
        out[i] = 0.f;
}

// ---------------- launch ----------------
extern "C" void kernel_launch(void* const* d_in, const int* in_sizes, int n_in,
                              void* d_out, int out_size)
{
    const float* inputs = (const float*)d_in[0];
    const float* conv   = (const float*)d_in[1];
    const float* emb    = (const float*)d_in[2];
    const float* shareW = (const float*)d_in[3];
    const float* shareB = (const float*)d_in[4];
    const float* gateW  = (const float*)d_in[5];
    const float* gateB  = (const float*)d_in[6];
    const float* expW   = (const float*)d_in[7];
    const float* expB   = (const float*)d_in[8];
    const float* gamma  = (const float*)d_in[9];
    const float* beta   = (const float*)d_in[10];
    float* out = (float*)d_out;

    prep_kernel<<<RBLK + NMAT * 64, 256>>>(conv, emb, gateW, gateB, gamma, beta,
                                           shareW, expW);

    cudaFuncSetAttribute(moe_mma_kernel,
                         cudaFuncAttributeMaxDynamicSharedMemorySize, SMEM_BYTES);
    moe_mma_kernel<<<dim3(4, 256), 256, SMEM_BYTES>>>(inputs, shareB, expB, out);

    finalize_kernel<<<1, 256>>>(out, out_size);
}

// round 12
// speedup vs baseline: 8.7585x; 1.0560x over previous
#include <cuda_runtime.h>
#include <cuda_fp16.h>
#include <math.h>
#include <stdint.h>

#define N_TOK 32768
#define C_DIM 256
#define E_NUM 16
#define NMAT 17
#define RBLK 512          // router blocks (64 tokens each)
#define NTASK 36          // 4 chunks x (8 matrix-pairs + 1 single)

// ---------------- scratch (no allocations allowed) ----------------
__device__ float g_combine[N_TOK * E_NUM];
__device__ float g_pt[RBLK * 16];
__device__ float g_pp[RBLK * 16];
__device__ __align__(128) __half g_Whi[NMAT * C_DIM * C_DIM];

__device__ __forceinline__ uint32_t smem_u32(const void* p) {
    uint32_t a;
    asm("{ .reg .u64 t; cvta.to.shared.u64 t, %1; cvt.u32.u64 %0, t; }" : "=r"(a) : "l"(p));
    return a;
}

// ---------------- kernel 1: fused router + W-prep ----------------
__global__ __launch_bounds__(256) void prep_kernel(
    const float* __restrict__ conv, const float* __restrict__ emb,
    const float* __restrict__ gateW, const float* __restrict__ gateB,
    const float* __restrict__ gamma, const float* __restrict__ beta,
    const float* __restrict__ shareW, const float* __restrict__ expW)
{
    int tid = threadIdx.x;

    if (blockIdx.x >= RBLK) {
        // ---- W prep: transpose + fp16 convert ----
        __shared__ float tile[32][33];
        int w = blockIdx.x - RBLK;
        int m = w >> 6;
        int rr = w & 63;
        int by = rr >> 3, bx = rr & 7;
        const float* src = (m == 0) ? shareW : expW + (size_t)(m - 1) * 65536;
        int tx = tid & 31, ty = tid >> 5;
        if (ty < 8) {
#pragma unroll
            for (int i = 0; i < 4; i++) {
                int k = by * 32 + ty + i * 8;
                int n = bx * 32 + tx;
                tile[ty + i * 8][tx] = src[k * 256 + n];
            }
        }
        __syncthreads();
        if (ty < 8) {
#pragma unroll
            for (int i = 0; i < 4; i++) {
                int n = bx * 32 + ty + i * 8;
                int k = by * 32 + tx;
                float v = tile[tx][ty + i * 8];
                g_Whi[(size_t)m * 65536 + (size_t)n * 256 + k] = __float2half_rn(v);
            }
        }
        return;
    }

    // ---- router: 8 warps x 8 tokens (4 pair-passes, 2 tokens/warp-pass) ----
    __shared__ float gwT[16 * 257];
    __shared__ float gbev[3 * 256 + 16];
    __shared__ float wpt[8 * 16], wpp[8 * 16];
    for (int idx = tid; idx < 4096; idx += 256)
        gwT[(idx & 15) * 257 + (idx >> 4)] = gateW[idx];
    if (tid < 256) {
        gbev[tid] = gamma[tid];
        gbev[256 + tid] = beta[tid];
        gbev[512 + tid] = emb[tid];
    }
    if (tid < 16) gbev[768 + tid] = gateB[tid];
    __syncthreads();

    int warp = tid >> 5, lane = tid & 31;
    int half = lane >> 4;
    int sl = lane & 15;
    float st = 0.f, sp = 0.f;

#pragma unroll 1
    for (int i = 0; i < 4; i++) {
        int n = blockIdx.x * 64 + warp * 8 + i * 2 + half;
        const float* row = conv + (size_t)n * C_DIM;

        float x[16];
        float s = 0.f, s2 = 0.f;
#pragma unroll
        for (int j = 0; j < 16; j++) {
            x[j] = row[sl + 16 * j];
            s += x[j]; s2 += x[j] * x[j];
        }
#pragma unroll
        for (int o = 8; o; o >>= 1) {
            s  += __shfl_xor_sync(0xffffffffu, s,  o);
            s2 += __shfl_xor_sync(0xffffffffu, s2, o);
        }
        float mu = s * (1.f / 256.f);
        float var = s2 * (1.f / 256.f) - mu * mu;
        float rstd = rsqrtf(var + 1e-5f);

        float r[16];
#pragma unroll
        for (int j = 0; j < 16; j++) {
            int c = sl + 16 * j;
            r[j] = (x[j] - mu) * rstd * gbev[c] + gbev[256 + c] + gbev[512 + c];
        }

        float v[16];
#pragma unroll
        for (int e = 0; e < 16; e++) {
            float p = 0.f;
#pragma unroll
            for (int j = 0; j < 16; j++) p += r[j] * gwT[e * 257 + sl + 16 * j];
            v[e] = p;
        }

        // butterfly fold: lane sl ends with logit of expert sl
        {
            bool hi = (sl & 8) != 0;
#pragma unroll
            for (int j = 0; j < 8; j++) {
                float keep = hi ? v[j + 8] : v[j];
                float send = hi ? v[j] : v[j + 8];
                v[j] = keep + __shfl_xor_sync(0xffffffffu, send, 8);
            }
        }
        {
            bool hi = (sl & 4) != 0;
#pragma unroll
            for (int j = 0; j < 4; j++) {
                float keep = hi ? v[j + 4] : v[j];
                float send = hi ? v[j] : v[j + 4];
                v[j] = keep + __shfl_xor_sync(0xffffffffu, send, 4);
            }
        }
        {
            bool hi = (sl & 2) != 0;
#pragma unroll
            for (int j = 0; j < 2; j++) {
                float keep = hi ? v[j + 2] : v[j];
                float send = hi ? v[j] : v[j + 2];
                v[j] = keep + __shfl_xor_sync(0xffffffffu, send, 2);
            }
        }
        {
            bool hi = (sl & 1) != 0;
            float keep = hi ? v[1] : v[0];
            float send = hi ? v[0] : v[1];
            v[0] = keep + __shfl_xor_sync(0xffffffffu, send, 1);
        }
        float L = v[0] + gbev[768 + sl];

        // all-gather: a[i] = logit of expert (sl ^ i)
        float a[16];
        a[0] = L;
        a[1] = __shfl_xor_sync(0xffffffffu, a[0], 1);
#pragma unroll
        for (int q = 0; q < 2; q++) a[2 + q] = __shfl_xor_sync(0xffffffffu, a[q], 2);
#pragma unroll
        for (int q = 0; q < 4; q++) a[4 + q] = __shfl_xor_sync(0xffffffffu, a[q], 4);
#pragma unroll
        for (int q = 0; q < 8; q++) a[8 + q] = __shfl_xor_sync(0xffffffffu, a[q], 8);

        float mx = a[0];
#pragma unroll
        for (int e = 1; e < 16; e++) mx = fmaxf(mx, a[e]);
        float sum = 0.f;
#pragma unroll
        for (int e = 0; e < 16; e++) { a[e] = expf(a[e] - mx); sum += a[e]; }
        float inv = 1.f / sum;
        float ent = 0.f;
#pragma unroll
        for (int e = 0; e < 16; e++) { a[e] *= inv; ent -= a[e] * logf(a[e] + 1e-12f); }
        float kf = ceilf(1.f + ent * (15.f / 2.7725887222397811f));
        int k = (int)kf; k = k < 1 ? 1 : (k > 16 ? 16 : k);

        float we = a[0];
        int rank = 0;
#pragma unroll
        for (int j = 1; j < 16; j++) {
            int ej = sl ^ j;
            rank += (a[j] > we) || (a[j] == we && ej < sl);
        }
        int sel = rank < k;
        g_combine[(size_t)n * 16 + sl] = sel ? we : 0.f;
        st += sel ? 1.f : 0.f;
        sp += we;
    }

    st += __shfl_xor_sync(0xffffffffu, st, 16);
    sp += __shfl_xor_sync(0xffffffffu, sp, 16);
    if (lane < 16) { wpt[warp * 16 + lane] = st; wpp[warp * 16 + lane] = sp; }
    __syncthreads();
    if (tid < 16) {
        float t = 0.f, p = 0.f;
#pragma unroll
        for (int w = 0; w < 8; w++) { t += wpt[w * 16 + tid]; p += wpp[w * 16 + tid]; }
        g_pt[blockIdx.x * 16 + tid] = t;
        g_pp[blockIdx.x * 16 + tid] = p;
    }
}

// ---------------- kernel 2: mma.sync fused MoE GEMM v10 ----------------
// CTA 128(M) x 64(N), 256 threads (8 warps 4x2, warp 32x32), 2 CTAs/SM.
// Two matrices per pipeline stage -> 36 sync windows instead of 68.
#define WS_OFF 0            // 3 stages x 18432 (2 matrices x 64 rows x 144B)
#define XC_OFF 55296        // current X chunk (fp16): 128 rows x 144B = 18432
#define SC_OFF 73728        // [17][64] half2 pairs = 4352
#define BS_OFF 78080        // [17][64] f32 = 4352
#define SMEM_BYTES 82432

#define LDSM4(R, A) \
    asm volatile("ldmatrix.sync.aligned.m8n8.x4.shared.b16 {%0,%1,%2,%3}, [%4];" \
        : "=r"((R)[0]), "=r"((R)[1]), "=r"((R)[2]), "=r"((R)[3]) : "r"(A))
#define MMA16816(D, A, B) \
    asm volatile("mma.sync.aligned.m16n8k16.row.col.f32.f16.f16.f32 " \
        "{%0,%1,%2,%3}, {%4,%5,%6,%7}, {%8,%9}, {%0,%1,%2,%3};" \
        : "+f"((D)[0]), "+f"((D)[1]), "+f"((D)[2]), "+f"((D)[3]) \
        : "r"((A)[0]), "r"((A)[1]), "r"((A)[2]), "r"((A)[3]), "r"((B)[0]), "r"((B)[1]))

__device__ __forceinline__ uint32_t packh(float a, float b) {
    __half2 h = __floats2half2_rn(a, b);
    return *reinterpret_cast<uint32_t*>(&h);
}
__device__ __forceinline__ uint32_t hmul2u(uint32_t a, uint32_t b) {
    __half2 r = __hmul2(*reinterpret_cast<__half2*>(&a), *reinterpret_cast<__half2*>(&b));
    return *reinterpret_cast<uint32_t*>(&r);
}

// prefetch W for task t: chunk c = t/9, pair p = t%9 (matrices 2p, 2p+1; p==8 single)
__device__ __forceinline__ void prefetch_w(uint32_t wbase, int t, int colBase, int tid)
{
    const int c = t / 9;
    const int p = t - c * 9;
    const int stage = t % 3;
    const int mbase = 2 * p;
    const int nseg = (p == 8) ? 512 : 1024;   // segments of 16B
#pragma unroll
    for (int i = 0; i < 4; i++) {
        int idx = tid + i * 256;           // 0..1023
        if (idx < nseg) {
            int mi = idx >> 9;             // matrix within pair
            int r = (idx >> 3) & 63;       // n row 0..63
            int q = idx & 7;               // 16B segment along k
            const __half* src = g_Whi +
                (size_t)(mbase + mi) * 65536 + (size_t)(colBase + r) * 256 + c * 64 + q * 8;
            uint32_t dst = wbase + stage * 18432 + mi * 9216 + r * 144 + q * 16;
            asm volatile("cp.async.cg.shared.global [%0], [%1], 16;"
                         :: "r"(dst), "l"(src) : "memory");
        }
    }
    asm volatile("cp.async.commit_group;" ::: "memory");
}

// convert X chunk (128 rows x 64 k) from gmem to fp16 into XC buffer
__device__ __forceinline__ void convert_x(char* smc, const float* Xb, int chunk, int tid)
{
#pragma unroll
    for (int i = 0; i < 8; i++) {
        int idx = tid + i * 256;           // 0..2047 float4 slots
        int r = idx >> 4;                  // row 0..127
        int k4 = idx & 15;
        float4 v = reinterpret_cast<const float4*>(Xb + (size_t)r * 256 + chunk * 64)[k4];
        uint2 h = make_uint2(packh(v.x, v.y), packh(v.z, v.w));
        *reinterpret_cast<uint2*>(smc + XC_OFF + r * 144 + k4 * 8) = h;
    }
}

__global__ __launch_bounds__(256, 2) void moe_mma_kernel(
    const float* __restrict__ X,
    const float* __restrict__ shareB,
    const float* __restrict__ expB,
    float* __restrict__ out)
{
    extern __shared__ char smc[];
    const int tid = threadIdx.x;
    const int lane = tid & 31, warp = tid >> 5;
    const int rowBase = blockIdx.y * 128;
    const int colBase = blockIdx.x * 64;
    const uint32_t sb = smem_u32(smc);
    const uint32_t wbase = sb + WS_OFF;

    prefetch_w(wbase, 0, colBase, tid);

    __half2* Sc2 = reinterpret_cast<__half2*>(smc + SC_OFF);
    float* Bs = reinterpret_cast<float*>(smc + BS_OFF);

    // stage paired scales: Sc2[m][j] = (s(row), s(row+8)), row = (j>>3)*16 + (j&7)
    for (int idx = tid; idx < 17 * 64; idx += 256) {
        int m = idx >> 6, j = idx & 63;
        int row = ((j >> 3) << 4) + (j & 7);
        float f0, f1;
        if (m == 0) { f0 = 1.0f; f1 = 1.0f; }
        else {
            f0 = g_combine[(size_t)(rowBase + row) * 16 + (m - 1)];
            f1 = g_combine[(size_t)(rowBase + row + 8) * 16 + (m - 1)];
        }
        Sc2[idx] = __floats2half2_rn(f0, f1);
    }
    for (int idx = tid; idx < 17 * 64; idx += 256) {
        int m = idx >> 6, c = idx & 63;
        Bs[idx] = (m == 0) ? shareB[colBase + c] : expB[(m - 1) * 256 + colBase + c];
    }

    prefetch_w(wbase, 1, colBase, tid);

    const float* Xb = X + (size_t)rowBase * 256;
    convert_x(smc, Xb, 0, tid);

    // warp tiling: m0 in {0,32,64,96}, n0 in {0,32}
    const int m0 = (warp & 3) * 32;
    const int n0 = (warp >> 2) * 32;

    const uint32_t xh_base = sb + XC_OFF + (uint32_t)(m0 + (lane & 15)) * 144 + (lane >> 4) * 16;
    const uint32_t wb_base = wbase +
        (uint32_t)(n0 + ((lane >> 4) & 1) * 8 + (lane & 7)) * 144 + ((lane >> 3) & 1) * 16;

    const int rq = lane >> 2;
    const int cq = (lane & 3) * 2;
    const int scBase = (warp & 3) * 16 + rq;

    float acc[2][4][4];
#pragma unroll
    for (int mt = 0; mt < 2; mt++)
#pragma unroll
        for (int nt = 0; nt < 4; nt++)
#pragma unroll
            for (int q = 0; q < 4; q++) acc[mt][nt][q] = 0.f;

    __syncthreads();   // X chunk 0 / Sc2 / Bs visible

    // acc init = sum_m s_m * b_m (same fp16-rounded scales)
#pragma unroll 1
    for (int m = 0; m < NMAT; m++) {
        float2 fa = __half22float2(Sc2[m * 64 + scBase]);
        float2 fb = __half22float2(Sc2[m * 64 + scBase + 8]);
#pragma unroll
        for (int nt = 0; nt < 4; nt++) {
            float b0 = Bs[m * 64 + n0 + nt * 8 + cq];
            float b1 = Bs[m * 64 + n0 + nt * 8 + cq + 1];
            acc[0][nt][0] += fa.x * b0; acc[0][nt][1] += fa.x * b1;
            acc[0][nt][2] += fa.y * b0; acc[0][nt][3] += fa.y * b1;
            acc[1][nt][0] += fb.x * b0; acc[1][nt][1] += fb.x * b1;
            acc[1][nt][2] += fb.y * b0; acc[1][nt][3] += fb.y * b1;
        }
    }

    uint32_t Ah[4][2][4];

#pragma unroll 1
    for (int t = 0; t < NTASK; t++) {
        const int c = t / 9;
        const int p = t - c * 9;
        const int stage = t % 3;
        const int mbase = 2 * p;
        const int nm = (p == 8) ? 1 : 2;

        asm volatile("cp.async.wait_group 1;" ::: "memory");
        __syncthreads();

        if (p == 0) {
            // A fragments for chunk c (persist for all 9 sub-steps)
#pragma unroll
            for (int ks = 0; ks < 4; ks++) {
#pragma unroll
                for (int mt = 0; mt < 2; mt++)
                    LDSM4(Ah[ks][mt], xh_base + mt * (16 * 144) + ks * 32);
            }
        }
        if (p == 1 && c < 3) {
            convert_x(smc, Xb, c + 1, tid);
        }

#pragma unroll 1
        for (int mi = 0; mi < nm; mi++) {
            const int m = mbase + mi;
            __half2 h2a = Sc2[m * 64 + scBase];
            __half2 h2b = Sc2[m * 64 + scBase + 8];
            uint32_t sA0, sA1, sB0, sB1;
            {
                __half2 t0 = __half2half2(__low2half(h2a));
                __half2 t1 = __half2half2(__high2half(h2a));
                __half2 t2 = __half2half2(__low2half(h2b));
                __half2 t3 = __half2half2(__high2half(h2b));
                sA0 = *reinterpret_cast<uint32_t*>(&t0);
                sA1 = *reinterpret_cast<uint32_t*>(&t1);
                sB0 = *reinterpret_cast<uint32_t*>(&t2);
                sB1 = *reinterpret_cast<uint32_t*>(&t3);
            }

            const uint32_t wbs = wb_base + stage * 18432 + mi * 9216;
#pragma unroll
            for (int ks = 0; ks < 4; ks++) {
                uint32_t Bh[4][2];
#pragma unroll
                for (int ntp = 0; ntp < 2; ntp++) {
                    uint32_t r4[4];
                    LDSM4(r4, wbs + ntp * (16 * 144) + ks * 32);
                    Bh[ntp * 2][0] = r4[0]; Bh[ntp * 2][1] = r4[1];
                    Bh[ntp * 2 + 1][0] = r4[2]; Bh[ntp * 2 + 1][1] = r4[3];
                }
                uint32_t As[4];
                As[0] = hmul2u(Ah[ks][0][0], sA0);
                As[1] = hmul2u(Ah[ks][0][1], sA1);
                As[2] = hmul2u(Ah[ks][0][2], sA0);
                As[3] = hmul2u(Ah[ks][0][3], sA1);
#pragma unroll
                for (int nt = 0; nt < 4; nt++)
                    MMA16816(acc[0][nt], As, Bh[nt]);
                As[0] = hmul2u(Ah[ks][1][0], sB0);
                As[1] = hmul2u(Ah[ks][1][1], sB1);
                As[2] = hmul2u(Ah[ks][1][2], sB0);
                As[3] = hmul2u(Ah[ks][1][3], sB1);
#pragma unroll
                for (int nt = 0; nt < 4; nt++)
                    MMA16816(acc[1][nt], As, Bh[nt]);
            }
        }

        if (t + 2 < NTASK) prefetch_w(wbase, t + 2, colBase, tid);
        else asm volatile("cp.async.commit_group;" ::: "memory");
    }

    // write output
#pragma unroll
    for (int mt = 0; mt < 2; mt++) {
        int rg = rowBase + m0 + mt * 16 + rq;
#pragma unroll
        for (int nt = 0; nt < 4; nt++) {
            int cg = colBase + n0 + nt * 8 + cq;
            *reinterpret_cast<float2*>(out + (size_t)rg * 256 + cg) =
                make_float2(acc[mt][nt][0], acc[mt][nt][1]);
            *reinterpret_cast<float2*>(out + (size_t)(rg + 8) * 256 + cg) =
                make_float2(acc[mt][nt][2], acc[mt][nt][3]);
        }
    }
}

// ---------------- kernel 3: loss reduce + finalize ----------------
__global__ __launch_bounds__(256) void finalize_kernel(float* __restrict__ out, int out_size)
{
    __shared__ float rt[16][17], rp[16][17];
    __shared__ float prod[16];
    int tid = threadIdx.x;
    int e = tid & 15, part = tid >> 4;   // 16 parts x 32 blocks
    float t = 0.f, p = 0.f;
    for (int b = part * 32; b < part * 32 + 32; b++) {
        t += g_pt[b * 16 + e];
        p += g_pp[b * 16 + e];
    }
    rt[part][e] = t; rp[part][e] = p;
    __syncthreads();
    if (tid < 16) {
        float ts = 0.f, ps = 0.f;
#pragma unroll
        for (int q = 0; q < 16; q++) { ts += rt[q][tid]; ps += rp[q][tid]; }
        prod[tid] = (ts * (1.f / (float)N_TOK)) * (ps * (1.f / (float)N_TOK));
    }
    __syncthreads();
    const int NC = N_TOK * C_DIM;
    if (tid == 0) {
        float a = 0.f;
#pragma unroll
        for (int q = 0; q < 16; q++) a += prod[q];
        if (out_size > NC) out[NC] = a * 16.f;
    }
    for (int i = NC + 1 + tid; i < out_size; i += 256)
        out[i] = 0.f;
}

// ---------------- launch ----------------
extern "C" void kernel_launch(void* const* d_in, const int* in_sizes, int n_in,
                              void* d_out, int out_size)
{
    const float* inputs = (const float*)d_in[0];
    const float* conv   = (const float*)d_in[1];
    const float* emb    = (const float*)d_in[2];
    const float* shareW = (const float*)d_in[3];
    const float* shareB = (const float*)d_in[4];
    const float* gateW  = (const float*)d_in[5];
    const float* gateB  = (const float*)d_in[6];
    const float* expW   = (const float*)d_in[7];
    const float* expB   = (const float*)d_in[8];
    const float* gamma  = (const float*)d_in[9];
    const float* beta   = (const float*)d_in[10];
    float* out = (float*)d_out;

    prep_kernel<<<RBLK + NMAT * 64, 256>>>(conv, emb, gateW, gateB, gamma, beta,
                                           shareW, expW);

    cudaFuncSetAttribute(moe_mma_kernel,
                         cudaFuncAttributeMaxDynamicSharedMemorySize, SMEM_BYTES);
    moe_mma_kernel<<<dim3(4, 256), 256, SMEM_BYTES>>>(inputs, shareB, expB, out);

    finalize_kernel<<<1, 256>>>(out, out_size);
}

// round 13
// speedup vs baseline: 9.0824x; 1.0370x over previous
#include <cuda_runtime.h>
#include <cuda_fp16.h>
#include <math.h>
#include <stdint.h>

#define N_TOK 32768
#define C_DIM 256
#define E_NUM 16
#define NMAT 17
#define RBLK 512          // router blocks (64 tokens each)
#define NTASK 36          // 4 chunks x (8 matrix-pairs + 1 single)

// ---------------- scratch (no allocations allowed) ----------------
__device__ float g_combine[N_TOK * E_NUM];
__device__ float g_pt[RBLK * 16];
__device__ float g_pp[RBLK * 16];
__device__ __align__(128) __half g_Whi[NMAT * C_DIM * C_DIM];

__device__ __forceinline__ uint32_t smem_u32(const void* p) {
    uint32_t a;
    asm("{ .reg .u64 t; cvta.to.shared.u64 t, %1; cvt.u32.u64 %0, t; }" : "=r"(a) : "l"(p));
    return a;
}

// ---------------- kernel 1: fused router + W-prep ----------------
__global__ __launch_bounds__(256) void prep_kernel(
    const float* __restrict__ conv, const float* __restrict__ emb,
    const float* __restrict__ gateW, const float* __restrict__ gateB,
    const float* __restrict__ gamma, const float* __restrict__ beta,
    const float* __restrict__ shareW, const float* __restrict__ expW)
{
    int tid = threadIdx.x;

    if (blockIdx.x >= RBLK) {
        // ---- W prep: transpose + fp16 convert ----
        __shared__ float tile[32][33];
        int w = blockIdx.x - RBLK;
        int m = w >> 6;
        int rr = w & 63;
        int by = rr >> 3, bx = rr & 7;
        const float* src = (m == 0) ? shareW : expW + (size_t)(m - 1) * 65536;
        int tx = tid & 31, ty = tid >> 5;
        if (ty < 8) {
#pragma unroll
            for (int i = 0; i < 4; i++) {
                int k = by * 32 + ty + i * 8;
                int n = bx * 32 + tx;
                tile[ty + i * 8][tx] = src[k * 256 + n];
            }
        }
        __syncthreads();
        if (ty < 8) {
#pragma unroll
            for (int i = 0; i < 4; i++) {
                int n = bx * 32 + ty + i * 8;
                int k = by * 32 + tx;
                float v = tile[tx][ty + i * 8];
                g_Whi[(size_t)m * 65536 + (size_t)n * 256 + k] = __float2half_rn(v);
            }
        }
        return;
    }

    // ---- router: 8 warps x 8 tokens, 4 tokens per e/j pass (2 pairs) ----
    __shared__ float gwT[16 * 257];
    __shared__ float gbev[3 * 256 + 16];
    __shared__ float wpt[8 * 16], wpp[8 * 16];
    for (int idx = tid; idx < 4096; idx += 256)
        gwT[(idx & 15) * 257 + (idx >> 4)] = gateW[idx];
    if (tid < 256) {
        gbev[tid] = gamma[tid];
        gbev[256 + tid] = beta[tid];
        gbev[512 + tid] = emb[tid];
    }
    if (tid < 16) gbev[768 + tid] = gateB[tid];
    __syncthreads();

    int warp = tid >> 5, lane = tid & 31;
    int half = lane >> 4;
    int sl = lane & 15;
    float st = 0.f, sp = 0.f;

#pragma unroll 1
    for (int i = 0; i < 2; i++) {
        // two tokens per lane this pass: n0t (pair 0) and n1t (pair 1)
        int nb = blockIdx.x * 64 + warp * 8 + i * 4;
        int n0t = nb + half;
        int n1t = nb + 2 + half;
        const float* row0 = conv + (size_t)n0t * C_DIM;
        const float* row1 = conv + (size_t)n1t * C_DIM;

        float r0[16], r1[16];
        {
            float x0[16], x1[16];
            float s0 = 0.f, q0 = 0.f, s1 = 0.f, q1 = 0.f;
#pragma unroll
            for (int j = 0; j < 16; j++) {
                x0[j] = row0[sl + 16 * j];
                x1[j] = row1[sl + 16 * j];
                s0 += x0[j]; q0 += x0[j] * x0[j];
                s1 += x1[j]; q1 += x1[j] * x1[j];
            }
#pragma unroll
            for (int o = 8; o; o >>= 1) {
                s0 += __shfl_xor_sync(0xffffffffu, s0, o);
                q0 += __shfl_xor_sync(0xffffffffu, q0, o);
                s1 += __shfl_xor_sync(0xffffffffu, s1, o);
                q1 += __shfl_xor_sync(0xffffffffu, q1, o);
            }
            float mu0 = s0 * (1.f / 256.f);
            float rstd0 = rsqrtf(q0 * (1.f / 256.f) - mu0 * mu0 + 1e-5f);
            float mu1 = s1 * (1.f / 256.f);
            float rstd1 = rsqrtf(q1 * (1.f / 256.f) - mu1 * mu1 + 1e-5f);
#pragma unroll
            for (int j = 0; j < 16; j++) {
                int c = sl + 16 * j;
                float g = gbev[c], b = gbev[256 + c] + gbev[512 + c];
                r0[j] = (x0[j] - mu0) * rstd0 * g + b;
                r1[j] = (x1[j] - mu1) * rstd1 * g + b;
            }
        }

        // partial dots: ONE LDS feeds TWO FMAs
        float v0[16], v1[16];
#pragma unroll
        for (int e = 0; e < 16; e++) {
            float p0 = 0.f, p1 = 0.f;
#pragma unroll
            for (int j = 0; j < 16; j++) {
                float gw = gwT[e * 257 + sl + 16 * j];
                p0 += r0[j] * gw;
                p1 += r1[j] * gw;
            }
            v0[e] = p0; v1[e] = p1;
        }

        // butterfly fold both tokens: lane sl ends with logit of expert sl
#pragma unroll
        for (int step = 8; step >= 1; step >>= 1) {
            bool hi = (sl & step) != 0;
#pragma unroll
            for (int j = 0; j < 8; j++) {
                if (j < step) {
                    float k0 = hi ? v0[j + step] : v0[j];
                    float d0 = hi ? v0[j] : v0[j + step];
                    v0[j] = k0 + __shfl_xor_sync(0xffffffffu, d0, step);
                    float k1 = hi ? v1[j + step] : v1[j];
                    float d1 = hi ? v1[j] : v1[j + step];
                    v1[j] = k1 + __shfl_xor_sync(0xffffffffu, d1, step);
                }
            }
        }

#pragma unroll 1
        for (int tk = 0; tk < 2; tk++) {
            int n = tk ? n1t : n0t;
            float L = (tk ? v1[0] : v0[0]) + gbev[768 + sl];

            // all-gather: a[i] = logit of expert (sl ^ i)
            float a[16];
            a[0] = L;
            a[1] = __shfl_xor_sync(0xffffffffu, a[0], 1);
#pragma unroll
            for (int q = 0; q < 2; q++) a[2 + q] = __shfl_xor_sync(0xffffffffu, a[q], 2);
#pragma unroll
            for (int q = 0; q < 4; q++) a[4 + q] = __shfl_xor_sync(0xffffffffu, a[q], 4);
#pragma unroll
            for (int q = 0; q < 8; q++) a[8 + q] = __shfl_xor_sync(0xffffffffu, a[q], 8);

            float mx = a[0];
#pragma unroll
            for (int e = 1; e < 16; e++) mx = fmaxf(mx, a[e]);
            float sum = 0.f;
#pragma unroll
            for (int e = 0; e < 16; e++) { a[e] = expf(a[e] - mx); sum += a[e]; }
            float inv = 1.f / sum;
            float ent = 0.f;
#pragma unroll
            for (int e = 0; e < 16; e++) { a[e] *= inv; ent -= a[e] * logf(a[e] + 1e-12f); }
            float kf = ceilf(1.f + ent * (15.f / 2.7725887222397811f));
            int k = (int)kf; k = k < 1 ? 1 : (k > 16 ? 16 : k);

            float we = a[0];
            int rank = 0;
#pragma unroll
            for (int j = 1; j < 16; j++) {
                int ej = sl ^ j;
                rank += (a[j] > we) || (a[j] == we && ej < sl);
            }
            int sel = rank < k;
            g_combine[(size_t)n * 16 + sl] = sel ? we : 0.f;
            st += sel ? 1.f : 0.f;
            sp += we;
        }
    }

    st += __shfl_xor_sync(0xffffffffu, st, 16);
    sp += __shfl_xor_sync(0xffffffffu, sp, 16);
    if (lane < 16) { wpt[warp * 16 + lane] = st; wpp[warp * 16 + lane] = sp; }
    __syncthreads();
    if (tid < 16) {
        float t = 0.f, p = 0.f;
#pragma unroll
        for (int w = 0; w < 8; w++) { t += wpt[w * 16 + tid]; p += wpp[w * 16 + tid]; }
        g_pt[blockIdx.x * 16 + tid] = t;
        g_pp[blockIdx.x * 16 + tid] = p;
    }
}

// ---------------- kernel 2: mma.sync fused MoE GEMM v10 + fused loss ----------------
// CTA 128(M) x 64(N), 256 threads (8 warps 4x2, warp 32x32), 2 CTAs/SM.
#define WS_OFF 0            // 3 stages x 18432 (2 matrices x 64 rows x 144B)
#define XC_OFF 55296        // current X chunk (fp16): 128 rows x 144B = 18432
#define SC_OFF 73728        // [17][64] half2 pairs = 4352
#define BS_OFF 78080        // [17][64] f32 = 4352
#define SMEM_BYTES 82432

#define LDSM4(R, A) \
    asm volatile("ldmatrix.sync.aligned.m8n8.x4.shared.b16 {%0,%1,%2,%3}, [%4];" \
        : "=r"((R)[0]), "=r"((R)[1]), "=r"((R)[2]), "=r"((R)[3]) : "r"(A))
#define MMA16816(D, A, B) \
    asm volatile("mma.sync.aligned.m16n8k16.row.col.f32.f16.f16.f32 " \
        "{%0,%1,%2,%3}, {%4,%5,%6,%7}, {%8,%9}, {%0,%1,%2,%3};" \
        : "+f"((D)[0]), "+f"((D)[1]), "+f"((D)[2]), "+f"((D)[3]) \
        : "r"((A)[0]), "r"((A)[1]), "r"((A)[2]), "r"((A)[3]), "r"((B)[0]), "r"((B)[1]))

__device__ __forceinline__ uint32_t packh(float a, float b) {
    __half2 h = __floats2half2_rn(a, b);
    return *reinterpret_cast<uint32_t*>(&h);
}
__device__ __forceinline__ uint32_t hmul2u(uint32_t a, uint32_t b) {
    __half2 r = __hmul2(*reinterpret_cast<__half2*>(&a), *reinterpret_cast<__half2*>(&b));
    return *reinterpret_cast<uint32_t*>(&r);
}

// prefetch W for task t: chunk c = t/9, pair p = t%9 (matrices 2p, 2p+1; p==8 single)
__device__ __forceinline__ void prefetch_w(uint32_t wbase, int t, int colBase, int tid)
{
    const int c = t / 9;
    const int p = t - c * 9;
    const int stage = t % 3;
    const int mbase = 2 * p;
    const int nseg = (p == 8) ? 512 : 1024;   // segments of 16B
#pragma unroll
    for (int i = 0; i < 4; i++) {
        int idx = tid + i * 256;           // 0..1023
        if (idx < nseg) {
            int mi = idx >> 9;             // matrix within pair
            int r = (idx >> 3) & 63;       // n row 0..63
            int q = idx & 7;               // 16B segment along k
            const __half* src = g_Whi +
                (size_t)(mbase + mi) * 65536 + (size_t)(colBase + r) * 256 + c * 64 + q * 8;
            uint32_t dst = wbase + stage * 18432 + mi * 9216 + r * 144 + q * 16;
            asm volatile("cp.async.cg.shared.global [%0], [%1], 16;"
                         :: "r"(dst), "l"(src) : "memory");
        }
    }
    asm volatile("cp.async.commit_group;" ::: "memory");
}

// convert X chunk (128 rows x 64 k) from gmem to fp16 into XC buffer
__device__ __forceinline__ void convert_x(char* smc, const float* Xb, int chunk, int tid)
{
#pragma unroll
    for (int i = 0; i < 8; i++) {
        int idx = tid + i * 256;           // 0..2047 float4 slots
        int r = idx >> 4;                  // row 0..127
        int k4 = idx & 15;
        float4 v = reinterpret_cast<const float4*>(Xb + (size_t)r * 256 + chunk * 64)[k4];
        uint2 h = make_uint2(packh(v.x, v.y), packh(v.z, v.w));
        *reinterpret_cast<uint2*>(smc + XC_OFF + r * 144 + k4 * 8) = h;
    }
}

__global__ __launch_bounds__(256, 2) void moe_mma_kernel(
    const float* __restrict__ X,
    const float* __restrict__ shareB,
    const float* __restrict__ expB,
    float* __restrict__ out,
    int out_size)
{
    extern __shared__ char smc[];
    const int tid = threadIdx.x;
    const int lane = tid & 31, warp = tid >> 5;
    const int rowBase = blockIdx.y * 128;
    const int colBase = blockIdx.x * 64;
    const uint32_t sb = smem_u32(smc);
    const uint32_t wbase = sb + WS_OFF;

    prefetch_w(wbase, 0, colBase, tid);

    // ---- fused loss finalize (block (0,0) only; g_pt/g_pp ready since prep
    //      finished before this kernel launched). Overlaps with prefetch. ----
    if (blockIdx.x == 0 && blockIdx.y == 0) {
        const int NC = N_TOK * C_DIM;
        if (tid < 16) {
            float t = 0.f, p = 0.f;
            for (int b = 0; b < RBLK; b++) {
                t += g_pt[b * 16 + tid];
                p += g_pp[b * 16 + tid];
            }
            float prod = (t * (1.f / (float)N_TOK)) * (p * (1.f / (float)N_TOK));
#pragma unroll
            for (int o = 8; o; o >>= 1) prod += __shfl_xor_sync(0xffffu, prod, o);
            if (tid == 0 && out_size > NC) out[NC] = prod * 16.f;
        }
        for (int i = NC + 1 + tid; i < out_size; i += 256)
            out[i] = 0.f;
    }

    __half2* Sc2 = reinterpret_cast<__half2*>(smc + SC_OFF);
    float* Bs = reinterpret_cast<float*>(smc + BS_OFF);

    for (int idx = tid; idx < 17 * 64; idx += 256) {
        int m = idx >> 6, j = idx & 63;
        int row = ((j >> 3) << 4) + (j & 7);
        float f0, f1;
        if (m == 0) { f0 = 1.0f; f1 = 1.0f; }
        else {
            f0 = g_combine[(size_t)(rowBase + row) * 16 + (m - 1)];
            f1 = g_combine[(size_t)(rowBase + row + 8) * 16 + (m - 1)];
        }
        Sc2[idx] = __floats2half2_rn(f0, f1);
    }
    for (int idx = tid; idx < 17 * 64; idx += 256) {
        int m = idx >> 6, c = idx & 63;
        Bs[idx] = (m == 0) ? shareB[colBase + c] : expB[(m - 1) * 256 + colBase + c];
    }

    prefetch_w(wbase, 1, colBase, tid);

    const float* Xb = X + (size_t)rowBase * 256;
    convert_x(smc, Xb, 0, tid);

    const int m0 = (warp & 3) * 32;
    const int n0 = (warp >> 2) * 32;

    const uint32_t xh_base = sb + XC_OFF + (uint32_t)(m0 + (lane & 15)) * 144 + (lane >> 4) * 16;
    const uint32_t wb_base = wbase +
        (uint32_t)(n0 + ((lane >> 4) & 1) * 8 + (lane & 7)) * 144 + ((lane >> 3) & 1) * 16;

    const int rq = lane >> 2;
    const int cq = (lane & 3) * 2;
    const int scBase = (warp & 3) * 16 + rq;

    float acc[2][4][4];
#pragma unroll
    for (int mt = 0; mt < 2; mt++)
#pragma unroll
        for (int nt = 0; nt < 4; nt++)
#pragma unroll
            for (int q = 0; q < 4; q++) acc[mt][nt][q] = 0.f;

    __syncthreads();   // X chunk 0 / Sc2 / Bs visible

    // acc init = sum_m s_m * b_m
#pragma unroll 1
    for (int m = 0; m < NMAT; m++) {
        float2 fa = __half22float2(Sc2[m * 64 + scBase]);
        float2 fb = __half22float2(Sc2[m * 64 + scBase + 8]);
#pragma unroll
        for (int nt = 0; nt < 4; nt++) {
            float b0 = Bs[m * 64 + n0 + nt * 8 + cq];
            float b1 = Bs[m * 64 + n0 + nt * 8 + cq + 1];
            acc[0][nt][0] += fa.x * b0; acc[0][nt][1] += fa.x * b1;
            acc[0][nt][2] += fa.y * b0; acc[0][nt][3] += fa.y * b1;
            acc[1][nt][0] += fb.x * b0; acc[1][nt][1] += fb.x * b1;
            acc[1][nt][2] += fb.y * b0; acc[1][nt][3] += fb.y * b1;
        }
    }

    uint32_t Ah[4][2][4];

#pragma unroll 1
    for (int t = 0; t < NTASK; t++) {
        const int c = t / 9;
        const int p = t - c * 9;
        const int stage = t % 3;
        const int mbase = 2 * p;
        const int nm = (p == 8) ? 1 : 2;

        asm volatile("cp.async.wait_group 1;" ::: "memory");
        __syncthreads();

        if (p == 0) {
#pragma unroll
            for (int ks = 0; ks < 4; ks++) {
#pragma unroll
                for (int mt = 0; mt < 2; mt++)
                    LDSM4(Ah[ks][mt], xh_base + mt * (16 * 144) + ks * 32);
            }
        }
        if (p == 1 && c < 3) {
            convert_x(smc, Xb, c + 1, tid);
        }

#pragma unroll 1
        for (int mi = 0; mi < nm; mi++) {
            const int m = mbase + mi;
            __half2 h2a = Sc2[m * 64 + scBase];
            __half2 h2b = Sc2[m * 64 + scBase + 8];
            uint32_t sA0, sA1, sB0, sB1;
            {
                __half2 t0 = __half2half2(__low2half(h2a));
                __half2 t1 = __half2half2(__high2half(h2a));
                __half2 t2 = __half2half2(__low2half(h2b));
                __half2 t3 = __half2half2(__high2half(h2b));
                sA0 = *reinterpret_cast<uint32_t*>(&t0);
                sA1 = *reinterpret_cast<uint32_t*>(&t1);
                sB0 = *reinterpret_cast<uint32_t*>(&t2);
                sB1 = *reinterpret_cast<uint32_t*>(&t3);
            }

            const uint32_t wbs = wb_base + stage * 18432 + mi * 9216;
#pragma unroll
            for (int ks = 0; ks < 4; ks++) {
                uint32_t Bh[4][2];
#pragma unroll
                for (int ntp = 0; ntp < 2; ntp++) {
                    uint32_t r4[4];
                    LDSM4(r4, wbs + ntp * (16 * 144) + ks * 32);
                    Bh[ntp * 2][0] = r4[0]; Bh[ntp * 2][1] = r4[1];
                    Bh[ntp * 2 + 1][0] = r4[2]; Bh[ntp * 2 + 1][1] = r4[3];
                }
                uint32_t As[4];
                As[0] = hmul2u(Ah[ks][0][0], sA0);
                As[1] = hmul2u(Ah[ks][0][1], sA1);
                As[2] = hmul2u(Ah[ks][0][2], sA0);
                As[3] = hmul2u(Ah[ks][0][3], sA1);
#pragma unroll
                for (int nt = 0; nt < 4; nt++)
                    MMA16816(acc[0][nt], As, Bh[nt]);
                As[0] = hmul2u(Ah[ks][1][0], sB0);
                As[1] = hmul2u(Ah[ks][1][1], sB1);
                As[2] = hmul2u(Ah[ks][1][2], sB0);
                As[3] = hmul2u(Ah[ks][1][3], sB1);
#pragma unroll
                for (int nt = 0; nt < 4; nt++)
                    MMA16816(acc[1][nt], As, Bh[nt]);
            }
        }

        if (t + 2 < NTASK) prefetch_w(wbase, t + 2, colBase, tid);
        else asm volatile("cp.async.commit_group;" ::: "memory");
    }

    // write output
#pragma unroll
    for (int mt = 0; mt < 2; mt++) {
        int rg = rowBase + m0 + mt * 16 + rq;
#pragma unroll
        for (int nt = 0; nt < 4; nt++) {
            int cg = colBase + n0 + nt * 8 + cq;
            *reinterpret_cast<float2*>(out + (size_t)rg * 256 + cg) =
                make_float2(acc[mt][nt][0], acc[mt][nt][1]);
            *reinterpret_cast<float2*>(out + (size_t)(rg + 8) * 256 + cg) =
                make_float2(acc[mt][nt][2], acc[mt][nt][3]);
        }
    }
}

// ---------------- launch ----------------
extern "C" void kernel_launch(void* const* d_in, const int* in_sizes, int n_in,
                              void* d_out, int out_size)
{
    const float* inputs = (const float*)d_in[0];
    const float* conv   = (const float*)d_in[1];
    const float* emb    = (const float*)d_in[2];
    const float* shareW = (const float*)d_in[3];
    const float* shareB = (const float*)d_in[4];
    const float* gateW  = (const float*)d_in[5];
    const float* gateB  = (const float*)d_in[6];
    const float* expW   = (const float*)d_in[7];
    const float* expB   = (const float*)d_in[8];
    const float* gamma  = (const float*)d_in[9];
    const float* beta   = (const float*)d_in[10];
    float* out = (float*)d_out;

    prep_kernel<<<RBLK + NMAT * 64, 256>>>(conv, emb, gateW, gateB, gamma, beta,
                                           shareW, expW);

    cudaFuncSetAttribute(moe_mma_kernel,
                         cudaFuncAttributeMaxDynamicSharedMemorySize, SMEM_BYTES);
    moe_mma_kernel<<<dim3(4, 256), 256, SMEM_BYTES>>>(inputs, shareB, expB, out,
                                                      out_size);
}